// round 1
// baseline (speedup 1.0000x reference)
#include <cuda_runtime.h>
#include <math.h>

// Problem dims (fixed)
#define BWN 4096   // B*W
#define HD  512    // hidden
#define QD  256    // quantized repr
#define AD  128    // alphabet
#define CD  16     // chars per word
#define G4H 2048   // 4*H

// State buffers (static device memory — no allocation allowed)
__device__ float g_hA[BWN * HD];
__device__ float g_hB[BWN * HD];
__device__ float g_c [BWN * HD];

__device__ __forceinline__ float sigmoidf_(float x) {
    return 1.0f / (1.0f + expf(-x));
}

// ============================================================================
// h0 = X @ Wp^T + bp  (M=4096, N=512, K=256);  also zero-init cell state
// NT GEMM: both operands K-major (row-major [rows, K]).
// BM=64, BN=64, KT=16, 256 threads, 4x4 micro-tile, interleaved mapping
// (j = cn + jj*16) for conflict-free LDS.
// ============================================================================
__global__ __launch_bounds__(256) void h0_kernel(
    const float* __restrict__ X,    // [4096,256]
    const float* __restrict__ Wp,   // [512,256]
    const float* __restrict__ bp,   // [512]
    float* __restrict__ h0,         // [4096,512]
    float* __restrict__ c0)         // [4096,512]
{
    __shared__ float sA[64][17];
    __shared__ float sB[64][17];
    const int tx = threadIdx.x;
    const int cn = tx & 15;   // column group
    const int rm = tx >> 4;   // row group
    const int m0 = blockIdx.x * 64;
    const int n0 = blockIdx.y * 64;

    float acc[4][4];
    #pragma unroll
    for (int i = 0; i < 4; i++)
        #pragma unroll
        for (int j = 0; j < 4; j++) acc[i][j] = 0.0f;

    for (int k0 = 0; k0 < QD; k0 += 16) {
        const int r  = tx >> 2;
        const int kq = (tx & 3) << 2;
        float4 va = *(const float4*)&X [(m0 + r) * QD + k0 + kq];
        sA[r][kq+0] = va.x; sA[r][kq+1] = va.y; sA[r][kq+2] = va.z; sA[r][kq+3] = va.w;
        float4 vb = *(const float4*)&Wp[(n0 + r) * QD + k0 + kq];
        sB[r][kq+0] = vb.x; sB[r][kq+1] = vb.y; sB[r][kq+2] = vb.z; sB[r][kq+3] = vb.w;
        __syncthreads();
        #pragma unroll
        for (int kk = 0; kk < 16; kk++) {
            float a[4], b[4];
            #pragma unroll
            for (int rr = 0; rr < 4; rr++) a[rr] = sA[rm + rr*16][kk];
            #pragma unroll
            for (int jj = 0; jj < 4; jj++) b[jj] = sB[cn + jj*16][kk];
            #pragma unroll
            for (int rr = 0; rr < 4; rr++)
                #pragma unroll
                for (int jj = 0; jj < 4; jj++) acc[rr][jj] += a[rr] * b[jj];
        }
        __syncthreads();
    }

    #pragma unroll
    for (int rr = 0; rr < 4; rr++) {
        const int m = m0 + rm + rr*16;
        #pragma unroll
        for (int jj = 0; jj < 4; jj++) {
            const int n = n0 + cn + jj*16;
            h0[m * HD + n] = acc[rr][jj] + bp[n];
            c0[m * HD + n] = 0.0f;
        }
    }
}

// ============================================================================
// Fused LSTM step:
//   gates[m, g*512+j] = sum_k h_in[m,k]*W_hh[g*512+j,k]
//                       + b_ih[n] + b_hh[n] + W_ih[n, idx(m,t)]
//   c = sig(f)*c + sig(i)*tanh(g);  h_out = sig(o)*tanh(c)
// Per block: 64 rows x 64 j-values x 4 gates. acc[rr][jj][g] = 64 fp32 regs.
// One-hot input handled as column gather of W_ih (idx=0 at t=0, else char t-1).
// ============================================================================
__global__ __launch_bounds__(256) void lstm_step_kernel(
    const float* __restrict__ h_in,
    float*       __restrict__ h_out,
    float*       __restrict__ c_state,
    const float* __restrict__ W_hh,  // [2048,512]
    const float* __restrict__ W_ih,  // [2048,128]
    const float* __restrict__ b_ih,  // [2048]
    const float* __restrict__ b_hh,  // [2048]
    const int*   __restrict__ chars, // [4096,16]
    int t)
{
    __shared__ float sH[64][17];      // [m_local][kk]
    __shared__ float sW[4][64][17];   // [gate][j_local][kk]
    __shared__ int   sIdx[64];

    const int tx = threadIdx.x;
    const int cn = tx & 15;
    const int rm = tx >> 4;
    const int m0 = blockIdx.x * 64;
    const int j0 = blockIdx.y * 64;

    if (tx < 64) {
        int idx = 0;
        if (t > 0) {
            int cch = chars[(m0 + tx) * CD + (t - 1)];
            idx = (cch >= 0 && cch < AD) ? cch : 0;
        }
        sIdx[tx] = idx;
    }

    float acc[4][4][4];  // [rr][jj][gate]
    #pragma unroll
    for (int a = 0; a < 4; a++)
        #pragma unroll
        for (int b = 0; b < 4; b++)
            #pragma unroll
            for (int c = 0; c < 4; c++) acc[a][b][c] = 0.0f;

    for (int k0 = 0; k0 < HD; k0 += 16) {
        // H tile: 64 rows x 16 k = 256 float4, one per thread
        {
            const int r  = tx >> 2;
            const int kq = (tx & 3) << 2;
            float4 v = *(const float4*)&h_in[(m0 + r) * HD + k0 + kq];
            sH[r][kq+0] = v.x; sH[r][kq+1] = v.y; sH[r][kq+2] = v.z; sH[r][kq+3] = v.w;
        }
        // W tile: 4 gates x 64 j x 16 k = 1024 float4, four per thread
        #pragma unroll
        for (int u = 0; u < 4; u++) {
            const int e   = tx + u * 256;       // 0..1023 (float4 index)
            const int kq  = (e & 3) << 2;
            const int row = e >> 2;             // 0..255
            const int g   = row >> 6;
            const int j   = row & 63;
            const int n   = g * HD + j0 + j;
            float4 v = *(const float4*)&W_hh[n * HD + k0 + kq];
            sW[g][j][kq+0] = v.x; sW[g][j][kq+1] = v.y;
            sW[g][j][kq+2] = v.z; sW[g][j][kq+3] = v.w;
        }
        __syncthreads();
        #pragma unroll
        for (int kk = 0; kk < 16; kk++) {
            float a[4];
            #pragma unroll
            for (int rr = 0; rr < 4; rr++) a[rr] = sH[rm + rr*16][kk];
            #pragma unroll
            for (int jj = 0; jj < 4; jj++) {
                const int j = cn + jj*16;
                #pragma unroll
                for (int g = 0; g < 4; g++) {
                    const float b = sW[g][j][kk];
                    #pragma unroll
                    for (int rr = 0; rr < 4; rr++) acc[rr][jj][g] += a[rr] * b;
                }
            }
        }
        __syncthreads();
    }

    // Epilogue: bias + one-hot gather + LSTM nonlinearity
    #pragma unroll
    for (int rr = 0; rr < 4; rr++) {
        const int ml  = rm + rr*16;
        const int m   = m0 + ml;
        const int idx = sIdx[ml];
        #pragma unroll
        for (int jj = 0; jj < 4; jj++) {
            const int j = j0 + cn + jj*16;
            float gv[4];
            #pragma unroll
            for (int g = 0; g < 4; g++) {
                const int n = g * HD + j;
                gv[g] = acc[rr][jj][g] + b_ih[n] + b_hh[n] + W_ih[n * AD + idx];
            }
            const float ig = sigmoidf_(gv[0]);
            const float fg = sigmoidf_(gv[1]);
            const float gg = tanhf(gv[2]);
            const float og = sigmoidf_(gv[3]);
            const float cc = fg * c_state[m * HD + j] + ig * gg;
            c_state[m * HD + j] = cc;
            h_out[m * HD + j]   = og * tanhf(cc);
        }
    }
}

// ============================================================================
// logits[m, t, n] = h[m,:] @ Wo[n,:] + bo[n]   (M=4096, N=128, K=512)
// ============================================================================
__global__ __launch_bounds__(256) void logits_kernel(
    const float* __restrict__ h,    // [4096,512]
    const float* __restrict__ Wo,   // [128,512]
    const float* __restrict__ bo,   // [128]
    float* __restrict__ out,        // [4096,16,128]
    int t)
{
    __shared__ float sA[64][17];
    __shared__ float sB[64][17];
    const int tx = threadIdx.x;
    const int cn = tx & 15;
    const int rm = tx >> 4;
    const int m0 = blockIdx.x * 64;
    const int n0 = blockIdx.y * 64;

    float acc[4][4];
    #pragma unroll
    for (int i = 0; i < 4; i++)
        #pragma unroll
        for (int j = 0; j < 4; j++) acc[i][j] = 0.0f;

    for (int k0 = 0; k0 < HD; k0 += 16) {
        const int r  = tx >> 2;
        const int kq = (tx & 3) << 2;
        float4 va = *(const float4*)&h [(m0 + r) * HD + k0 + kq];
        sA[r][kq+0] = va.x; sA[r][kq+1] = va.y; sA[r][kq+2] = va.z; sA[r][kq+3] = va.w;
        float4 vb = *(const float4*)&Wo[(n0 + r) * HD + k0 + kq];
        sB[r][kq+0] = vb.x; sB[r][kq+1] = vb.y; sB[r][kq+2] = vb.z; sB[r][kq+3] = vb.w;
        __syncthreads();
        #pragma unroll
        for (int kk = 0; kk < 16; kk++) {
            float a[4], b[4];
            #pragma unroll
            for (int rr = 0; rr < 4; rr++) a[rr] = sA[rm + rr*16][kk];
            #pragma unroll
            for (int jj = 0; jj < 4; jj++) b[jj] = sB[cn + jj*16][kk];
            #pragma unroll
            for (int rr = 0; rr < 4; rr++)
                #pragma unroll
                for (int jj = 0; jj < 4; jj++) acc[rr][jj] += a[rr] * b[jj];
        }
        __syncthreads();
    }

    #pragma unroll
    for (int rr = 0; rr < 4; rr++) {
        const int m = m0 + rm + rr*16;
        #pragma unroll
        for (int jj = 0; jj < 4; jj++) {
            const int n = n0 + cn + jj*16;
            out[m * (CD * AD) + t * AD + n] = acc[rr][jj] + bo[n];
        }
    }
}

// ============================================================================
// kernel_launch: h0 GEMM, then 16 x (fused LSTM step + logits GEMM).
// All launches on the default stream -> graph-capturable, no allocs.
// ============================================================================
extern "C" void kernel_launch(void* const* d_in, const int* in_sizes, int n_in,
                              void* d_out, int out_size)
{
    const float* X    = (const float*)d_in[0];  // quantized_repr [32,128,256]
    const int*   tc   = (const int*)  d_in[1];  // target_chars   [32,128,16]
    const float* Wp   = (const float*)d_in[2];  // [512,256]
    const float* bp   = (const float*)d_in[3];  // [512]
    const float* Wih  = (const float*)d_in[4];  // [2048,128]
    const float* Whh  = (const float*)d_in[5];  // [2048,512]
    const float* bih  = (const float*)d_in[6];  // [2048]
    const float* bhh  = (const float*)d_in[7];  // [2048]
    const float* Wo   = (const float*)d_in[8];  // [128,512]
    const float* bo   = (const float*)d_in[9];  // [128]
    float* out = (float*)d_out;                 // [32,128,16,128]

    float *hA, *hB, *cS;
    cudaGetSymbolAddress((void**)&hA, g_hA);
    cudaGetSymbolAddress((void**)&hB, g_hB);
    cudaGetSymbolAddress((void**)&cS, g_c);

    // h0 projection + zero cell state
    h0_kernel<<<dim3(BWN/64, HD/64), 256>>>(X, Wp, bp, hA, cS);

    // 16 teacher-forced steps
    for (int t = 0; t < CD; t++) {
        const float* hin  = (t & 1) ? hB : hA;
        float*       hout = (t & 1) ? hA : hB;
        lstm_step_kernel<<<dim3(BWN/64, HD/64), 256>>>(
            hin, hout, cS, Whh, Wih, bih, bhh, tc, t);
        logits_kernel<<<dim3(BWN/64, AD/64), 256>>>(hout, Wo, bo, out, t);
    }
}

// round 3
// speedup vs baseline: 2.2175x; 2.2175x over previous
#include <cuda_runtime.h>
#include <cuda_bf16.h>
#include <math.h>
#include <stdint.h>

// Problem dims (fixed)
#define BWN 4096   // B*W
#define HD  512    // hidden
#define QD  256    // quantized repr
#define AD  128    // alphabet
#define CD  16     // chars per word
#define G4H 2048   // 4*H

// ============================================================================
// PTX helpers (compute_103-safe: mma.sync / ldmatrix / cp.async only)
// ============================================================================
__device__ __forceinline__ uint32_t smem_u32(const void* p) {
    uint32_t a;
    asm("{ .reg .u64 t; cvta.to.shared.u64 t, %1; cvt.u32.u64 %0, t; }"
        : "=r"(a) : "l"(p));
    return a;
}
__device__ __forceinline__ void ldmatrix_x4(uint32_t& r0, uint32_t& r1,
                                            uint32_t& r2, uint32_t& r3,
                                            uint32_t addr) {
    asm volatile("ldmatrix.sync.aligned.m8n8.x4.shared.b16 {%0,%1,%2,%3}, [%4];"
                 : "=r"(r0), "=r"(r1), "=r"(r2), "=r"(r3) : "r"(addr));
}
__device__ __forceinline__ void ldmatrix_x2(uint32_t& r0, uint32_t& r1,
                                            uint32_t addr) {
    asm volatile("ldmatrix.sync.aligned.m8n8.x2.shared.b16 {%0,%1}, [%2];"
                 : "=r"(r0), "=r"(r1) : "r"(addr));
}
__device__ __forceinline__ void mma16816(float (&d)[4], const uint32_t (&a)[4],
                                         const uint32_t (&b)[2]) {
    asm volatile("mma.sync.aligned.m16n8k16.row.col.f32.bf16.bf16.f32 "
                 "{%0,%1,%2,%3}, {%4,%5,%6,%7}, {%8,%9}, {%0,%1,%2,%3};"
                 : "+f"(d[0]), "+f"(d[1]), "+f"(d[2]), "+f"(d[3])
                 : "r"(a[0]), "r"(a[1]), "r"(a[2]), "r"(a[3]),
                   "r"(b[0]), "r"(b[1]));
}
__device__ __forceinline__ void cp_async16(uint32_t saddr, const void* g) {
    asm volatile("cp.async.cg.shared.global [%0], [%1], 16;"
                 :: "r"(saddr), "l"(g) : "memory");
}
#define CP_COMMIT() asm volatile("cp.async.commit_group;" ::: "memory")
#define CP_WAIT0()  asm volatile("cp.async.wait_group 0;" ::: "memory")

// ============================================================================
// Device state (no allocation allowed)
// ============================================================================
__device__ __nv_bfloat16 g_hhi0[BWN * HD], g_hlo0[BWN * HD];
__device__ __nv_bfloat16 g_hhi1[BWN * HD], g_hlo1[BWN * HD];
__device__ float         g_c[BWN * HD];                        // MMA-fragment layout
__device__ __nv_bfloat16 g_WPhi[G4H * HD], g_WPlo[G4H * HD];   // gate-permuted W_hh
__device__ __nv_bfloat16 g_WoHi[AD * HD],  g_WoLo[AD * HD];
__device__ float         g_xbT[AD * G4H];                      // fragment-ordered xbias

__device__ __forceinline__ void bf16_split(float v, __nv_bfloat16& hi, __nv_bfloat16& lo) {
    hi = __float2bfloat16(v);
    lo = __float2bfloat16(v - __bfloat162float(hi));
}
__device__ __forceinline__ float sigmoidf_(float x) { return 1.0f / (1.0f + expf(-x)); }

// ============================================================================
// Prep kernels
// Permuted row p (within block bn of 128): p = bn*128 + wn*32 + g*8 + jl,
// original n = g*512 + (bn*32 + wn*8 + jl).
// ============================================================================
__global__ void prep_whh(const float* __restrict__ Whh,
                         __nv_bfloat16* __restrict__ Phi,
                         __nv_bfloat16* __restrict__ Plo) {
    int i = blockIdx.x * 256 + threadIdx.x;        // over 2048*512
    int p = i >> 9, k = i & 511;
    int bn = p >> 7, r = p & 127;
    int wn = r >> 5, cw = r & 31, g = cw >> 3, jl = cw & 7;
    int n = g * HD + bn * 32 + wn * 8 + jl;
    __nv_bfloat16 hi, lo; bf16_split(Whh[n * HD + k], hi, lo);
    Phi[i] = hi; Plo[i] = lo;
}
// xbT[q], q = ((a*16 + bn)*4 + wn)*32 + jl*4 + g
__global__ void prep_xbias(const float* __restrict__ Wih,
                           const float* __restrict__ bih,
                           const float* __restrict__ bhh,
                           float* __restrict__ xb) {
    int q = blockIdx.x * 256 + threadIdx.x;        // over 128*2048
    int a = q >> 11, bn = (q >> 7) & 15, wn = (q >> 5) & 3, jl = (q >> 2) & 7, g = q & 3;
    int n = g * HD + bn * 32 + wn * 8 + jl;
    xb[q] = Wih[n * AD + a] + bih[n] + bhh[n];
}
__global__ void prep_wo(const float* __restrict__ Wo,
                        __nv_bfloat16* __restrict__ Phi,
                        __nv_bfloat16* __restrict__ Plo) {
    int i = blockIdx.x * 256 + threadIdx.x;        // over 128*512
    __nv_bfloat16 hi, lo; bf16_split(Wo[i], hi, lo);
    Phi[i] = hi; Plo[i] = lo;
}
__global__ void zero_c(float* __restrict__ c) {
    int i = blockIdx.x * 256 + threadIdx.x;
    *(float4*)(c + i * 4) = make_float4(0.f, 0.f, 0.f, 0.f);
}

// ============================================================================
// h0 = X @ Wp^T + bp  (SIMT fp32, M=4096 N=512 K=256) -> bf16 hi/lo split
// ============================================================================
__global__ __launch_bounds__(256) void h0_kernel(
    const float* __restrict__ X, const float* __restrict__ Wp,
    const float* __restrict__ bp,
    __nv_bfloat16* __restrict__ hhi, __nv_bfloat16* __restrict__ hlo)
{
    __shared__ float sA[64][17];
    __shared__ float sB[64][17];
    const int tx = threadIdx.x;
    const int cn = tx & 15, rm = tx >> 4;
    const int m0 = blockIdx.x * 64, n0 = blockIdx.y * 64;

    float acc[4][4];
    #pragma unroll
    for (int i = 0; i < 4; i++)
        #pragma unroll
        for (int j = 0; j < 4; j++) acc[i][j] = 0.0f;

    for (int k0 = 0; k0 < QD; k0 += 16) {
        const int r = tx >> 2, kq = (tx & 3) << 2;
        float4 va = *(const float4*)&X [(m0 + r) * QD + k0 + kq];
        sA[r][kq+0] = va.x; sA[r][kq+1] = va.y; sA[r][kq+2] = va.z; sA[r][kq+3] = va.w;
        float4 vb = *(const float4*)&Wp[(n0 + r) * QD + k0 + kq];
        sB[r][kq+0] = vb.x; sB[r][kq+1] = vb.y; sB[r][kq+2] = vb.z; sB[r][kq+3] = vb.w;
        __syncthreads();
        #pragma unroll
        for (int kk = 0; kk < 16; kk++) {
            float a[4], b[4];
            #pragma unroll
            for (int rr = 0; rr < 4; rr++) a[rr] = sA[rm + rr*16][kk];
            #pragma unroll
            for (int jj = 0; jj < 4; jj++) b[jj] = sB[cn + jj*16][kk];
            #pragma unroll
            for (int rr = 0; rr < 4; rr++)
                #pragma unroll
                for (int jj = 0; jj < 4; jj++) acc[rr][jj] += a[rr] * b[jj];
        }
        __syncthreads();
    }
    #pragma unroll
    for (int rr = 0; rr < 4; rr++) {
        const int m = m0 + rm + rr*16;
        #pragma unroll
        for (int jj = 0; jj < 4; jj++) {
            const int n = n0 + cn + jj*16;
            __nv_bfloat16 hi, lo; bf16_split(acc[rr][jj] + bp[n], hi, lo);
            hhi[m * HD + n] = hi;
            hlo[m * HD + n] = lo;
        }
    }
}

// ============================================================================
// Fused HMMA LSTM step. grid(32,16), 256 threads (8 warps, 2m x 4n).
// Block tile 128m x 128p; warp tile 64m x 32p (p = wn*32 + gate*8 + jl).
// 3 split passes: Ahi*Bhi + Ahi*Blo + Alo*Bhi. K pipelined 8 x 64, cp.async x2.
// SMEM tile: row stride 72 bf16 (144B) for conflict-free ldmatrix.
// ============================================================================
#define T_BYTES  18432          // 128 * 144
#define S_ALO    T_BYTES
#define S_BHI    (2 * T_BYTES)
#define S_BLO    (3 * T_BYTES)
#define STAGE_BYTES (4 * T_BYTES)
#define GEMM_SMEM (2 * STAGE_BYTES)

__global__ __launch_bounds__(256) void gates_kernel(
    int t,
    const __nv_bfloat16* __restrict__ hin_hi,
    const __nv_bfloat16* __restrict__ hin_lo,
    __nv_bfloat16* __restrict__ hout_hi,
    __nv_bfloat16* __restrict__ hout_lo,
    const __nv_bfloat16* __restrict__ WPhi,
    const __nv_bfloat16* __restrict__ WPlo,
    const float* __restrict__ xbT,
    const int* __restrict__ chars,
    float* __restrict__ cst)
{
    extern __shared__ char smem[];
    __shared__ int sIdx[128];
    const int tid = threadIdx.x;
    const int wid = tid >> 5, lane = tid & 31;
    const int wm = wid >> 2, wn = wid & 3;
    const int bm = blockIdx.x, bn = blockIdx.y;
    const int m0 = bm * 128, p0 = bn * 128;
    const uint32_t sb = smem_u32(smem);

    if (tid < 128) {
        int idx = 0;
        if (t > 0) {
            int c = chars[(m0 + tid) * CD + (t - 1)];
            idx = (c >= 0 && c < AD) ? c : 0;
        }
        sIdx[tid] = idx;
    }

    float acc[4][4][4];
    #pragma unroll
    for (int a = 0; a < 4; a++)
        #pragma unroll
        for (int b = 0; b < 4; b++)
            #pragma unroll
            for (int c = 0; c < 4; c++) acc[a][b][c] = 0.0f;

    auto issue_loads = [&](int kc, int stage) {
        const int k0 = kc * 64;
        const uint32_t s0 = sb + stage * STAGE_BYTES;
        #pragma unroll
        for (int i = 0; i < 4; i++) {
            const int e = tid + i * 256;
            const int r = e >> 3, ck = e & 7;
            const uint32_t so = (uint32_t)(r * 144 + ck * 16);
            const int ga = (m0 + r) * HD + k0 + ck * 8;
            cp_async16(s0 + so,         hin_hi + ga);
            cp_async16(s0 + S_ALO + so, hin_lo + ga);
            const int gb = (p0 + r) * HD + k0 + ck * 8;
            cp_async16(s0 + S_BHI + so, WPhi + gb);
            cp_async16(s0 + S_BLO + so, WPlo + gb);
        }
        CP_COMMIT();
    };

    const int arow = (lane & 7) + ((lane >> 3) & 1) * 8;
    const int acol = (lane >> 4) * 8;
    const int brow = lane & 7;
    const int bcol = (((lane & 15) >> 3) & 1) * 8;

    issue_loads(0, 0);
    for (int kc = 0; kc < 8; kc++) {
        CP_WAIT0();
        __syncthreads();
        if (kc < 7) issue_loads(kc + 1, (kc + 1) & 1);
        const uint32_t s0 = sb + (kc & 1) * STAGE_BYTES;
        #pragma unroll
        for (int ks = 0; ks < 4; ks++) {
            uint32_t ahi[4][4], alo[4][4], bhi[4][2], blo[4][2];
            #pragma unroll
            for (int mi = 0; mi < 4; mi++) {
                const uint32_t ao = (uint32_t)(((wm*64 + mi*16 + arow) * 72 + ks*16 + acol) * 2);
                ldmatrix_x4(ahi[mi][0], ahi[mi][1], ahi[mi][2], ahi[mi][3], s0 + ao);
                ldmatrix_x4(alo[mi][0], alo[mi][1], alo[mi][2], alo[mi][3], s0 + S_ALO + ao);
            }
            #pragma unroll
            for (int f = 0; f < 4; f++) {
                const uint32_t bo_ = (uint32_t)(((wn*32 + f*8 + brow) * 72 + ks*16 + bcol) * 2);
                ldmatrix_x2(bhi[f][0], bhi[f][1], s0 + S_BHI + bo_);
                ldmatrix_x2(blo[f][0], blo[f][1], s0 + S_BLO + bo_);
            }
            #pragma unroll
            for (int mi = 0; mi < 4; mi++)
                #pragma unroll
                for (int f = 0; f < 4; f++) mma16816(acc[mi][f], ahi[mi], bhi[f]);
            #pragma unroll
            for (int mi = 0; mi < 4; mi++)
                #pragma unroll
                for (int f = 0; f < 4; f++) mma16816(acc[mi][f], ahi[mi], blo[f]);
            #pragma unroll
            for (int mi = 0; mi < 4; mi++)
                #pragma unroll
                for (int f = 0; f < 4; f++) mma16816(acc[mi][f], alo[mi], bhi[f]);
        }
        __syncthreads();
    }

    // Epilogue: gates -> LSTM cell update. acc[mi][gate][k], k = rh*2 + cp.
    const int lr = lane >> 2;
    const int lc = (lane & 3) * 2;
    float* cp_base = cst + (((bm * 16 + bn) * 8 + wid) * 512 + lane * 16);

    #pragma unroll
    for (int mi = 0; mi < 4; mi++) {
        float4 cold = *(float4*)(cp_base + mi * 4);
        float cn_[4];
        #pragma unroll
        for (int rh = 0; rh < 2; rh++) {
            const int mloc = wm*64 + mi*16 + lr + rh*8;
            const int idx = sIdx[mloc];
            const float* xb = xbT + ((idx * 16 + bn) * 4 + wn) * 32 + lc * 4;
            const float4 x0 = *(const float4*)xb;
            const float4 x1 = *(const float4*)(xb + 4);
            float hv[2];
            #pragma unroll
            for (int cpp = 0; cpp < 2; cpp++) {
                const float4 xv = cpp ? x1 : x0;
                const int k = rh * 2 + cpp;
                const float gi = acc[mi][0][k] + xv.x;
                const float gf = acc[mi][1][k] + xv.y;
                const float gg = acc[mi][2][k] + xv.z;
                const float go = acc[mi][3][k] + xv.w;
                const float co = (k == 0) ? cold.x : (k == 1) ? cold.y
                               : (k == 2) ? cold.z : cold.w;
                const float cn = sigmoidf_(gf) * co + sigmoidf_(gi) * tanhf(gg);
                cn_[k] = cn;
                hv[cpp] = sigmoidf_(go) * tanhf(cn);
            }
            const int m = m0 + mloc;
            const int j = bn * 32 + wn * 8 + lc;
            __nv_bfloat16 h0h, h0l, h1h, h1l;
            bf16_split(hv[0], h0h, h0l);
            bf16_split(hv[1], h1h, h1l);
            const uint32_t ph = (uint32_t)__bfloat16_as_ushort(h0h)
                              | ((uint32_t)__bfloat16_as_ushort(h1h) << 16);
            const uint32_t pl = (uint32_t)__bfloat16_as_ushort(h0l)
                              | ((uint32_t)__bfloat16_as_ushort(h1l) << 16);
            *(uint32_t*)(hout_hi + m * HD + j) = ph;
            *(uint32_t*)(hout_lo + m * HD + j) = pl;
        }
        *(float4*)(cp_base + mi * 4) = make_float4(cn_[0], cn_[1], cn_[2], cn_[3]);
    }
}

// ============================================================================
// HMMA logits: out[m, t, n] = h @ Wo^T + bo  (M=4096, N=128, K=512). grid(32).
// ============================================================================
__global__ __launch_bounds__(256) void logits_kernel(
    const __nv_bfloat16* __restrict__ h_hi,
    const __nv_bfloat16* __restrict__ h_lo,
    const __nv_bfloat16* __restrict__ WoHi,
    const __nv_bfloat16* __restrict__ WoLo,
    const float* __restrict__ bo,
    float* __restrict__ out, int t)
{
    extern __shared__ char smem[];
    const int tid = threadIdx.x;
    const int wid = tid >> 5, lane = tid & 31;
    const int wm = wid >> 2, wn = wid & 3;
    const int m0 = blockIdx.x * 128;
    const uint32_t sb = smem_u32(smem);

    float acc[4][4][4];
    #pragma unroll
    for (int a = 0; a < 4; a++)
        #pragma unroll
        for (int b = 0; b < 4; b++)
            #pragma unroll
            for (int c = 0; c < 4; c++) acc[a][b][c] = 0.0f;

    auto issue_loads = [&](int kc, int stage) {
        const int k0 = kc * 64;
        const uint32_t s0 = sb + stage * STAGE_BYTES;
        #pragma unroll
        for (int i = 0; i < 4; i++) {
            const int e = tid + i * 256;
            const int r = e >> 3, ck = e & 7;
            const uint32_t so = (uint32_t)(r * 144 + ck * 16);
            const int ga = (m0 + r) * HD + k0 + ck * 8;
            cp_async16(s0 + so,         h_hi + ga);
            cp_async16(s0 + S_ALO + so, h_lo + ga);
            const int gb = r * HD + k0 + ck * 8;     // Wo rows 0..127
            cp_async16(s0 + S_BHI + so, WoHi + gb);
            cp_async16(s0 + S_BLO + so, WoLo + gb);
        }
        CP_COMMIT();
    };

    const int arow = (lane & 7) + ((lane >> 3) & 1) * 8;
    const int acol = (lane >> 4) * 8;
    const int brow = lane & 7;
    const int bcol = (((lane & 15) >> 3) & 1) * 8;

    issue_loads(0, 0);
    for (int kc = 0; kc < 8; kc++) {
        CP_WAIT0();
        __syncthreads();
        if (kc < 7) issue_loads(kc + 1, (kc + 1) & 1);
        const uint32_t s0 = sb + (kc & 1) * STAGE_BYTES;
        #pragma unroll
        for (int ks = 0; ks < 4; ks++) {
            uint32_t ahi[4][4], alo[4][4], bhi[4][2], blo[4][2];
            #pragma unroll
            for (int mi = 0; mi < 4; mi++) {
                const uint32_t ao = (uint32_t)(((wm*64 + mi*16 + arow) * 72 + ks*16 + acol) * 2);
                ldmatrix_x4(ahi[mi][0], ahi[mi][1], ahi[mi][2], ahi[mi][3], s0 + ao);
                ldmatrix_x4(alo[mi][0], alo[mi][1], alo[mi][2], alo[mi][3], s0 + S_ALO + ao);
            }
            #pragma unroll
            for (int f = 0; f < 4; f++) {
                const uint32_t bo_ = (uint32_t)(((wn*32 + f*8 + brow) * 72 + ks*16 + bcol) * 2);
                ldmatrix_x2(bhi[f][0], bhi[f][1], s0 + S_BHI + bo_);
                ldmatrix_x2(blo[f][0], blo[f][1], s0 + S_BLO + bo_);
            }
            #pragma unroll
            for (int mi = 0; mi < 4; mi++)
                #pragma unroll
                for (int f = 0; f < 4; f++) mma16816(acc[mi][f], ahi[mi], bhi[f]);
            #pragma unroll
            for (int mi = 0; mi < 4; mi++)
                #pragma unroll
                for (int f = 0; f < 4; f++) mma16816(acc[mi][f], ahi[mi], blo[f]);
            #pragma unroll
            for (int mi = 0; mi < 4; mi++)
                #pragma unroll
                for (int f = 0; f < 4; f++) mma16816(acc[mi][f], alo[mi], bhi[f]);
        }
        __syncthreads();
    }

    const int lr = lane >> 2;
    const int lc = (lane & 3) * 2;
    #pragma unroll
    for (int mi = 0; mi < 4; mi++) {
        #pragma unroll
        for (int rh = 0; rh < 2; rh++) {
            const int m = m0 + wm*64 + mi*16 + lr + rh*8;
            float* orow = out + m * (CD * AD) + t * AD;
            #pragma unroll
            for (int f = 0; f < 4; f++) {
                const int n = wn*32 + f*8 + lc;
                const float2 b2 = *(const float2*)(bo + n);
                float2 v;
                v.x = acc[mi][f][rh*2 + 0] + b2.x;
                v.y = acc[mi][f][rh*2 + 1] + b2.y;
                *(float2*)(orow + n) = v;
            }
        }
    }
}

// ============================================================================
// kernel_launch
// ============================================================================
extern "C" void kernel_launch(void* const* d_in, const int* in_sizes, int n_in,
                              void* d_out, int out_size)
{
    const float* X    = (const float*)d_in[0];
    const int*   tc   = (const int*)  d_in[1];
    const float* Wp   = (const float*)d_in[2];
    const float* bp   = (const float*)d_in[3];
    const float* Wih  = (const float*)d_in[4];
    const float* Whh  = (const float*)d_in[5];
    const float* bih  = (const float*)d_in[6];
    const float* bhh  = (const float*)d_in[7];
    const float* Wo   = (const float*)d_in[8];
    const float* bo   = (const float*)d_in[9];
    float* out = (float*)d_out;

    __nv_bfloat16 *hhi0, *hlo0, *hhi1, *hlo1, *wphi, *wplo, *wohi, *wolo;
    float *cS, *xb;
    cudaGetSymbolAddress((void**)&hhi0, g_hhi0);
    cudaGetSymbolAddress((void**)&hlo0, g_hlo0);
    cudaGetSymbolAddress((void**)&hhi1, g_hhi1);
    cudaGetSymbolAddress((void**)&hlo1, g_hlo1);
    cudaGetSymbolAddress((void**)&cS,   g_c);
    cudaGetSymbolAddress((void**)&wphi, g_WPhi);
    cudaGetSymbolAddress((void**)&wplo, g_WPlo);
    cudaGetSymbolAddress((void**)&wohi, g_WoHi);
    cudaGetSymbolAddress((void**)&wolo, g_WoLo);
    cudaGetSymbolAddress((void**)&xb,   g_xbT);

    cudaFuncSetAttribute(gates_kernel,  cudaFuncAttributeMaxDynamicSharedMemorySize, GEMM_SMEM);
    cudaFuncSetAttribute(logits_kernel, cudaFuncAttributeMaxDynamicSharedMemorySize, GEMM_SMEM);

    prep_whh  <<<(G4H * HD) / 256, 256>>>(Whh, wphi, wplo);
    prep_xbias<<<(AD * G4H) / 256, 256>>>(Wih, bih, bhh, xb);
    prep_wo   <<<(AD * HD) / 256, 256>>>(Wo, wohi, wolo);
    zero_c    <<<(BWN * HD) / 1024, 256>>>(cS);
    h0_kernel <<<dim3(BWN / 64, HD / 64), 256>>>(X, Wp, bp, hhi0, hlo0);

    for (int t = 0; t < CD; t++) {
        const __nv_bfloat16* ihh = (t & 1) ? hhi1 : hhi0;
        const __nv_bfloat16* ihl = (t & 1) ? hlo1 : hlo0;
        __nv_bfloat16* ohh = (t & 1) ? hhi0 : hhi1;
        __nv_bfloat16* ohl = (t & 1) ? hlo0 : hlo1;
        gates_kernel<<<dim3(BWN / 128, G4H / 128), 256, GEMM_SMEM>>>(
            t, ihh, ihl, ohh, ohl, wphi, wplo, xb, tc, cS);
        logits_kernel<<<BWN / 128, 256, GEMM_SMEM>>>(ohh, ohl, wohi, wolo, bo, out, t);
    }
}

// round 4
// speedup vs baseline: 2.8833x; 1.3002x over previous
#include <cuda_runtime.h>
#include <cuda_bf16.h>
#include <math.h>
#include <stdint.h>

// Problem dims (fixed)
#define BWN 4096   // B*W
#define HD  512    // hidden
#define QD  256    // quantized repr
#define AD  128    // alphabet
#define CD  16     // chars per word
#define G4H 2048   // 4*H

// ============================================================================
// PTX helpers (compute_103-safe: mma.sync / ldmatrix / cp.async only)
// ============================================================================
__device__ __forceinline__ uint32_t smem_u32(const void* p) {
    uint32_t a;
    asm("{ .reg .u64 t; cvta.to.shared.u64 t, %1; cvt.u32.u64 %0, t; }"
        : "=r"(a) : "l"(p));
    return a;
}
__device__ __forceinline__ void ldmatrix_x4(uint32_t& r0, uint32_t& r1,
                                            uint32_t& r2, uint32_t& r3,
                                            uint32_t addr) {
    asm volatile("ldmatrix.sync.aligned.m8n8.x4.shared.b16 {%0,%1,%2,%3}, [%4];"
                 : "=r"(r0), "=r"(r1), "=r"(r2), "=r"(r3) : "r"(addr));
}
__device__ __forceinline__ void ldmatrix_x2(uint32_t& r0, uint32_t& r1,
                                            uint32_t addr) {
    asm volatile("ldmatrix.sync.aligned.m8n8.x2.shared.b16 {%0,%1}, [%2];"
                 : "=r"(r0), "=r"(r1) : "r"(addr));
}
__device__ __forceinline__ void mma16816(float (&d)[4], const uint32_t (&a)[4],
                                         const uint32_t (&b)[2]) {
    asm volatile("mma.sync.aligned.m16n8k16.row.col.f32.bf16.bf16.f32 "
                 "{%0,%1,%2,%3}, {%4,%5,%6,%7}, {%8,%9}, {%0,%1,%2,%3};"
                 : "+f"(d[0]), "+f"(d[1]), "+f"(d[2]), "+f"(d[3])
                 : "r"(a[0]), "r"(a[1]), "r"(a[2]), "r"(a[3]),
                   "r"(b[0]), "r"(b[1]));
}
__device__ __forceinline__ void cp_async16(uint32_t saddr, const void* g) {
    asm volatile("cp.async.cg.shared.global [%0], [%1], 16;"
                 :: "r"(saddr), "l"(g) : "memory");
}
#define CP_COMMIT() asm volatile("cp.async.commit_group;" ::: "memory")
#define CP_WAIT0()  asm volatile("cp.async.wait_group 0;" ::: "memory")

// ============================================================================
// Device state (no allocation allowed)
// ============================================================================
__device__ __nv_bfloat16 g_hhi0[BWN * HD], g_hlo0[BWN * HD];
__device__ __nv_bfloat16 g_hhi1[BWN * HD], g_hlo1[BWN * HD];
__device__ float         g_c[BWN * HD];                        // MMA-fragment layout
__device__ __nv_bfloat16 g_WPhi[G4H * HD], g_WPlo[G4H * HD];   // gate-permuted W_hh
__device__ __nv_bfloat16 g_WoHi[AD * HD],  g_WoLo[AD * HD];
__device__ float         g_xbT[AD * G4H];                      // fragment-ordered xbias

__device__ __forceinline__ void bf16_split(float v, __nv_bfloat16& hi, __nv_bfloat16& lo) {
    hi = __float2bfloat16(v);
    lo = __float2bfloat16(v - __bfloat162float(hi));
}
__device__ __forceinline__ float sigmoidf_(float x) { return 1.0f / (1.0f + expf(-x)); }

// ============================================================================
// Prep kernels
// Permuted row p (within block bn of 128): p = bn*128 + wn*32 + g*8 + jl,
// original n = g*512 + (bn*32 + wn*8 + jl).
// ============================================================================
__global__ void prep_whh(const float* __restrict__ Whh,
                         __nv_bfloat16* __restrict__ Phi,
                         __nv_bfloat16* __restrict__ Plo) {
    int i = blockIdx.x * 256 + threadIdx.x;        // over 2048*512
    int p = i >> 9, k = i & 511;
    int bn = p >> 7, r = p & 127;
    int wn = r >> 5, cw = r & 31, g = cw >> 3, jl = cw & 7;
    int n = g * HD + bn * 32 + wn * 8 + jl;
    __nv_bfloat16 hi, lo; bf16_split(Whh[n * HD + k], hi, lo);
    Phi[i] = hi; Plo[i] = lo;
}
// xbT[q], q = ((a*16 + bn)*4 + wn)*32 + jl*4 + g
__global__ void prep_xbias(const float* __restrict__ Wih,
                           const float* __restrict__ bih,
                           const float* __restrict__ bhh,
                           float* __restrict__ xb) {
    int q = blockIdx.x * 256 + threadIdx.x;        // over 128*2048
    int a = q >> 11, bn = (q >> 7) & 15, wn = (q >> 5) & 3, jl = (q >> 2) & 7, g = q & 3;
    int n = g * HD + bn * 32 + wn * 8 + jl;
    xb[q] = Wih[n * AD + a] + bih[n] + bhh[n];
}
__global__ void prep_wo(const float* __restrict__ Wo,
                        __nv_bfloat16* __restrict__ Phi,
                        __nv_bfloat16* __restrict__ Plo) {
    int i = blockIdx.x * 256 + threadIdx.x;        // over 128*512
    __nv_bfloat16 hi, lo; bf16_split(Wo[i], hi, lo);
    Phi[i] = hi; Plo[i] = lo;
}
__global__ void zero_c(float* __restrict__ c) {
    int i = blockIdx.x * 256 + threadIdx.x;
    *(float4*)(c + i * 4) = make_float4(0.f, 0.f, 0.f, 0.f);
}

// ============================================================================
// h0 = X @ Wp^T + bp  (SIMT fp32, M=4096 N=512 K=256) -> bf16 hi/lo split
// ============================================================================
__global__ __launch_bounds__(256) void h0_kernel(
    const float* __restrict__ X, const float* __restrict__ Wp,
    const float* __restrict__ bp,
    __nv_bfloat16* __restrict__ hhi, __nv_bfloat16* __restrict__ hlo)
{
    __shared__ float sA[64][17];
    __shared__ float sB[64][17];
    const int tx = threadIdx.x;
    const int cn = tx & 15, rm = tx >> 4;
    const int m0 = blockIdx.x * 64, n0 = blockIdx.y * 64;

    float acc[4][4];
    #pragma unroll
    for (int i = 0; i < 4; i++)
        #pragma unroll
        for (int j = 0; j < 4; j++) acc[i][j] = 0.0f;

    for (int k0 = 0; k0 < QD; k0 += 16) {
        const int r = tx >> 2, kq = (tx & 3) << 2;
        float4 va = *(const float4*)&X [(m0 + r) * QD + k0 + kq];
        sA[r][kq+0] = va.x; sA[r][kq+1] = va.y; sA[r][kq+2] = va.z; sA[r][kq+3] = va.w;
        float4 vb = *(const float4*)&Wp[(n0 + r) * QD + k0 + kq];
        sB[r][kq+0] = vb.x; sB[r][kq+1] = vb.y; sB[r][kq+2] = vb.z; sB[r][kq+3] = vb.w;
        __syncthreads();
        #pragma unroll
        for (int kk = 0; kk < 16; kk++) {
            float a[4], b[4];
            #pragma unroll
            for (int rr = 0; rr < 4; rr++) a[rr] = sA[rm + rr*16][kk];
            #pragma unroll
            for (int jj = 0; jj < 4; jj++) b[jj] = sB[cn + jj*16][kk];
            #pragma unroll
            for (int rr = 0; rr < 4; rr++)
                #pragma unroll
                for (int jj = 0; jj < 4; jj++) acc[rr][jj] += a[rr] * b[jj];
        }
        __syncthreads();
    }
    #pragma unroll
    for (int rr = 0; rr < 4; rr++) {
        const int m = m0 + rm + rr*16;
        #pragma unroll
        for (int jj = 0; jj < 4; jj++) {
            const int n = n0 + cn + jj*16;
            __nv_bfloat16 hi, lo; bf16_split(acc[rr][jj] + bp[n], hi, lo);
            hhi[m * HD + n] = hi;
            hlo[m * HD + n] = lo;
        }
    }
}

// ============================================================================
// Fused HMMA LSTM step. grid(32,16), 256 threads (8 warps, 2m x 4n).
// Block tile 128m x 128p; warp tile 64m x 32p.
// K pipelined 16 x 32 (KC=32), double-buffered cp.async.
// Tile row stride = 80B: 8 consecutive rows hit 8 distinct 16B bank slots
// (r*80 mod 128 = {0,80,32,112,64,16,96,48}) -> conflict-free LDSM, and
// stage = 4 * 10.24KB = 40.96KB; 2 stages = 81.9KB -> 2 CTAs/SM resident.
// ============================================================================
#define T80      10240          // 128 * 80
#define S_ALO    T80
#define S_BHI    (2 * T80)
#define S_BLO    (3 * T80)
#define STAGE_BYTES (4 * T80)
#define GEMM_SMEM (2 * STAGE_BYTES)

__global__ __launch_bounds__(256, 2) void gates_kernel(
    int t,
    const __nv_bfloat16* __restrict__ hin_hi,
    const __nv_bfloat16* __restrict__ hin_lo,
    __nv_bfloat16* __restrict__ hout_hi,
    __nv_bfloat16* __restrict__ hout_lo,
    const __nv_bfloat16* __restrict__ WPhi,
    const __nv_bfloat16* __restrict__ WPlo,
    const float* __restrict__ xbT,
    const int* __restrict__ chars,
    float* __restrict__ cst)
{
    extern __shared__ char smem[];
    __shared__ int sIdx[128];
    const int tid = threadIdx.x;
    const int wid = tid >> 5, lane = tid & 31;
    const int wm = wid >> 2, wn = wid & 3;
    const int bm = blockIdx.x, bn = blockIdx.y;
    const int m0 = bm * 128, p0 = bn * 128;
    const uint32_t sb = smem_u32(smem);

    if (tid < 128) {
        int idx = 0;
        if (t > 0) {
            int c = chars[(m0 + tid) * CD + (t - 1)];
            idx = (c >= 0 && c < AD) ? c : 0;
        }
        sIdx[tid] = idx;
    }

    float acc[4][4][4];
    #pragma unroll
    for (int a = 0; a < 4; a++)
        #pragma unroll
        for (int b = 0; b < 4; b++)
            #pragma unroll
            for (int c = 0; c < 4; c++) acc[a][b][c] = 0.0f;

    auto issue_loads = [&](int kc, int stage) {
        const int k0 = kc * 32;
        const uint32_t s0 = sb + stage * STAGE_BYTES;
        #pragma unroll
        for (int i = 0; i < 2; i++) {
            const int e = tid + i * 256;              // 0..511
            const int r = e >> 2, ck = e & 3;
            const uint32_t so = (uint32_t)(r * 80 + ck * 16);
            const int ga = (m0 + r) * HD + k0 + ck * 8;
            cp_async16(s0 + so,         hin_hi + ga);
            cp_async16(s0 + S_ALO + so, hin_lo + ga);
            const int gb = (p0 + r) * HD + k0 + ck * 8;
            cp_async16(s0 + S_BHI + so, WPhi + gb);
            cp_async16(s0 + S_BLO + so, WPlo + gb);
        }
        CP_COMMIT();
    };

    const int arow = (lane & 7) + ((lane >> 3) & 1) * 8;
    const int acol = (lane >> 4) * 8;
    const int brow = lane & 7;
    const int bcol = ((lane >> 3) & 1) * 8;

    issue_loads(0, 0);
    for (int kc = 0; kc < 16; kc++) {
        CP_WAIT0();
        __syncthreads();
        if (kc < 15) issue_loads(kc + 1, (kc + 1) & 1);
        const uint32_t s0 = sb + (kc & 1) * STAGE_BYTES;
        #pragma unroll
        for (int ks = 0; ks < 2; ks++) {
            // pass 1: Ahi * Bhi
            uint32_t ahi[4][4], bhi[4][2];
            #pragma unroll
            for (int mi = 0; mi < 4; mi++) {
                const uint32_t ao = (uint32_t)((wm*64 + mi*16 + arow) * 80 + (ks*16 + acol) * 2);
                ldmatrix_x4(ahi[mi][0], ahi[mi][1], ahi[mi][2], ahi[mi][3], s0 + ao);
            }
            #pragma unroll
            for (int f = 0; f < 4; f++) {
                const uint32_t bo_ = (uint32_t)((wn*32 + f*8 + brow) * 80 + (ks*16 + bcol) * 2);
                ldmatrix_x2(bhi[f][0], bhi[f][1], s0 + S_BHI + bo_);
            }
            #pragma unroll
            for (int mi = 0; mi < 4; mi++)
                #pragma unroll
                for (int f = 0; f < 4; f++) mma16816(acc[mi][f], ahi[mi], bhi[f]);
            // pass 2: Ahi * Blo
            uint32_t blo[4][2];
            #pragma unroll
            for (int f = 0; f < 4; f++) {
                const uint32_t bo_ = (uint32_t)((wn*32 + f*8 + brow) * 80 + (ks*16 + bcol) * 2);
                ldmatrix_x2(blo[f][0], blo[f][1], s0 + S_BLO + bo_);
            }
            #pragma unroll
            for (int mi = 0; mi < 4; mi++)
                #pragma unroll
                for (int f = 0; f < 4; f++) mma16816(acc[mi][f], ahi[mi], blo[f]);
            // pass 3: Alo * Bhi
            uint32_t alo[4][4];
            #pragma unroll
            for (int mi = 0; mi < 4; mi++) {
                const uint32_t ao = (uint32_t)((wm*64 + mi*16 + arow) * 80 + (ks*16 + acol) * 2);
                ldmatrix_x4(alo[mi][0], alo[mi][1], alo[mi][2], alo[mi][3], s0 + S_ALO + ao);
            }
            #pragma unroll
            for (int mi = 0; mi < 4; mi++)
                #pragma unroll
                for (int f = 0; f < 4; f++) mma16816(acc[mi][f], alo[mi], bhi[f]);
        }
        __syncthreads();
    }

    // Epilogue: gates -> LSTM cell update. acc[mi][gate][k], k = rh*2 + cp.
    const int lr = lane >> 2;
    const int lc = (lane & 3) * 2;
    float* cp_base = cst + (((bm * 16 + bn) * 8 + wid) * 512 + lane * 16);

    #pragma unroll
    for (int mi = 0; mi < 4; mi++) {
        float4 cold = *(float4*)(cp_base + mi * 4);
        float cn_[4];
        #pragma unroll
        for (int rh = 0; rh < 2; rh++) {
            const int mloc = wm*64 + mi*16 + lr + rh*8;
            const int idx = sIdx[mloc];
            const float* xb = xbT + ((idx * 16 + bn) * 4 + wn) * 32 + lc * 4;
            const float4 x0 = *(const float4*)xb;
            const float4 x1 = *(const float4*)(xb + 4);
            float hv[2];
            #pragma unroll
            for (int cpp = 0; cpp < 2; cpp++) {
                const float4 xv = cpp ? x1 : x0;
                const int k = rh * 2 + cpp;
                const float gi = acc[mi][0][k] + xv.x;
                const float gf = acc[mi][1][k] + xv.y;
                const float gg = acc[mi][2][k] + xv.z;
                const float go = acc[mi][3][k] + xv.w;
                const float co = (k == 0) ? cold.x : (k == 1) ? cold.y
                               : (k == 2) ? cold.z : cold.w;
                const float cn = sigmoidf_(gf) * co + sigmoidf_(gi) * tanhf(gg);
                cn_[k] = cn;
                hv[cpp] = sigmoidf_(go) * tanhf(cn);
            }
            const int m = m0 + mloc;
            const int j = bn * 32 + wn * 8 + lc;
            __nv_bfloat16 h0h, h0l, h1h, h1l;
            bf16_split(hv[0], h0h, h0l);
            bf16_split(hv[1], h1h, h1l);
            const uint32_t ph = (uint32_t)__bfloat16_as_ushort(h0h)
                              | ((uint32_t)__bfloat16_as_ushort(h1h) << 16);
            const uint32_t pl = (uint32_t)__bfloat16_as_ushort(h0l)
                              | ((uint32_t)__bfloat16_as_ushort(h1l) << 16);
            *(uint32_t*)(hout_hi + m * HD + j) = ph;
            *(uint32_t*)(hout_lo + m * HD + j) = pl;
        }
        *(float4*)(cp_base + mi * 4) = make_float4(cn_[0], cn_[1], cn_[2], cn_[3]);
    }
}

// ============================================================================
// HMMA logits: out[m, t, n] = h @ Wo^T + bo. M-tile 32 -> grid 128 (full chip).
// 8 warps, warp tile 32m x 16n. KC=32 double-buffered, stride-80 tiles.
// ============================================================================
#define LT_A     2560           // 32 * 80
#define LS_ALO   LT_A
#define LS_BHI   (2 * LT_A)
#define LS_BLO   (LS_BHI + T80)
#define LSTAGE_BYTES (LS_BLO + T80)
#define LOGIT_SMEM (2 * LSTAGE_BYTES)

__global__ __launch_bounds__(256) void logits_kernel(
    const __nv_bfloat16* __restrict__ h_hi,
    const __nv_bfloat16* __restrict__ h_lo,
    const __nv_bfloat16* __restrict__ WoHi,
    const __nv_bfloat16* __restrict__ WoLo,
    const float* __restrict__ bo,
    float* __restrict__ out, int t)
{
    extern __shared__ char smem[];
    const int tid = threadIdx.x;
    const int wid = tid >> 5, lane = tid & 31;
    const int m0 = blockIdx.x * 32;
    const uint32_t sb = smem_u32(smem);

    float acc[2][2][4];
    #pragma unroll
    for (int a = 0; a < 2; a++)
        #pragma unroll
        for (int b = 0; b < 2; b++)
            #pragma unroll
            for (int c = 0; c < 4; c++) acc[a][b][c] = 0.0f;

    auto issue_loads = [&](int kc, int stage) {
        const int k0 = kc * 32;
        const uint32_t s0 = sb + stage * LSTAGE_BYTES;
        if (tid < 128) {                              // A: 32 rows x 4 chunks
            const int r = tid >> 2, ck = tid & 3;
            const uint32_t so = (uint32_t)(r * 80 + ck * 16);
            const int ga = (m0 + r) * HD + k0 + ck * 8;
            cp_async16(s0 + so,          h_hi + ga);
            cp_async16(s0 + LS_ALO + so, h_lo + ga);
        }
        #pragma unroll
        for (int i = 0; i < 2; i++) {                 // B: 128 rows x 4 chunks
            const int e = tid + i * 256;
            const int r = e >> 2, ck = e & 3;
            const uint32_t so = (uint32_t)(r * 80 + ck * 16);
            const int gb = r * HD + k0 + ck * 8;
            cp_async16(s0 + LS_BHI + so, WoHi + gb);
            cp_async16(s0 + LS_BLO + so, WoLo + gb);
        }
        CP_COMMIT();
    };

    const int arow = (lane & 7) + ((lane >> 3) & 1) * 8;
    const int acol = (lane >> 4) * 8;
    const int brow = lane & 7;
    const int bcol = ((lane >> 3) & 1) * 8;

    issue_loads(0, 0);
    for (int kc = 0; kc < 16; kc++) {
        CP_WAIT0();
        __syncthreads();
        if (kc < 15) issue_loads(kc + 1, (kc + 1) & 1);
        const uint32_t s0 = sb + (kc & 1) * LSTAGE_BYTES;
        #pragma unroll
        for (int ks = 0; ks < 2; ks++) {
            uint32_t ahi[2][4], alo[2][4], bhi[2][2], blo[2][2];
            #pragma unroll
            for (int mi = 0; mi < 2; mi++) {
                const uint32_t ao = (uint32_t)((mi*16 + arow) * 80 + (ks*16 + acol) * 2);
                ldmatrix_x4(ahi[mi][0], ahi[mi][1], ahi[mi][2], ahi[mi][3], s0 + ao);
                ldmatrix_x4(alo[mi][0], alo[mi][1], alo[mi][2], alo[mi][3], s0 + LS_ALO + ao);
            }
            #pragma unroll
            for (int f = 0; f < 2; f++) {
                const uint32_t bo_ = (uint32_t)((wid*16 + f*8 + brow) * 80 + (ks*16 + bcol) * 2);
                ldmatrix_x2(bhi[f][0], bhi[f][1], s0 + LS_BHI + bo_);
                ldmatrix_x2(blo[f][0], blo[f][1], s0 + LS_BLO + bo_);
            }
            #pragma unroll
            for (int mi = 0; mi < 2; mi++)
                #pragma unroll
                for (int f = 0; f < 2; f++) {
                    mma16816(acc[mi][f], ahi[mi], bhi[f]);
                    mma16816(acc[mi][f], ahi[mi], blo[f]);
                    mma16816(acc[mi][f], alo[mi], bhi[f]);
                }
        }
        __syncthreads();
    }

    const int lr = lane >> 2;
    const int lc = (lane & 3) * 2;
    #pragma unroll
    for (int mi = 0; mi < 2; mi++) {
        #pragma unroll
        for (int rh = 0; rh < 2; rh++) {
            const int m = m0 + mi*16 + lr + rh*8;
            float* orow = out + m * (CD * AD) + t * AD;
            #pragma unroll
            for (int f = 0; f < 2; f++) {
                const int n = wid*16 + f*8 + lc;
                const float2 b2 = *(const float2*)(bo + n);
                float2 v;
                v.x = acc[mi][f][rh*2 + 0] + b2.x;
                v.y = acc[mi][f][rh*2 + 1] + b2.y;
                *(float2*)(orow + n) = v;
            }
        }
    }
}

// ============================================================================
// kernel_launch
// ============================================================================
extern "C" void kernel_launch(void* const* d_in, const int* in_sizes, int n_in,
                              void* d_out, int out_size)
{
    const float* X    = (const float*)d_in[0];
    const int*   tc   = (const int*)  d_in[1];
    const float* Wp   = (const float*)d_in[2];
    const float* bp   = (const float*)d_in[3];
    const float* Wih  = (const float*)d_in[4];
    const float* Whh  = (const float*)d_in[5];
    const float* bih  = (const float*)d_in[6];
    const float* bhh  = (const float*)d_in[7];
    const float* Wo   = (const float*)d_in[8];
    const float* bo   = (const float*)d_in[9];
    float* out = (float*)d_out;

    __nv_bfloat16 *hhi0, *hlo0, *hhi1, *hlo1, *wphi, *wplo, *wohi, *wolo;
    float *cS, *xb;
    cudaGetSymbolAddress((void**)&hhi0, g_hhi0);
    cudaGetSymbolAddress((void**)&hlo0, g_hlo0);
    cudaGetSymbolAddress((void**)&hhi1, g_hhi1);
    cudaGetSymbolAddress((void**)&hlo1, g_hlo1);
    cudaGetSymbolAddress((void**)&cS,   g_c);
    cudaGetSymbolAddress((void**)&wphi, g_WPhi);
    cudaGetSymbolAddress((void**)&wplo, g_WPlo);
    cudaGetSymbolAddress((void**)&wohi, g_WoHi);
    cudaGetSymbolAddress((void**)&wolo, g_WoLo);
    cudaGetSymbolAddress((void**)&xb,   g_xbT);

    cudaFuncSetAttribute(gates_kernel,  cudaFuncAttributeMaxDynamicSharedMemorySize, GEMM_SMEM);
    cudaFuncSetAttribute(logits_kernel, cudaFuncAttributeMaxDynamicSharedMemorySize, LOGIT_SMEM);

    prep_whh  <<<(G4H * HD) / 256, 256>>>(Whh, wphi, wplo);
    prep_xbias<<<(AD * G4H) / 256, 256>>>(Wih, bih, bhh, xb);
    prep_wo   <<<(AD * HD) / 256, 256>>>(Wo, wohi, wolo);
    zero_c    <<<(BWN * HD) / 1024, 256>>>(cS);
    h0_kernel <<<dim3(BWN / 64, HD / 64), 256>>>(X, Wp, bp, hhi0, hlo0);

    for (int t = 0; t < CD; t++) {
        const __nv_bfloat16* ihh = (t & 1) ? hhi1 : hhi0;
        const __nv_bfloat16* ihl = (t & 1) ? hlo1 : hlo0;
        __nv_bfloat16* ohh = (t & 1) ? hhi0 : hhi1;
        __nv_bfloat16* ohl = (t & 1) ? hlo0 : hlo1;
        gates_kernel<<<dim3(BWN / 128, G4H / 128), 256, GEMM_SMEM>>>(
            t, ihh, ihl, ohh, ohl, wphi, wplo, xb, tc, cS);
        logits_kernel<<<BWN / 32, 256, LOGIT_SMEM>>>(ohh, ohl, wohi, wolo, bo, out, t);
    }
}

// round 5
// speedup vs baseline: 4.2766x; 1.4833x over previous
#include <cuda_runtime.h>
#include <cuda_fp16.h>
#include <math.h>
#include <stdint.h>

// Problem dims (fixed)
#define BWN 4096   // B*W
#define HD  512    // hidden
#define QD  256    // quantized repr
#define AD  128    // alphabet
#define CD  16     // chars per word
#define G4H 2048   // 4*H

// ============================================================================
// PTX helpers (compute_103-safe: mma.sync / ldmatrix / cp.async only)
// ============================================================================
__device__ __forceinline__ uint32_t smem_u32(const void* p) {
    uint32_t a;
    asm("{ .reg .u64 t; cvta.to.shared.u64 t, %1; cvt.u32.u64 %0, t; }"
        : "=r"(a) : "l"(p));
    return a;
}
__device__ __forceinline__ void ldmatrix_x4(uint32_t& r0, uint32_t& r1,
                                            uint32_t& r2, uint32_t& r3,
                                            uint32_t addr) {
    asm volatile("ldmatrix.sync.aligned.m8n8.x4.shared.b16 {%0,%1,%2,%3}, [%4];"
                 : "=r"(r0), "=r"(r1), "=r"(r2), "=r"(r3) : "r"(addr));
}
__device__ __forceinline__ void ldmatrix_x2(uint32_t& r0, uint32_t& r1,
                                            uint32_t addr) {
    asm volatile("ldmatrix.sync.aligned.m8n8.x2.shared.b16 {%0,%1}, [%2];"
                 : "=r"(r0), "=r"(r1) : "r"(addr));
}
__device__ __forceinline__ void mma16816(float (&d)[4], const uint32_t (&a)[4],
                                         const uint32_t (&b)[2]) {
    asm volatile("mma.sync.aligned.m16n8k16.row.col.f32.f16.f16.f32 "
                 "{%0,%1,%2,%3}, {%4,%5,%6,%7}, {%8,%9}, {%0,%1,%2,%3};"
                 : "+f"(d[0]), "+f"(d[1]), "+f"(d[2]), "+f"(d[3])
                 : "r"(a[0]), "r"(a[1]), "r"(a[2]), "r"(a[3]),
                   "r"(b[0]), "r"(b[1]));
}
__device__ __forceinline__ void cp_async16(uint32_t saddr, const void* g) {
    asm volatile("cp.async.cg.shared.global [%0], [%1], 16;"
                 :: "r"(saddr), "l"(g) : "memory");
}
#define CP_COMMIT() asm volatile("cp.async.commit_group;" ::: "memory")
#define CP_WAIT0()  asm volatile("cp.async.wait_group 0;" ::: "memory")

// ============================================================================
// Device state (no allocation allowed)
// ============================================================================
__device__ __half g_h0[BWN * HD];                    // hidden, fp16 (|h| <= 1)
__device__ __half g_h1[BWN * HD];
__device__ float  g_c[BWN * HD];                     // MMA-fragment layout
__device__ __half g_WPhi[G4H * HD], g_WPlo[G4H * HD];// gate-permuted W_hh fp16 split
__device__ __half g_WoHi[AD * HD],  g_WoLo[AD * HD]; // Wo fp16 split
__device__ float  g_xbT[AD * G4H];                   // fragment-ordered xbias

__device__ __forceinline__ void f16_split(float v, __half& hi, __half& lo) {
    hi = __float2half_rn(v);
    lo = __float2half_rn(v - __half2float(hi));
}
__device__ __forceinline__ float sigmoidf_(float x) { return 1.0f / (1.0f + expf(-x)); }

// ============================================================================
// Prep kernels
// Permuted row p: p = bn*128 + wn*32 + g*8 + jl, original n = g*512 + bn*32 + wn*8 + jl.
// ============================================================================
__global__ void prep_whh(const float* __restrict__ Whh,
                         __half* __restrict__ Phi, __half* __restrict__ Plo) {
    int i = blockIdx.x * 256 + threadIdx.x;        // over 2048*512
    int p = i >> 9, k = i & 511;
    int bn = p >> 7, r = p & 127;
    int wn = r >> 5, cw = r & 31, g = cw >> 3, jl = cw & 7;
    int n = g * HD + bn * 32 + wn * 8 + jl;
    __half hi, lo; f16_split(Whh[n * HD + k], hi, lo);
    Phi[i] = hi; Plo[i] = lo;
}
// Combined: blocks [0,1024) -> xbias (128*2048), blocks [1024,1280) -> Wo split (128*512)
__global__ void prep_comb(const float* __restrict__ Wih,
                          const float* __restrict__ bih,
                          const float* __restrict__ bhh,
                          const float* __restrict__ Wo,
                          float* __restrict__ xb,
                          __half* __restrict__ WoHi, __half* __restrict__ WoLo) {
    if (blockIdx.x < 1024) {
        int q = blockIdx.x * 256 + threadIdx.x;    // xbT[q], q = ((a*16+bn)*4+wn)*32 + jl*4 + g
        int a = q >> 11, bn = (q >> 7) & 15, wn = (q >> 5) & 3, jl = (q >> 2) & 7, g = q & 3;
        int n = g * HD + bn * 32 + wn * 8 + jl;
        xb[q] = Wih[n * AD + a] + bih[n] + bhh[n];
    } else {
        int i = (blockIdx.x - 1024) * 256 + threadIdx.x;   // over 128*512
        __half hi, lo; f16_split(Wo[i], hi, lo);
        WoHi[i] = hi; WoLo[i] = lo;
    }
}

// ============================================================================
// h0 = X @ Wp^T + bp  (SIMT fp32, M=4096 N=512 K=256) -> fp16
// ============================================================================
__global__ __launch_bounds__(256) void h0_kernel(
    const float* __restrict__ X, const float* __restrict__ Wp,
    const float* __restrict__ bp, __half* __restrict__ hout)
{
    __shared__ float sA[64][17];
    __shared__ float sB[64][17];
    const int tx = threadIdx.x;
    const int cn = tx & 15, rm = tx >> 4;
    const int m0 = blockIdx.x * 64, n0 = blockIdx.y * 64;

    float acc[4][4];
    #pragma unroll
    for (int i = 0; i < 4; i++)
        #pragma unroll
        for (int j = 0; j < 4; j++) acc[i][j] = 0.0f;

    for (int k0 = 0; k0 < QD; k0 += 16) {
        const int r = tx >> 2, kq = (tx & 3) << 2;
        float4 va = *(const float4*)&X [(m0 + r) * QD + k0 + kq];
        sA[r][kq+0] = va.x; sA[r][kq+1] = va.y; sA[r][kq+2] = va.z; sA[r][kq+3] = va.w;
        float4 vb = *(const float4*)&Wp[(n0 + r) * QD + k0 + kq];
        sB[r][kq+0] = vb.x; sB[r][kq+1] = vb.y; sB[r][kq+2] = vb.z; sB[r][kq+3] = vb.w;
        __syncthreads();
        #pragma unroll
        for (int kk = 0; kk < 16; kk++) {
            float a[4], b[4];
            #pragma unroll
            for (int rr = 0; rr < 4; rr++) a[rr] = sA[rm + rr*16][kk];
            #pragma unroll
            for (int jj = 0; jj < 4; jj++) b[jj] = sB[cn + jj*16][kk];
            #pragma unroll
            for (int rr = 0; rr < 4; rr++)
                #pragma unroll
                for (int jj = 0; jj < 4; jj++) acc[rr][jj] += a[rr] * b[jj];
        }
        __syncthreads();
    }
    #pragma unroll
    for (int rr = 0; rr < 4; rr++) {
        const int m = m0 + rm + rr*16;
        #pragma unroll
        for (int jj = 0; jj < 4; jj++) {
            const int n = n0 + cn + jj*16;
            hout[m * HD + n] = __float2half_rn(acc[rr][jj] + bp[n]);
        }
    }
}

// ============================================================================
// Fused HMMA LSTM step. grid(32,16), 256 threads (8 warps, 2m x 4n).
// Block tile 128m x 128p; warp tile 64m x 32p. fp16 2-pass: A single fp16,
// B = Bhi + Blo fp16 split (error source is A quantization only, ~2^-12).
// K pipelined 8 x 64 (KC=64), double-buffered cp.async.
// Tile row stride 144B (conflict-free LDSM). Stage = 3*18432B = 55.3KB,
// 2 stages = 110.6KB -> 2 CTAs/SM resident.
// ============================================================================
#define T144     18432          // 128 * 144
#define S_BHI    T144
#define S_BLO    (2 * T144)
#define STAGE_BYTES (3 * T144)
#define GEMM_SMEM (2 * STAGE_BYTES)

__global__ __launch_bounds__(256, 2) void gates_kernel(
    int t,
    const __half* __restrict__ hin,
    __half*       __restrict__ hout,
    const __half* __restrict__ WPhi,
    const __half* __restrict__ WPlo,
    const float* __restrict__ xbT,
    const int* __restrict__ chars,
    float* __restrict__ cst)
{
    extern __shared__ char smem[];
    __shared__ int sIdx[128];
    const int tid = threadIdx.x;
    const int wid = tid >> 5, lane = tid & 31;
    const int wm = wid >> 2, wn = wid & 3;
    const int bm = blockIdx.x, bn = blockIdx.y;
    const int m0 = bm * 128, p0 = bn * 128;
    const uint32_t sb = smem_u32(smem);

    if (tid < 128) {
        int idx = 0;
        if (t > 0) {
            int c = chars[(m0 + tid) * CD + (t - 1)];
            idx = (c >= 0 && c < AD) ? c : 0;
        }
        sIdx[tid] = idx;
    }

    float acc[4][4][4];
    #pragma unroll
    for (int a = 0; a < 4; a++)
        #pragma unroll
        for (int b = 0; b < 4; b++)
            #pragma unroll
            for (int c = 0; c < 4; c++) acc[a][b][c] = 0.0f;

    auto issue_loads = [&](int kc, int stage) {
        const int k0 = kc * 64;
        const uint32_t s0 = sb + stage * STAGE_BYTES;
        #pragma unroll
        for (int i = 0; i < 4; i++) {
            const int e = tid + i * 256;              // 0..1023
            const int r = e >> 3, ck = e & 7;
            const uint32_t so = (uint32_t)(r * 144 + ck * 16);
            const int ga = (m0 + r) * HD + k0 + ck * 8;
            cp_async16(s0 + so, hin + ga);
            const int gb = (p0 + r) * HD + k0 + ck * 8;
            cp_async16(s0 + S_BHI + so, WPhi + gb);
            cp_async16(s0 + S_BLO + so, WPlo + gb);
        }
        CP_COMMIT();
    };

    const int arow = (lane & 7) + ((lane >> 3) & 1) * 8;
    const int acol = (lane >> 4) * 8;
    const int brow = lane & 7;
    const int bcol = ((lane >> 3) & 1) * 8;

    issue_loads(0, 0);
    for (int kc = 0; kc < 8; kc++) {
        CP_WAIT0();
        __syncthreads();
        if (kc < 7) issue_loads(kc + 1, (kc + 1) & 1);
        const uint32_t s0 = sb + (kc & 1) * STAGE_BYTES;
        #pragma unroll
        for (int ks = 0; ks < 4; ks++) {
            uint32_t af[4][4], bhi[4][2], blo[4][2];
            #pragma unroll
            for (int mi = 0; mi < 4; mi++) {
                const uint32_t ao = (uint32_t)((wm*64 + mi*16 + arow) * 144 + (ks*16 + acol) * 2);
                ldmatrix_x4(af[mi][0], af[mi][1], af[mi][2], af[mi][3], s0 + ao);
            }
            #pragma unroll
            for (int f = 0; f < 4; f++) {
                const uint32_t bo_ = (uint32_t)((wn*32 + f*8 + brow) * 144 + (ks*16 + bcol) * 2);
                ldmatrix_x2(bhi[f][0], bhi[f][1], s0 + S_BHI + bo_);
                ldmatrix_x2(blo[f][0], blo[f][1], s0 + S_BLO + bo_);
            }
            #pragma unroll
            for (int mi = 0; mi < 4; mi++)
                #pragma unroll
                for (int f = 0; f < 4; f++) mma16816(acc[mi][f], af[mi], bhi[f]);
            #pragma unroll
            for (int mi = 0; mi < 4; mi++)
                #pragma unroll
                for (int f = 0; f < 4; f++) mma16816(acc[mi][f], af[mi], blo[f]);
        }
        __syncthreads();
    }

    // Epilogue: gates -> LSTM cell update. acc[mi][gate][k], k = rh*2 + cp.
    const int lr = lane >> 2;
    const int lc = (lane & 3) * 2;
    float* cp_base = cst + (((bm * 16 + bn) * 8 + wid) * 512 + lane * 16);

    #pragma unroll
    for (int mi = 0; mi < 4; mi++) {
        float4 cold = (t > 0) ? *(float4*)(cp_base + mi * 4)
                              : make_float4(0.f, 0.f, 0.f, 0.f);
        float cn_[4];
        #pragma unroll
        for (int rh = 0; rh < 2; rh++) {
            const int mloc = wm*64 + mi*16 + lr + rh*8;
            const int idx = sIdx[mloc];
            const float* xb = xbT + ((idx * 16 + bn) * 4 + wn) * 32 + lc * 4;
            const float4 x0 = *(const float4*)xb;
            const float4 x1 = *(const float4*)(xb + 4);
            __half hv[2];
            #pragma unroll
            for (int cpp = 0; cpp < 2; cpp++) {
                const float4 xv = cpp ? x1 : x0;
                const int k = rh * 2 + cpp;
                const float gi = acc[mi][0][k] + xv.x;
                const float gf = acc[mi][1][k] + xv.y;
                const float gg = acc[mi][2][k] + xv.z;
                const float go = acc[mi][3][k] + xv.w;
                const float co = (k == 0) ? cold.x : (k == 1) ? cold.y
                               : (k == 2) ? cold.z : cold.w;
                const float cn = sigmoidf_(gf) * co + sigmoidf_(gi) * tanhf(gg);
                cn_[k] = cn;
                hv[cpp] = __float2half_rn(sigmoidf_(go) * tanhf(cn));
            }
            const int m = m0 + mloc;
            const int j = bn * 32 + wn * 8 + lc;
            const uint32_t ph = (uint32_t)__half_as_ushort(hv[0])
                              | ((uint32_t)__half_as_ushort(hv[1]) << 16);
            *(uint32_t*)(hout + m * HD + j) = ph;
        }
        *(float4*)(cp_base + mi * 4) = make_float4(cn_[0], cn_[1], cn_[2], cn_[3]);
    }
}

// ============================================================================
// HMMA logits: out[m, t, n] = h @ Wo^T + bo. M-tile 32, grid 128 (full chip).
// 8 warps, warp tile 32m x 16n. fp16 2-pass, KC=64 double-buffered.
// ============================================================================
#define LT_A     4608           // 32 * 144
#define LS_BHI   LT_A
#define LS_BLO   (LT_A + T144)
#define LSTAGE_BYTES (LT_A + 2 * T144)
#define LOGIT_SMEM (2 * LSTAGE_BYTES)

__global__ __launch_bounds__(256, 2) void logits_kernel(
    const __half* __restrict__ h,
    const __half* __restrict__ WoHi,
    const __half* __restrict__ WoLo,
    const float* __restrict__ bo,
    float* __restrict__ out, int t)
{
    extern __shared__ char smem[];
    const int tid = threadIdx.x;
    const int wid = tid >> 5, lane = tid & 31;
    const int m0 = blockIdx.x * 32;
    const uint32_t sb = smem_u32(smem);

    float acc[2][2][4];
    #pragma unroll
    for (int a = 0; a < 2; a++)
        #pragma unroll
        for (int b = 0; b < 2; b++)
            #pragma unroll
            for (int c = 0; c < 4; c++) acc[a][b][c] = 0.0f;

    auto issue_loads = [&](int kc, int stage) {
        const int k0 = kc * 64;
        const uint32_t s0 = sb + stage * LSTAGE_BYTES;
        {                                             // A: 32 rows x 8 chunks
            const int r = tid >> 3, ck = tid & 7;
            if (r < 32) {
                const uint32_t so = (uint32_t)(r * 144 + ck * 16);
                cp_async16(s0 + so, h + (m0 + r) * HD + k0 + ck * 8);
            }
        }
        #pragma unroll
        for (int i = 0; i < 4; i++) {                 // B: 128 rows x 8 chunks
            const int e = tid + i * 256;
            const int r = e >> 3, ck = e & 7;
            const uint32_t so = (uint32_t)(r * 144 + ck * 16);
            const int gb = r * HD + k0 + ck * 8;
            cp_async16(s0 + LS_BHI + so, WoHi + gb);
            cp_async16(s0 + LS_BLO + so, WoLo + gb);
        }
        CP_COMMIT();
    };

    const int arow = (lane & 7) + ((lane >> 3) & 1) * 8;
    const int acol = (lane >> 4) * 8;
    const int brow = lane & 7;
    const int bcol = ((lane >> 3) & 1) * 8;

    issue_loads(0, 0);
    for (int kc = 0; kc < 8; kc++) {
        CP_WAIT0();
        __syncthreads();
        if (kc < 7) issue_loads(kc + 1, (kc + 1) & 1);
        const uint32_t s0 = sb + (kc & 1) * LSTAGE_BYTES;
        #pragma unroll
        for (int ks = 0; ks < 4; ks++) {
            uint32_t af[2][4], bhi[2][2], blo[2][2];
            #pragma unroll
            for (int mi = 0; mi < 2; mi++) {
                const uint32_t ao = (uint32_t)((mi*16 + arow) * 144 + (ks*16 + acol) * 2);
                ldmatrix_x4(af[mi][0], af[mi][1], af[mi][2], af[mi][3], s0 + ao);
            }
            #pragma unroll
            for (int f = 0; f < 2; f++) {
                const uint32_t bo_ = (uint32_t)((wid*16 + f*8 + brow) * 144 + (ks*16 + bcol) * 2);
                ldmatrix_x2(bhi[f][0], bhi[f][1], s0 + LS_BHI + bo_);
                ldmatrix_x2(blo[f][0], blo[f][1], s0 + LS_BLO + bo_);
            }
            #pragma unroll
            for (int mi = 0; mi < 2; mi++)
                #pragma unroll
                for (int f = 0; f < 2; f++) {
                    mma16816(acc[mi][f], af[mi], bhi[f]);
                    mma16816(acc[mi][f], af[mi], blo[f]);
                }
        }
        __syncthreads();
    }

    const int lr = lane >> 2;
    const int lc = (lane & 3) * 2;
    #pragma unroll
    for (int mi = 0; mi < 2; mi++) {
        #pragma unroll
        for (int rh = 0; rh < 2; rh++) {
            const int m = m0 + mi*16 + lr + rh*8;
            float* orow = out + m * (CD * AD) + t * AD;
            #pragma unroll
            for (int f = 0; f < 2; f++) {
                const int n = wid*16 + f*8 + lc;
                const float2 b2 = *(const float2*)(bo + n);
                float2 v;
                v.x = acc[mi][f][rh*2 + 0] + b2.x;
                v.y = acc[mi][f][rh*2 + 1] + b2.y;
                *(float2*)(orow + n) = v;
            }
        }
    }
}

// ============================================================================
// kernel_launch
// ============================================================================
extern "C" void kernel_launch(void* const* d_in, const int* in_sizes, int n_in,
                              void* d_out, int out_size)
{
    const float* X    = (const float*)d_in[0];
    const int*   tc   = (const int*)  d_in[1];
    const float* Wp   = (const float*)d_in[2];
    const float* bp   = (const float*)d_in[3];
    const float* Wih  = (const float*)d_in[4];
    const float* Whh  = (const float*)d_in[5];
    const float* bih  = (const float*)d_in[6];
    const float* bhh  = (const float*)d_in[7];
    const float* Wo   = (const float*)d_in[8];
    const float* bo   = (const float*)d_in[9];
    float* out = (float*)d_out;

    __half *h0b, *h1b, *wphi, *wplo, *wohi, *wolo;
    float *cS, *xb;
    cudaGetSymbolAddress((void**)&h0b,  g_h0);
    cudaGetSymbolAddress((void**)&h1b,  g_h1);
    cudaGetSymbolAddress((void**)&cS,   g_c);
    cudaGetSymbolAddress((void**)&wphi, g_WPhi);
    cudaGetSymbolAddress((void**)&wplo, g_WPlo);
    cudaGetSymbolAddress((void**)&wohi, g_WoHi);
    cudaGetSymbolAddress((void**)&wolo, g_WoLo);
    cudaGetSymbolAddress((void**)&xb,   g_xbT);

    cudaFuncSetAttribute(gates_kernel,  cudaFuncAttributeMaxDynamicSharedMemorySize, GEMM_SMEM);
    cudaFuncSetAttribute(logits_kernel, cudaFuncAttributeMaxDynamicSharedMemorySize, LOGIT_SMEM);

    prep_whh <<<(G4H * HD) / 256, 256>>>(Whh, wphi, wplo);
    prep_comb<<<1280, 256>>>(Wih, bih, bhh, Wo, xb, wohi, wolo);
    h0_kernel<<<dim3(BWN / 64, HD / 64), 256>>>(X, Wp, bp, h0b);

    for (int t = 0; t < CD; t++) {
        const __half* hin  = (t & 1) ? h1b : h0b;
        __half*       hout = (t & 1) ? h0b : h1b;
        gates_kernel<<<dim3(BWN / 128, G4H / 128), 256, GEMM_SMEM>>>(
            t, hin, hout, wphi, wplo, xb, tc, cS);
        logits_kernel<<<BWN / 32, 256, LOGIT_SMEM>>>(hout, wohi, wolo, bo, out, t);
    }
}

// round 6
// speedup vs baseline: 6.4064x; 1.4980x over previous
#include <cuda_runtime.h>
#include <cuda_fp16.h>
#include <math.h>
#include <stdint.h>

// Problem dims (fixed)
#define BWN 4096   // B*W
#define HD  512    // hidden
#define QD  256    // quantized repr
#define AD  128    // alphabet
#define CD  16     // chars per word
#define G4H 2048   // 4*H

// ============================================================================
// PTX helpers (compute_103-safe: mma.sync / ldmatrix / cp.async only)
// ============================================================================
__device__ __forceinline__ uint32_t smem_u32(const void* p) {
    uint32_t a;
    asm("{ .reg .u64 t; cvta.to.shared.u64 t, %1; cvt.u32.u64 %0, t; }"
        : "=r"(a) : "l"(p));
    return a;
}
__device__ __forceinline__ void ldmatrix_x4(uint32_t& r0, uint32_t& r1,
                                            uint32_t& r2, uint32_t& r3,
                                            uint32_t addr) {
    asm volatile("ldmatrix.sync.aligned.m8n8.x4.shared.b16 {%0,%1,%2,%3}, [%4];"
                 : "=r"(r0), "=r"(r1), "=r"(r2), "=r"(r3) : "r"(addr));
}
__device__ __forceinline__ void ldmatrix_x2(uint32_t& r0, uint32_t& r1,
                                            uint32_t addr) {
    asm volatile("ldmatrix.sync.aligned.m8n8.x2.shared.b16 {%0,%1}, [%2];"
                 : "=r"(r0), "=r"(r1) : "r"(addr));
}
__device__ __forceinline__ void mma16816(float (&d)[4], const uint32_t (&a)[4],
                                         const uint32_t (&b)[2]) {
    asm volatile("mma.sync.aligned.m16n8k16.row.col.f32.f16.f16.f32 "
                 "{%0,%1,%2,%3}, {%4,%5,%6,%7}, {%8,%9}, {%0,%1,%2,%3};"
                 : "+f"(d[0]), "+f"(d[1]), "+f"(d[2]), "+f"(d[3])
                 : "r"(a[0]), "r"(a[1]), "r"(a[2]), "r"(a[3]),
                   "r"(b[0]), "r"(b[1]));
}
__device__ __forceinline__ void cp_async16(uint32_t saddr, const void* g) {
    asm volatile("cp.async.cg.shared.global [%0], [%1], 16;"
                 :: "r"(saddr), "l"(g) : "memory");
}
#define CP_COMMIT() asm volatile("cp.async.commit_group;" ::: "memory")
#define CP_WAIT1()  asm volatile("cp.async.wait_group 1;" ::: "memory")
#define CP_WAIT0()  asm volatile("cp.async.wait_group 0;" ::: "memory")

// ============================================================================
// Device state (no allocation allowed)
// ============================================================================
__device__ __half g_h0[BWN * HD];                    // hidden, fp16 (|h| <= 1)
__device__ __half g_h1[BWN * HD];
__device__ float  g_c[BWN * HD];                     // MMA-fragment layout
__device__ __half g_WP[G4H * HD];                    // gate-permuted W_hh fp16
__device__ __half g_Wo16[AD * HD];                   // Wo fp16
__device__ float  g_xbT[AD * G4H];                   // fragment-ordered xbias

__device__ __forceinline__ float sigmoidf_(float x) { return 1.0f / (1.0f + expf(-x)); }

// ============================================================================
// Prep kernels
// Permuted row p: p = bn*128 + wn*32 + g*8 + jl, original n = g*512 + bn*32 + wn*8 + jl.
// ============================================================================
__global__ void prep_whh(const float* __restrict__ Whh, __half* __restrict__ P) {
    int i = blockIdx.x * 256 + threadIdx.x;        // over 2048*512
    int p = i >> 9, k = i & 511;
    int bn = p >> 7, r = p & 127;
    int wn = r >> 5, cw = r & 31, g = cw >> 3, jl = cw & 7;
    int n = g * HD + bn * 32 + wn * 8 + jl;
    P[i] = __float2half_rn(Whh[n * HD + k]);
}
// Combined: blocks [0,1024) -> xbias (128*2048), blocks [1024,1280) -> Wo fp16 (128*512)
__global__ void prep_comb(const float* __restrict__ Wih,
                          const float* __restrict__ bih,
                          const float* __restrict__ bhh,
                          const float* __restrict__ Wo,
                          float* __restrict__ xb,
                          __half* __restrict__ Wo16) {
    if (blockIdx.x < 1024) {
        int q = blockIdx.x * 256 + threadIdx.x;    // xbT[q], q = ((a*16+bn)*4+wn)*32 + jl*4 + g
        int a = q >> 11, bn = (q >> 7) & 15, wn = (q >> 5) & 3, jl = (q >> 2) & 7, g = q & 3;
        int n = g * HD + bn * 32 + wn * 8 + jl;
        xb[q] = Wih[n * AD + a] + bih[n] + bhh[n];
    } else {
        int i = (blockIdx.x - 1024) * 256 + threadIdx.x;   // over 128*512
        Wo16[i] = __float2half_rn(Wo[i]);
    }
}

// ============================================================================
// h0 = X @ Wp^T + bp  (SIMT fp32, M=4096 N=512 K=256) -> fp16
// ============================================================================
__global__ __launch_bounds__(256) void h0_kernel(
    const float* __restrict__ X, const float* __restrict__ Wp,
    const float* __restrict__ bp, __half* __restrict__ hout)
{
    __shared__ float sA[64][17];
    __shared__ float sB[64][17];
    const int tx = threadIdx.x;
    const int cn = tx & 15, rm = tx >> 4;
    const int m0 = blockIdx.x * 64, n0 = blockIdx.y * 64;

    float acc[4][4];
    #pragma unroll
    for (int i = 0; i < 4; i++)
        #pragma unroll
        for (int j = 0; j < 4; j++) acc[i][j] = 0.0f;

    for (int k0 = 0; k0 < QD; k0 += 16) {
        const int r = tx >> 2, kq = (tx & 3) << 2;
        float4 va = *(const float4*)&X [(m0 + r) * QD + k0 + kq];
        sA[r][kq+0] = va.x; sA[r][kq+1] = va.y; sA[r][kq+2] = va.z; sA[r][kq+3] = va.w;
        float4 vb = *(const float4*)&Wp[(n0 + r) * QD + k0 + kq];
        sB[r][kq+0] = vb.x; sB[r][kq+1] = vb.y; sB[r][kq+2] = vb.z; sB[r][kq+3] = vb.w;
        __syncthreads();
        #pragma unroll
        for (int kk = 0; kk < 16; kk++) {
            float a[4], b[4];
            #pragma unroll
            for (int rr = 0; rr < 4; rr++) a[rr] = sA[rm + rr*16][kk];
            #pragma unroll
            for (int jj = 0; jj < 4; jj++) b[jj] = sB[cn + jj*16][kk];
            #pragma unroll
            for (int rr = 0; rr < 4; rr++)
                #pragma unroll
                for (int jj = 0; jj < 4; jj++) acc[rr][jj] += a[rr] * b[jj];
        }
        __syncthreads();
    }
    #pragma unroll
    for (int rr = 0; rr < 4; rr++) {
        const int m = m0 + rm + rr*16;
        #pragma unroll
        for (int jj = 0; jj < 4; jj++) {
            const int n = n0 + cn + jj*16;
            hout[m * HD + n] = __float2half_rn(acc[rr][jj] + bp[n]);
        }
    }
}

// ============================================================================
// Fused HMMA LSTM step. grid(32,16), 256 threads (8 warps, 2m x 4n).
// Block tile 128m x 128p; warp tile 64m x 32p. Single-pass fp16.
// K pipelined 8 x 64 (KC=64), 3-stage cp.async (wait_group 1).
// Tile row stride 144B (conflict-free LDSM). Stage = 2*18432B = 36.9KB,
// 3 stages = 110.6KB -> 2 CTAs/SM resident (221KB).
// ============================================================================
#define T144     18432          // 128 * 144
#define S_B      T144
#define STAGE_BYTES (2 * T144)
#define GEMM_SMEM (3 * STAGE_BYTES)

__global__ __launch_bounds__(256, 2) void gates_kernel(
    int t,
    const __half* __restrict__ hin,
    __half*       __restrict__ hout,
    const __half* __restrict__ WP,
    const float* __restrict__ xbT,
    const int* __restrict__ chars,
    float* __restrict__ cst)
{
    extern __shared__ char smem[];
    __shared__ int sIdx[128];
    const int tid = threadIdx.x;
    const int wid = tid >> 5, lane = tid & 31;
    const int wm = wid >> 2, wn = wid & 3;
    const int bm = blockIdx.x, bn = blockIdx.y;
    const int m0 = bm * 128, p0 = bn * 128;
    const uint32_t sb = smem_u32(smem);

    if (tid < 128) {
        int idx = 0;
        if (t > 0) {
            int c = chars[(m0 + tid) * CD + (t - 1)];
            idx = (c >= 0 && c < AD) ? c : 0;
        }
        sIdx[tid] = idx;
    }

    float acc[4][4][4];
    #pragma unroll
    for (int a = 0; a < 4; a++)
        #pragma unroll
        for (int b = 0; b < 4; b++)
            #pragma unroll
            for (int c = 0; c < 4; c++) acc[a][b][c] = 0.0f;

    auto issue_loads = [&](int kc, int stage) {
        const int k0 = kc * 64;
        const uint32_t s0 = sb + stage * STAGE_BYTES;
        #pragma unroll
        for (int i = 0; i < 4; i++) {
            const int e = tid + i * 256;              // 0..1023
            const int r = e >> 3, ck = e & 7;
            const uint32_t so = (uint32_t)(r * 144 + ck * 16);
            cp_async16(s0 + so,       hin + (m0 + r) * HD + k0 + ck * 8);
            cp_async16(s0 + S_B + so, WP  + (p0 + r) * HD + k0 + ck * 8);
        }
    };

    const int arow = (lane & 7) + ((lane >> 3) & 1) * 8;
    const int acol = (lane >> 4) * 8;
    const int brow = lane & 7;
    const int bcol = ((lane >> 3) & 1) * 8;

    issue_loads(0, 0); CP_COMMIT();
    issue_loads(1, 1); CP_COMMIT();
    int st = 0, st_w = 2;                             // compute stage / write stage
    for (int kc = 0; kc < 8; kc++) {
        CP_WAIT1();
        __syncthreads();
        if (kc < 6) issue_loads(kc + 2, st_w);
        CP_COMMIT();                                  // uniform (maybe empty) commit
        const uint32_t s0 = sb + st * STAGE_BYTES;
        #pragma unroll
        for (int ks = 0; ks < 4; ks++) {
            uint32_t af[4][4], bf[4][2];
            #pragma unroll
            for (int mi = 0; mi < 4; mi++) {
                const uint32_t ao = (uint32_t)((wm*64 + mi*16 + arow) * 144 + (ks*16 + acol) * 2);
                ldmatrix_x4(af[mi][0], af[mi][1], af[mi][2], af[mi][3], s0 + ao);
            }
            #pragma unroll
            for (int f = 0; f < 4; f++) {
                const uint32_t bo_ = (uint32_t)((wn*32 + f*8 + brow) * 144 + (ks*16 + bcol) * 2);
                ldmatrix_x2(bf[f][0], bf[f][1], s0 + S_B + bo_);
            }
            #pragma unroll
            for (int mi = 0; mi < 4; mi++)
                #pragma unroll
                for (int f = 0; f < 4; f++) mma16816(acc[mi][f], af[mi], bf[f]);
        }
        st = (st == 2) ? 0 : st + 1;
        st_w = (st_w == 2) ? 0 : st_w + 1;
    }

    // Epilogue: gates -> LSTM cell update. acc[mi][gate][k], k = rh*2 + cp.
    const int lr = lane >> 2;
    const int lc = (lane & 3) * 2;
    float* cp_base = cst + (((bm * 16 + bn) * 8 + wid) * 512 + lane * 16);

    #pragma unroll
    for (int mi = 0; mi < 4; mi++) {
        float4 cold = (t > 0) ? *(float4*)(cp_base + mi * 4)
                              : make_float4(0.f, 0.f, 0.f, 0.f);
        float cn_[4];
        #pragma unroll
        for (int rh = 0; rh < 2; rh++) {
            const int mloc = wm*64 + mi*16 + lr + rh*8;
            const int idx = sIdx[mloc];
            const float* xb = xbT + ((idx * 16 + bn) * 4 + wn) * 32 + lc * 4;
            const float4 x0 = *(const float4*)xb;
            const float4 x1 = *(const float4*)(xb + 4);
            __half hv[2];
            #pragma unroll
            for (int cpp = 0; cpp < 2; cpp++) {
                const float4 xv = cpp ? x1 : x0;
                const int k = rh * 2 + cpp;
                const float gi = acc[mi][0][k] + xv.x;
                const float gf = acc[mi][1][k] + xv.y;
                const float gg = acc[mi][2][k] + xv.z;
                const float go = acc[mi][3][k] + xv.w;
                const float co = (k == 0) ? cold.x : (k == 1) ? cold.y
                               : (k == 2) ? cold.z : cold.w;
                const float cn = sigmoidf_(gf) * co + sigmoidf_(gi) * tanhf(gg);
                cn_[k] = cn;
                hv[cpp] = __float2half_rn(sigmoidf_(go) * tanhf(cn));
            }
            const int m = m0 + mloc;
            const int j = bn * 32 + wn * 8 + lc;
            const uint32_t ph = (uint32_t)__half_as_ushort(hv[0])
                              | ((uint32_t)__half_as_ushort(hv[1]) << 16);
            *(uint32_t*)(hout + m * HD + j) = ph;
        }
        *(float4*)(cp_base + mi * 4) = make_float4(cn_[0], cn_[1], cn_[2], cn_[3]);
    }
}

// ============================================================================
// HMMA logits: out[m, t, n] = h @ Wo^T + bo. M-tile 32, grid 128 (full chip).
// 8 warps, warp tile 32m x 16n. Single-pass fp16, KC=64 double-buffered.
// ============================================================================
#define LT_A     4608           // 32 * 144
#define LS_B     LT_A
#define LSTAGE_BYTES (LT_A + T144)
#define LOGIT_SMEM (2 * LSTAGE_BYTES)

__global__ __launch_bounds__(256, 2) void logits_kernel(
    const __half* __restrict__ h,
    const __half* __restrict__ Wo16,
    const float* __restrict__ bo,
    float* __restrict__ out, int t)
{
    extern __shared__ char smem[];
    const int tid = threadIdx.x;
    const int wid = tid >> 5, lane = tid & 31;
    const int m0 = blockIdx.x * 32;
    const uint32_t sb = smem_u32(smem);

    float acc[2][2][4];
    #pragma unroll
    for (int a = 0; a < 2; a++)
        #pragma unroll
        for (int b = 0; b < 2; b++)
            #pragma unroll
            for (int c = 0; c < 4; c++) acc[a][b][c] = 0.0f;

    auto issue_loads = [&](int kc, int stage) {
        const int k0 = kc * 64;
        const uint32_t s0 = sb + stage * LSTAGE_BYTES;
        {                                             // A: 32 rows x 8 chunks
            const int r = tid >> 3, ck = tid & 7;
            const uint32_t so = (uint32_t)(r * 144 + ck * 16);
            cp_async16(s0 + so, h + (m0 + r) * HD + k0 + ck * 8);
        }
        #pragma unroll
        for (int i = 0; i < 4; i++) {                 // B: 128 rows x 8 chunks
            const int e = tid + i * 256;
            const int r = e >> 3, ck = e & 7;
            const uint32_t so = (uint32_t)(r * 144 + ck * 16);
            cp_async16(s0 + LS_B + so, Wo16 + r * HD + k0 + ck * 8);
        }
        CP_COMMIT();
    };

    const int arow = (lane & 7) + ((lane >> 3) & 1) * 8;
    const int acol = (lane >> 4) * 8;
    const int brow = lane & 7;
    const int bcol = ((lane >> 3) & 1) * 8;

    issue_loads(0, 0);
    for (int kc = 0; kc < 8; kc++) {
        CP_WAIT0();
        __syncthreads();
        if (kc < 7) issue_loads(kc + 1, (kc + 1) & 1);
        const uint32_t s0 = sb + (kc & 1) * LSTAGE_BYTES;
        #pragma unroll
        for (int ks = 0; ks < 4; ks++) {
            uint32_t af[2][4], bf[2][2];
            #pragma unroll
            for (int mi = 0; mi < 2; mi++) {
                const uint32_t ao = (uint32_t)((mi*16 + arow) * 144 + (ks*16 + acol) * 2);
                ldmatrix_x4(af[mi][0], af[mi][1], af[mi][2], af[mi][3], s0 + ao);
            }
            #pragma unroll
            for (int f = 0; f < 2; f++) {
                const uint32_t bo_ = (uint32_t)((wid*16 + f*8 + brow) * 144 + (ks*16 + bcol) * 2);
                ldmatrix_x2(bf[f][0], bf[f][1], s0 + LS_B + bo_);
            }
            #pragma unroll
            for (int mi = 0; mi < 2; mi++)
                #pragma unroll
                for (int f = 0; f < 2; f++) mma16816(acc[mi][f], af[mi], bf[f]);
        }
        __syncthreads();
    }

    const int lr = lane >> 2;
    const int lc = (lane & 3) * 2;
    #pragma unroll
    for (int mi = 0; mi < 2; mi++) {
        #pragma unroll
        for (int rh = 0; rh < 2; rh++) {
            const int m = m0 + mi*16 + lr + rh*8;
            float* orow = out + m * (CD * AD) + t * AD;
            #pragma unroll
            for (int f = 0; f < 2; f++) {
                const int n = wid*16 + f*8 + lc;
                const float2 b2 = *(const float2*)(bo + n);
                float2 v;
                v.x = acc[mi][f][rh*2 + 0] + b2.x;
                v.y = acc[mi][f][rh*2 + 1] + b2.y;
                *(float2*)(orow + n) = v;
            }
        }
    }
}

// ============================================================================
// kernel_launch
// ============================================================================
extern "C" void kernel_launch(void* const* d_in, const int* in_sizes, int n_in,
                              void* d_out, int out_size)
{
    const float* X    = (const float*)d_in[0];
    const int*   tc   = (const int*)  d_in[1];
    const float* Wp   = (const float*)d_in[2];
    const float* bp   = (const float*)d_in[3];
    const float* Wih  = (const float*)d_in[4];
    const float* Whh  = (const float*)d_in[5];
    const float* bih  = (const float*)d_in[6];
    const float* bhh  = (const float*)d_in[7];
    const float* Wo   = (const float*)d_in[8];
    const float* bo   = (const float*)d_in[9];
    float* out = (float*)d_out;

    __half *h0b, *h1b, *wp16, *wo16;
    float *cS, *xb;
    cudaGetSymbolAddress((void**)&h0b,  g_h0);
    cudaGetSymbolAddress((void**)&h1b,  g_h1);
    cudaGetSymbolAddress((void**)&cS,   g_c);
    cudaGetSymbolAddress((void**)&wp16, g_WP);
    cudaGetSymbolAddress((void**)&wo16, g_Wo16);
    cudaGetSymbolAddress((void**)&xb,   g_xbT);

    cudaFuncSetAttribute(gates_kernel,  cudaFuncAttributeMaxDynamicSharedMemorySize, GEMM_SMEM);
    cudaFuncSetAttribute(logits_kernel, cudaFuncAttributeMaxDynamicSharedMemorySize, LOGIT_SMEM);

    prep_whh <<<(G4H * HD) / 256, 256>>>(Whh, wp16);
    prep_comb<<<1280, 256>>>(Wih, bih, bhh, Wo, xb, wo16);
    h0_kernel<<<dim3(BWN / 64, HD / 64), 256>>>(X, Wp, bp, h0b);

    for (int t = 0; t < CD; t++) {
        const __half* hin  = (t & 1) ? h1b : h0b;
        __half*       hout = (t & 1) ? h0b : h1b;
        gates_kernel<<<dim3(BWN / 128, G4H / 128), 256, GEMM_SMEM>>>(
            t, hin, hout, wp16, xb, tc, cS);
        logits_kernel<<<BWN / 32, 256, LOGIT_SMEM>>>(hout, wo16, bo, out, t);
    }
}

// round 7
// speedup vs baseline: 6.6655x; 1.0404x over previous
#include <cuda_runtime.h>
#include <cuda_fp16.h>
#include <math.h>
#include <stdint.h>

// Problem dims (fixed)
#define BWN 4096   // B*W
#define HD  512    // hidden
#define QD  256    // quantized repr
#define AD  128    // alphabet
#define CD  16     // chars per word
#define G4H 2048   // 4*H

// ============================================================================
// PTX helpers (compute_103-safe: mma.sync / ldmatrix / cp.async only)
// ============================================================================
__device__ __forceinline__ uint32_t smem_u32(const void* p) {
    uint32_t a;
    asm("{ .reg .u64 t; cvta.to.shared.u64 t, %1; cvt.u32.u64 %0, t; }"
        : "=r"(a) : "l"(p));
    return a;
}
__device__ __forceinline__ void ldmatrix_x4(uint32_t& r0, uint32_t& r1,
                                            uint32_t& r2, uint32_t& r3,
                                            uint32_t addr) {
    asm volatile("ldmatrix.sync.aligned.m8n8.x4.shared.b16 {%0,%1,%2,%3}, [%4];"
                 : "=r"(r0), "=r"(r1), "=r"(r2), "=r"(r3) : "r"(addr));
}
__device__ __forceinline__ void mma16816(float (&d)[4], const uint32_t (&a)[4],
                                         const uint32_t (&b)[2]) {
    asm volatile("mma.sync.aligned.m16n8k16.row.col.f32.f16.f16.f32 "
                 "{%0,%1,%2,%3}, {%4,%5,%6,%7}, {%8,%9}, {%0,%1,%2,%3};"
                 : "+f"(d[0]), "+f"(d[1]), "+f"(d[2]), "+f"(d[3])
                 : "r"(a[0]), "r"(a[1]), "r"(a[2]), "r"(a[3]),
                   "r"(b[0]), "r"(b[1]));
}
__device__ __forceinline__ void cp_async16(uint32_t saddr, const void* g) {
    asm volatile("cp.async.cg.shared.global [%0], [%1], 16;"
                 :: "r"(saddr), "l"(g) : "memory");
}
#define CP_COMMIT() asm volatile("cp.async.commit_group;" ::: "memory")
#define CP_WAIT1()  asm volatile("cp.async.wait_group 1;" ::: "memory")
#define CP_WAIT0()  asm volatile("cp.async.wait_group 0;" ::: "memory")

// ============================================================================
// Device state (no allocation allowed)
// ============================================================================
__device__ __half g_h0[BWN * HD];                    // hidden, fp16 (|h| <= 1)
__device__ __half g_h1[BWN * HD];
__device__ float  g_c[BWN * HD];                     // MMA-fragment layout
__device__ __half g_WP[G4H * HD];                    // gate-permuted W_hh fp16
__device__ __half g_Wo16[AD * HD];                   // Wo fp16
__device__ float  g_xbT[AD * G4H];                   // fragment-ordered xbias

__device__ __forceinline__ float sigmoidf_(float x) { return 1.0f / (1.0f + expf(-x)); }

// ============================================================================
// Prep kernels
// Permuted row p: p = bn*128 + wn*32 + g*8 + jl, original n = g*512 + bn*32 + wn*8 + jl.
// ============================================================================
__global__ void prep_whh(const float* __restrict__ Whh, __half* __restrict__ P) {
    int i = blockIdx.x * 256 + threadIdx.x;        // over 2048*512
    int p = i >> 9, k = i & 511;
    int bn = p >> 7, r = p & 127;
    int wn = r >> 5, cw = r & 31, g = cw >> 3, jl = cw & 7;
    int n = g * HD + bn * 32 + wn * 8 + jl;
    P[i] = __float2half_rn(Whh[n * HD + k]);
}
// Combined: blocks [0,1024) -> xbias (128*2048), blocks [1024,1280) -> Wo fp16 (128*512)
__global__ void prep_comb(const float* __restrict__ Wih,
                          const float* __restrict__ bih,
                          const float* __restrict__ bhh,
                          const float* __restrict__ Wo,
                          float* __restrict__ xb,
                          __half* __restrict__ Wo16) {
    if (blockIdx.x < 1024) {
        int q = blockIdx.x * 256 + threadIdx.x;    // xbT[q], q = ((a*16+bn)*4+wn)*32 + jl*4 + g
        int a = q >> 11, bn = (q >> 7) & 15, wn = (q >> 5) & 3, jl = (q >> 2) & 7, g = q & 3;
        int n = g * HD + bn * 32 + wn * 8 + jl;
        xb[q] = Wih[n * AD + a] + bih[n] + bhh[n];
    } else {
        int i = (blockIdx.x - 1024) * 256 + threadIdx.x;   // over 128*512
        Wo16[i] = __float2half_rn(Wo[i]);
    }
}

// ============================================================================
// h0 = X @ Wp^T + bp  (SIMT fp32, M=4096 N=512 K=256) -> fp16
// ============================================================================
__global__ __launch_bounds__(256) void h0_kernel(
    const float* __restrict__ X, const float* __restrict__ Wp,
    const float* __restrict__ bp, __half* __restrict__ hout)
{
    __shared__ float sA[64][17];
    __shared__ float sB[64][17];
    const int tx = threadIdx.x;
    const int cn = tx & 15, rm = tx >> 4;
    const int m0 = blockIdx.x * 64, n0 = blockIdx.y * 64;

    float acc[4][4];
    #pragma unroll
    for (int i = 0; i < 4; i++)
        #pragma unroll
        for (int j = 0; j < 4; j++) acc[i][j] = 0.0f;

    for (int k0 = 0; k0 < QD; k0 += 16) {
        const int r = tx >> 2, kq = (tx & 3) << 2;
        float4 va = *(const float4*)&X [(m0 + r) * QD + k0 + kq];
        sA[r][kq+0] = va.x; sA[r][kq+1] = va.y; sA[r][kq+2] = va.z; sA[r][kq+3] = va.w;
        float4 vb = *(const float4*)&Wp[(n0 + r) * QD + k0 + kq];
        sB[r][kq+0] = vb.x; sB[r][kq+1] = vb.y; sB[r][kq+2] = vb.z; sB[r][kq+3] = vb.w;
        __syncthreads();
        #pragma unroll
        for (int kk = 0; kk < 16; kk++) {
            float a[4], b[4];
            #pragma unroll
            for (int rr = 0; rr < 4; rr++) a[rr] = sA[rm + rr*16][kk];
            #pragma unroll
            for (int jj = 0; jj < 4; jj++) b[jj] = sB[cn + jj*16][kk];
            #pragma unroll
            for (int rr = 0; rr < 4; rr++)
                #pragma unroll
                for (int jj = 0; jj < 4; jj++) acc[rr][jj] += a[rr] * b[jj];
        }
        __syncthreads();
    }
    #pragma unroll
    for (int rr = 0; rr < 4; rr++) {
        const int m = m0 + rm + rr*16;
        #pragma unroll
        for (int jj = 0; jj < 4; jj++) {
            const int n = n0 + cn + jj*16;
            hout[m * HD + n] = __float2half_rn(acc[rr][jj] + bp[n]);
        }
    }
}

// ============================================================================
// Merged step kernel.
// Blocks [0,512): gates(t)   — consume hin=h_{t-1}, produce hout=h_t, update c.
// Blocks [512,640): logits(t-1) — consume hin=h_{t-1}, write out[:, t-1, :].
// Both paths read ONLY hin -> no intra-launch dependency; light logits CTAs
// back-fill the partially-empty second gates wave (512 CTAs vs 296 slots).
//
// Gates: block tile 128m x 128p, 8 warps (2m x 4n), warp tile 64m x 32p,
// single-pass fp16, KC=64, 3-stage cp.async (wait_group 1), stride-144 tiles.
// Logits: m-tile 32, warp tile 32m x 16n, KC=64 double-buffered.
// ============================================================================
#define T144     18432          // 128 * 144
#define S_B      T144
#define STAGE_BYTES (2 * T144)
#define GEMM_SMEM (3 * STAGE_BYTES)

#define LT_A     4608           // 32 * 144
#define LS_B     LT_A
#define LSTAGE_BYTES (LT_A + T144)
#define LOGIT_SMEM (2 * LSTAGE_BYTES)

__global__ __launch_bounds__(256, 2) void step_kernel(
    int t,
    const __half* __restrict__ hin,
    __half*       __restrict__ hout,
    const __half* __restrict__ WP,
    const float* __restrict__ xbT,
    const int* __restrict__ chars,
    float* __restrict__ cst,
    const __half* __restrict__ Wo16,
    const float* __restrict__ bo,
    float* __restrict__ out)
{
    extern __shared__ char smem[];
    __shared__ int sIdx[128];
    const int tid = threadIdx.x;
    const int wid = tid >> 5, lane = tid & 31;
    const uint32_t sb = smem_u32(smem);
    const int bx = blockIdx.x;

    // lane-invariant LDSM geometry
    const int arow = (lane & 7) + ((lane >> 3) & 1) * 8;
    const int acol = (lane >> 4) * 8;
    // B x4 geometry: matrix = lane>>3; rows from (matrix>>1), col half from (matrix&1)
    const int bx4row = ((lane >> 4) << 3) + (lane & 7);
    const int bx4col = ((lane >> 3) & 1) * 8;

    if (bx < 512) {
        // ======================= GATES PATH =======================
        const int bm = bx & 31, bn = bx >> 5;
        const int m0 = bm * 128, p0 = bn * 128;
        const int wm = wid >> 2, wn = wid & 3;

        if (tid < 128) {
            int idx = 0;
            if (t > 0) {
                int c = chars[(m0 + tid) * CD + (t - 1)];
                idx = (c >= 0 && c < AD) ? c : 0;
            }
            sIdx[tid] = idx;
        }

        float acc[4][4][4];
        #pragma unroll
        for (int a = 0; a < 4; a++)
            #pragma unroll
            for (int b = 0; b < 4; b++)
                #pragma unroll
                for (int c = 0; c < 4; c++) acc[a][b][c] = 0.0f;

        auto issue_loads = [&](int kc, int stage) {
            const int k0 = kc * 64;
            const uint32_t s0 = sb + stage * STAGE_BYTES;
            #pragma unroll
            for (int i = 0; i < 4; i++) {
                const int e = tid + i * 256;              // 0..1023
                const int r = e >> 3, ck = e & 7;
                const uint32_t so = (uint32_t)(r * 144 + ck * 16);
                cp_async16(s0 + so,       hin + (m0 + r) * HD + k0 + ck * 8);
                cp_async16(s0 + S_B + so, WP  + (p0 + r) * HD + k0 + ck * 8);
            }
        };

        issue_loads(0, 0); CP_COMMIT();
        issue_loads(1, 1); CP_COMMIT();
        int st = 0, st_w = 2;
        for (int kc = 0; kc < 8; kc++) {
            CP_WAIT1();
            __syncthreads();
            if (kc < 6) issue_loads(kc + 2, st_w);
            CP_COMMIT();
            const uint32_t s0 = sb + st * STAGE_BYTES;
            #pragma unroll
            for (int ks = 0; ks < 4; ks++) {
                uint32_t af[4][4], bf[4][2];
                #pragma unroll
                for (int mi = 0; mi < 4; mi++) {
                    const uint32_t ao = (uint32_t)((wm*64 + mi*16 + arow) * 144 + (ks*16 + acol) * 2);
                    ldmatrix_x4(af[mi][0], af[mi][1], af[mi][2], af[mi][3], s0 + ao);
                }
                #pragma unroll
                for (int fp = 0; fp < 2; fp++) {
                    const uint32_t bo_ = (uint32_t)((wn*32 + fp*16 + bx4row) * 144
                                                    + (ks*16 + bx4col) * 2);
                    ldmatrix_x4(bf[fp*2][0], bf[fp*2][1], bf[fp*2+1][0], bf[fp*2+1][1],
                                s0 + S_B + bo_);
                }
                #pragma unroll
                for (int mi = 0; mi < 4; mi++)
                    #pragma unroll
                    for (int f = 0; f < 4; f++) mma16816(acc[mi][f], af[mi], bf[f]);
            }
            st = (st == 2) ? 0 : st + 1;
            st_w = (st_w == 2) ? 0 : st_w + 1;
        }

        // Epilogue: gates -> LSTM cell update. acc[mi][gate][k], k = rh*2 + cp.
        const int lr = lane >> 2;
        const int lc = (lane & 3) * 2;
        float* cp_base = cst + (((bm * 16 + bn) * 8 + wid) * 512 + lane * 16);

        #pragma unroll
        for (int mi = 0; mi < 4; mi++) {
            float4 cold = (t > 0) ? *(float4*)(cp_base + mi * 4)
                                  : make_float4(0.f, 0.f, 0.f, 0.f);
            float cn_[4];
            #pragma unroll
            for (int rh = 0; rh < 2; rh++) {
                const int mloc = wm*64 + mi*16 + lr + rh*8;
                const int idx = sIdx[mloc];
                const float* xb = xbT + ((idx * 16 + bn) * 4 + wn) * 32 + lc * 4;
                const float4 x0 = *(const float4*)xb;
                const float4 x1 = *(const float4*)(xb + 4);
                __half hv[2];
                #pragma unroll
                for (int cpp = 0; cpp < 2; cpp++) {
                    const float4 xv = cpp ? x1 : x0;
                    const int k = rh * 2 + cpp;
                    const float gi = acc[mi][0][k] + xv.x;
                    const float gf = acc[mi][1][k] + xv.y;
                    const float gg = acc[mi][2][k] + xv.z;
                    const float go = acc[mi][3][k] + xv.w;
                    const float co = (k == 0) ? cold.x : (k == 1) ? cold.y
                                   : (k == 2) ? cold.z : cold.w;
                    const float cn = sigmoidf_(gf) * co + sigmoidf_(gi) * tanhf(gg);
                    cn_[k] = cn;
                    hv[cpp] = __float2half_rn(sigmoidf_(go) * tanhf(cn));
                }
                const int m = m0 + mloc;
                const int j = bn * 32 + wn * 8 + lc;
                const uint32_t ph = (uint32_t)__half_as_ushort(hv[0])
                                  | ((uint32_t)__half_as_ushort(hv[1]) << 16);
                *(uint32_t*)(hout + m * HD + j) = ph;
            }
            *(float4*)(cp_base + mi * 4) = make_float4(cn_[0], cn_[1], cn_[2], cn_[3]);
        }
    } else {
        // ======================= LOGITS PATH (for step t-1) =======================
        if (t == 0) return;
        const int m0 = (bx - 512) * 32;
        const int tprev = t - 1;

        float acc[2][2][4];
        #pragma unroll
        for (int a = 0; a < 2; a++)
            #pragma unroll
            for (int b = 0; b < 2; b++)
                #pragma unroll
                for (int c = 0; c < 4; c++) acc[a][b][c] = 0.0f;

        auto issue_loads = [&](int kc, int stage) {
            const int k0 = kc * 64;
            const uint32_t s0 = sb + stage * LSTAGE_BYTES;
            {                                             // A: 32 rows x 8 chunks
                const int r = tid >> 3, ck = tid & 7;
                const uint32_t so = (uint32_t)(r * 144 + ck * 16);
                cp_async16(s0 + so, hin + (m0 + r) * HD + k0 + ck * 8);
            }
            #pragma unroll
            for (int i = 0; i < 4; i++) {                 // B: 128 rows x 8 chunks
                const int e = tid + i * 256;
                const int r = e >> 3, ck = e & 7;
                const uint32_t so = (uint32_t)(r * 144 + ck * 16);
                cp_async16(s0 + LS_B + so, Wo16 + r * HD + k0 + ck * 8);
            }
            CP_COMMIT();
        };

        issue_loads(0, 0);
        for (int kc = 0; kc < 8; kc++) {
            CP_WAIT0();
            __syncthreads();
            if (kc < 7) issue_loads(kc + 1, (kc + 1) & 1);
            const uint32_t s0 = sb + (kc & 1) * LSTAGE_BYTES;
            #pragma unroll
            for (int ks = 0; ks < 4; ks++) {
                uint32_t af[2][4], bf[2][2];
                #pragma unroll
                for (int mi = 0; mi < 2; mi++) {
                    const uint32_t ao = (uint32_t)((mi*16 + arow) * 144 + (ks*16 + acol) * 2);
                    ldmatrix_x4(af[mi][0], af[mi][1], af[mi][2], af[mi][3], s0 + ao);
                }
                {
                    const uint32_t bo_ = (uint32_t)((wid*16 + bx4row) * 144
                                                    + (ks*16 + bx4col) * 2);
                    ldmatrix_x4(bf[0][0], bf[0][1], bf[1][0], bf[1][1], s0 + LS_B + bo_);
                }
                #pragma unroll
                for (int mi = 0; mi < 2; mi++)
                    #pragma unroll
                    for (int f = 0; f < 2; f++) mma16816(acc[mi][f], af[mi], bf[f]);
            }
            __syncthreads();
        }

        const int lr = lane >> 2;
        const int lc = (lane & 3) * 2;
        #pragma unroll
        for (int mi = 0; mi < 2; mi++) {
            #pragma unroll
            for (int rh = 0; rh < 2; rh++) {
                const int m = m0 + mi*16 + lr + rh*8;
                float* orow = out + m * (CD * AD) + tprev * AD;
                #pragma unroll
                for (int f = 0; f < 2; f++) {
                    const int n = wid*16 + f*8 + lc;
                    const float2 b2 = *(const float2*)(bo + n);
                    float2 v;
                    v.x = acc[mi][f][rh*2 + 0] + b2.x;
                    v.y = acc[mi][f][rh*2 + 1] + b2.y;
                    *(float2*)(orow + n) = v;
                }
            }
        }
    }
}

// ============================================================================
// Standalone logits (final step). Same structure as logits path above.
// ============================================================================
__global__ __launch_bounds__(256, 2) void logits_kernel(
    const __half* __restrict__ h,
    const __half* __restrict__ Wo16,
    const float* __restrict__ bo,
    float* __restrict__ out, int t)
{
    extern __shared__ char smem[];
    const int tid = threadIdx.x;
    const int wid = tid >> 5, lane = tid & 31;
    const int m0 = blockIdx.x * 32;
    const uint32_t sb = smem_u32(smem);

    const int arow = (lane & 7) + ((lane >> 3) & 1) * 8;
    const int acol = (lane >> 4) * 8;
    const int bx4row = ((lane >> 4) << 3) + (lane & 7);
    const int bx4col = ((lane >> 3) & 1) * 8;

    float acc[2][2][4];
    #pragma unroll
    for (int a = 0; a < 2; a++)
        #pragma unroll
        for (int b = 0; b < 2; b++)
            #pragma unroll
            for (int c = 0; c < 4; c++) acc[a][b][c] = 0.0f;

    auto issue_loads = [&](int kc, int stage) {
        const int k0 = kc * 64;
        const uint32_t s0 = sb + stage * LSTAGE_BYTES;
        {
            const int r = tid >> 3, ck = tid & 7;
            const uint32_t so = (uint32_t)(r * 144 + ck * 16);
            cp_async16(s0 + so, h + (m0 + r) * HD + k0 + ck * 8);
        }
        #pragma unroll
        for (int i = 0; i < 4; i++) {
            const int e = tid + i * 256;
            const int r = e >> 3, ck = e & 7;
            const uint32_t so = (uint32_t)(r * 144 + ck * 16);
            cp_async16(s0 + LS_B + so, Wo16 + r * HD + k0 + ck * 8);
        }
        CP_COMMIT();
    };

    issue_loads(0, 0);
    for (int kc = 0; kc < 8; kc++) {
        CP_WAIT0();
        __syncthreads();
        if (kc < 7) issue_loads(kc + 1, (kc + 1) & 1);
        const uint32_t s0 = sb + (kc & 1) * LSTAGE_BYTES;
        #pragma unroll
        for (int ks = 0; ks < 4; ks++) {
            uint32_t af[2][4], bf[2][2];
            #pragma unroll
            for (int mi = 0; mi < 2; mi++) {
                const uint32_t ao = (uint32_t)((mi*16 + arow) * 144 + (ks*16 + acol) * 2);
                ldmatrix_x4(af[mi][0], af[mi][1], af[mi][2], af[mi][3], s0 + ao);
            }
            {
                const uint32_t bo_ = (uint32_t)((wid*16 + bx4row) * 144
                                                + (ks*16 + bx4col) * 2);
                ldmatrix_x4(bf[0][0], bf[0][1], bf[1][0], bf[1][1], s0 + LS_B + bo_);
            }
            #pragma unroll
            for (int mi = 0; mi < 2; mi++)
                #pragma unroll
                for (int f = 0; f < 2; f++) mma16816(acc[mi][f], af[mi], bf[f]);
        }
        __syncthreads();
    }

    const int lr = lane >> 2;
    const int lc = (lane & 3) * 2;
    #pragma unroll
    for (int mi = 0; mi < 2; mi++) {
        #pragma unroll
        for (int rh = 0; rh < 2; rh++) {
            const int m = m0 + mi*16 + lr + rh*8;
            float* orow = out + m * (CD * AD) + t * AD;
            #pragma unroll
            for (int f = 0; f < 2; f++) {
                const int n = wid*16 + f*8 + lc;
                const float2 b2 = *(const float2*)(bo + n);
                float2 v;
                v.x = acc[mi][f][rh*2 + 0] + b2.x;
                v.y = acc[mi][f][rh*2 + 1] + b2.y;
                *(float2*)(orow + n) = v;
            }
        }
    }
}

// ============================================================================
// kernel_launch
// ============================================================================
extern "C" void kernel_launch(void* const* d_in, const int* in_sizes, int n_in,
                              void* d_out, int out_size)
{
    const float* X    = (const float*)d_in[0];
    const int*   tc   = (const int*)  d_in[1];
    const float* Wp   = (const float*)d_in[2];
    const float* bp   = (const float*)d_in[3];
    const float* Wih  = (const float*)d_in[4];
    const float* Whh  = (const float*)d_in[5];
    const float* bih  = (const float*)d_in[6];
    const float* bhh  = (const float*)d_in[7];
    const float* Wo   = (const float*)d_in[8];
    const float* bo   = (const float*)d_in[9];
    float* out = (float*)d_out;

    __half *h0b, *h1b, *wp16, *wo16;
    float *cS, *xb;
    cudaGetSymbolAddress((void**)&h0b,  g_h0);
    cudaGetSymbolAddress((void**)&h1b,  g_h1);
    cudaGetSymbolAddress((void**)&cS,   g_c);
    cudaGetSymbolAddress((void**)&wp16, g_WP);
    cudaGetSymbolAddress((void**)&wo16, g_Wo16);
    cudaGetSymbolAddress((void**)&xb,   g_xbT);

    cudaFuncSetAttribute(step_kernel,   cudaFuncAttributeMaxDynamicSharedMemorySize, GEMM_SMEM);
    cudaFuncSetAttribute(logits_kernel, cudaFuncAttributeMaxDynamicSharedMemorySize, LOGIT_SMEM);

    prep_whh <<<(G4H * HD) / 256, 256>>>(Whh, wp16);
    prep_comb<<<1280, 256>>>(Wih, bih, bhh, Wo, xb, wo16);
    h0_kernel<<<dim3(BWN / 64, HD / 64), 256>>>(X, Wp, bp, h0b);

    for (int t = 0; t < CD; t++) {
        const __half* hin  = (t & 1) ? h1b : h0b;
        __half*       hout = (t & 1) ? h0b : h1b;
        const int nblk = (t == 0) ? 512 : 640;    // gates + (t>0) logits(t-1)
        step_kernel<<<nblk, 256, GEMM_SMEM>>>(
            t, hin, hout, wp16, xb, tc, cS, wo16, bo, out);
    }
    // final logits for t = 15 (h15 lives in the buffer written at t=15)
    logits_kernel<<<BWN / 32, 256, LOGIT_SMEM>>>(
        (CD & 1) ? h1b : h0b, wo16, bo, out, CD - 1);
}

// round 8
// speedup vs baseline: 7.5909x; 1.1388x over previous
#include <cuda_runtime.h>
#include <cuda_fp16.h>
#include <math.h>
#include <stdint.h>

// Problem dims (fixed)
#define BWN 4096   // B*W
#define HD  512    // hidden
#define QD  256    // quantized repr
#define AD  128    // alphabet
#define CD  16     // chars per word
#define G4H 2048   // 4*H

// ============================================================================
// PTX helpers (compute_103-safe: mma.sync / ldmatrix / cp.async only)
// ============================================================================
__device__ __forceinline__ uint32_t smem_u32(const void* p) {
    uint32_t a;
    asm("{ .reg .u64 t; cvta.to.shared.u64 t, %1; cvt.u32.u64 %0, t; }"
        : "=r"(a) : "l"(p));
    return a;
}
__device__ __forceinline__ void ldmatrix_x4(uint32_t& r0, uint32_t& r1,
                                            uint32_t& r2, uint32_t& r3,
                                            uint32_t addr) {
    asm volatile("ldmatrix.sync.aligned.m8n8.x4.shared.b16 {%0,%1,%2,%3}, [%4];"
                 : "=r"(r0), "=r"(r1), "=r"(r2), "=r"(r3) : "r"(addr));
}
__device__ __forceinline__ void mma16816(float (&d)[4], const uint32_t (&a)[4],
                                         const uint32_t (&b)[2]) {
    asm volatile("mma.sync.aligned.m16n8k16.row.col.f32.f16.f16.f32 "
                 "{%0,%1,%2,%3}, {%4,%5,%6,%7}, {%8,%9}, {%0,%1,%2,%3};"
                 : "+f"(d[0]), "+f"(d[1]), "+f"(d[2]), "+f"(d[3])
                 : "r"(a[0]), "r"(a[1]), "r"(a[2]), "r"(a[3]),
                   "r"(b[0]), "r"(b[1]));
}
__device__ __forceinline__ void cp_async16(uint32_t saddr, const void* g) {
    asm volatile("cp.async.cg.shared.global [%0], [%1], 16;"
                 :: "r"(saddr), "l"(g) : "memory");
}
#define CP_COMMIT() asm volatile("cp.async.commit_group;" ::: "memory")
#define CP_WAIT0()  asm volatile("cp.async.wait_group 0;" ::: "memory")

// ============================================================================
// Device state (no allocation allowed)
// ============================================================================
__device__ __half g_h0[BWN * HD];                    // hidden, fp16 (|h| <= 1)
__device__ __half g_h1[BWN * HD];
__device__ float  g_c[BWN * HD];                     // MMA-fragment layout
__device__ __half g_WP[G4H * HD];                    // gate-permuted W_hh fp16
__device__ __half g_Wo16[AD * HD];                   // Wo fp16
__device__ float  g_xbT[AD * G4H];                   // fragment-ordered xbias

__device__ __forceinline__ float sigmoidf_(float x) { return 1.0f / (1.0f + expf(-x)); }

// ============================================================================
// Prep kernels
// Permuted row p: p = bn*128 + wn*32 + g*8 + jl, original n = g*512 + bn*32 + wn*8 + jl.
// ============================================================================
__global__ void prep_whh(const float* __restrict__ Whh, __half* __restrict__ P) {
    int i = blockIdx.x * 256 + threadIdx.x;        // over 2048*512
    int p = i >> 9, k = i & 511;
    int bn = p >> 7, r = p & 127;
    int wn = r >> 5, cw = r & 31, g = cw >> 3, jl = cw & 7;
    int n = g * HD + bn * 32 + wn * 8 + jl;
    P[i] = __float2half_rn(Whh[n * HD + k]);
}
// Combined: blocks [0,1024) -> xbias (128*2048), blocks [1024,1280) -> Wo fp16 (128*512)
__global__ void prep_comb(const float* __restrict__ Wih,
                          const float* __restrict__ bih,
                          const float* __restrict__ bhh,
                          const float* __restrict__ Wo,
                          float* __restrict__ xb,
                          __half* __restrict__ Wo16) {
    if (blockIdx.x < 1024) {
        int q = blockIdx.x * 256 + threadIdx.x;    // xbT[q], q = ((a*16+bn)*4+wn)*32 + jl*4 + g
        int a = q >> 11, bn = (q >> 7) & 15, wn = (q >> 5) & 3, jl = (q >> 2) & 7, g = q & 3;
        int n = g * HD + bn * 32 + wn * 8 + jl;
        xb[q] = Wih[n * AD + a] + bih[n] + bhh[n];
    } else {
        int i = (blockIdx.x - 1024) * 256 + threadIdx.x;   // over 128*512
        Wo16[i] = __float2half_rn(Wo[i]);
    }
}

// ============================================================================
// h0 = X @ Wp^T + bp  (SIMT fp32, M=4096 N=512 K=256) -> fp16
// ============================================================================
__global__ __launch_bounds__(256) void h0_kernel(
    const float* __restrict__ X, const float* __restrict__ Wp,
    const float* __restrict__ bp, __half* __restrict__ hout)
{
    __shared__ float sA[64][17];
    __shared__ float sB[64][17];
    const int tx = threadIdx.x;
    const int cn = tx & 15, rm = tx >> 4;
    const int m0 = blockIdx.x * 64, n0 = blockIdx.y * 64;

    float acc[4][4];
    #pragma unroll
    for (int i = 0; i < 4; i++)
        #pragma unroll
        for (int j = 0; j < 4; j++) acc[i][j] = 0.0f;

    for (int k0 = 0; k0 < QD; k0 += 16) {
        const int r = tx >> 2, kq = (tx & 3) << 2;
        float4 va = *(const float4*)&X [(m0 + r) * QD + k0 + kq];
        sA[r][kq+0] = va.x; sA[r][kq+1] = va.y; sA[r][kq+2] = va.z; sA[r][kq+3] = va.w;
        float4 vb = *(const float4*)&Wp[(n0 + r) * QD + k0 + kq];
        sB[r][kq+0] = vb.x; sB[r][kq+1] = vb.y; sB[r][kq+2] = vb.z; sB[r][kq+3] = vb.w;
        __syncthreads();
        #pragma unroll
        for (int kk = 0; kk < 16; kk++) {
            float a[4], b[4];
            #pragma unroll
            for (int rr = 0; rr < 4; rr++) a[rr] = sA[rm + rr*16][kk];
            #pragma unroll
            for (int jj = 0; jj < 4; jj++) b[jj] = sB[cn + jj*16][kk];
            #pragma unroll
            for (int rr = 0; rr < 4; rr++)
                #pragma unroll
                for (int jj = 0; jj < 4; jj++) acc[rr][jj] += a[rr] * b[jj];
        }
        __syncthreads();
    }
    #pragma unroll
    for (int rr = 0; rr < 4; rr++) {
        const int m = m0 + rm + rr*16;
        #pragma unroll
        for (int jj = 0; jj < 4; jj++) {
            const int n = n0 + cn + jj*16;
            hout[m * HD + n] = __float2half_rn(acc[rr][jj] + bp[n]);
        }
    }
}

// ============================================================================
// Merged step kernel (3 CTAs/SM target).
// Blocks [0,1024): gates(t) — block tile 64m x 128p, 8 warps (2m x 4n),
//   warp tile 32m x 32p, acc = 32 regs. KC=64, 2-stage cp.async.
// Blocks [1024,1152): logits(t-1) — m-tile 32, warp tile 32m x 16n.
// Both read only hin=h_{t-1} -> no intra-launch dependency.
// Stage = A(64x144) 9.2KB + B(128x144) 18.4KB = 27.6KB; 2 stages = 55.3KB;
// 3 CTAs/SM = 166KB smem, 24 warps/SM (6 per SMSP).
// ============================================================================
#define TB144    18432          // 128 * 144 (B tile)
#define TA144    9216           // 64 * 144  (A tile)
#define S_B      TA144
#define STAGE_BYTES (TA144 + TB144)
#define GEMM_SMEM (2 * STAGE_BYTES)

#define LT_A     4608           // 32 * 144
#define LS_B     LT_A
#define LSTAGE_BYTES (LT_A + TB144)

__global__ __launch_bounds__(256, 3) void step_kernel(
    int t,
    const __half* __restrict__ hin,
    __half*       __restrict__ hout,
    const __half* __restrict__ WP,
    const float* __restrict__ xbT,
    const int* __restrict__ chars,
    float* __restrict__ cst,
    const __half* __restrict__ Wo16,
    const float* __restrict__ bo,
    float* __restrict__ out)
{
    extern __shared__ char smem[];
    __shared__ int sIdx[64];
    const int tid = threadIdx.x;
    const int wid = tid >> 5, lane = tid & 31;
    const uint32_t sb = smem_u32(smem);
    const int bx = blockIdx.x;

    // lane-invariant LDSM geometry
    const int arow = (lane & 7) + ((lane >> 3) & 1) * 8;
    const int acol = (lane >> 4) * 8;
    const int bx4row = ((lane >> 4) << 3) + (lane & 7);
    const int bx4col = ((lane >> 3) & 1) * 8;

    if (bx < 1024) {
        // ======================= GATES PATH =======================
        const int bm = bx & 63, bn = bx >> 6;       // 64 x 16
        const int m0 = bm * 64, p0 = bn * 128;
        const int wm = wid >> 2, wn = wid & 3;      // 2m x 4n warps

        if (tid < 64) {
            int idx = 0;
            if (t > 0) {
                int c = chars[(m0 + tid) * CD + (t - 1)];
                idx = (c >= 0 && c < AD) ? c : 0;
            }
            sIdx[tid] = idx;
        }

        float acc[2][4][4];
        #pragma unroll
        for (int a = 0; a < 2; a++)
            #pragma unroll
            for (int b = 0; b < 4; b++)
                #pragma unroll
                for (int c = 0; c < 4; c++) acc[a][b][c] = 0.0f;

        auto issue_loads = [&](int kc, int stage) {
            const int k0 = kc * 64;
            const uint32_t s0 = sb + stage * STAGE_BYTES;
            #pragma unroll
            for (int i = 0; i < 2; i++) {                 // A: 64 rows x 8 chunks
                const int e = tid + i * 256;              // 0..511
                const int r = e >> 3, ck = e & 7;
                cp_async16(s0 + (uint32_t)(r * 144 + ck * 16),
                           hin + (m0 + r) * HD + k0 + ck * 8);
            }
            #pragma unroll
            for (int i = 0; i < 4; i++) {                 // B: 128 rows x 8 chunks
                const int e = tid + i * 256;              // 0..1023
                const int r = e >> 3, ck = e & 7;
                cp_async16(s0 + S_B + (uint32_t)(r * 144 + ck * 16),
                           WP + (p0 + r) * HD + k0 + ck * 8);
            }
            CP_COMMIT();
        };

        issue_loads(0, 0);
        for (int kc = 0; kc < 8; kc++) {
            CP_WAIT0();
            __syncthreads();
            if (kc < 7) issue_loads(kc + 1, (kc + 1) & 1);
            const uint32_t s0 = sb + (kc & 1) * STAGE_BYTES;
            #pragma unroll
            for (int ks = 0; ks < 4; ks++) {
                uint32_t af[2][4], bf[4][2];
                #pragma unroll
                for (int mi = 0; mi < 2; mi++) {
                    const uint32_t ao = (uint32_t)((wm*32 + mi*16 + arow) * 144
                                                   + (ks*16 + acol) * 2);
                    ldmatrix_x4(af[mi][0], af[mi][1], af[mi][2], af[mi][3], s0 + ao);
                }
                #pragma unroll
                for (int fp = 0; fp < 2; fp++) {
                    const uint32_t bo_ = (uint32_t)((wn*32 + fp*16 + bx4row) * 144
                                                    + (ks*16 + bx4col) * 2);
                    ldmatrix_x4(bf[fp*2][0], bf[fp*2][1], bf[fp*2+1][0], bf[fp*2+1][1],
                                s0 + S_B + bo_);
                }
                #pragma unroll
                for (int mi = 0; mi < 2; mi++)
                    #pragma unroll
                    for (int f = 0; f < 4; f++) mma16816(acc[mi][f], af[mi], bf[f]);
            }
            __syncthreads();
        }

        // Epilogue: gates -> LSTM cell update. acc[mi][gate][k], k = rh*2 + cp.
        const int lr = lane >> 2;
        const int lc = (lane & 3) * 2;
        float* cp_base = cst + (((bm * 16 + bn) * 8 + wid) * 256 + lane * 8);

        #pragma unroll
        for (int mi = 0; mi < 2; mi++) {
            float4 cold = (t > 0) ? *(float4*)(cp_base + mi * 4)
                                  : make_float4(0.f, 0.f, 0.f, 0.f);
            float cn_[4];
            #pragma unroll
            for (int rh = 0; rh < 2; rh++) {
                const int mloc = wm*32 + mi*16 + lr + rh*8;
                const int idx = sIdx[mloc];
                const float* xb = xbT + ((idx * 16 + bn) * 4 + wn) * 32 + lc * 4;
                const float4 x0 = *(const float4*)xb;
                const float4 x1 = *(const float4*)(xb + 4);
                __half hv[2];
                #pragma unroll
                for (int cpp = 0; cpp < 2; cpp++) {
                    const float4 xv = cpp ? x1 : x0;
                    const int k = rh * 2 + cpp;
                    const float gi = acc[mi][0][k] + xv.x;
                    const float gf = acc[mi][1][k] + xv.y;
                    const float gg = acc[mi][2][k] + xv.z;
                    const float go = acc[mi][3][k] + xv.w;
                    const float co = (k == 0) ? cold.x : (k == 1) ? cold.y
                                   : (k == 2) ? cold.z : cold.w;
                    const float cn = sigmoidf_(gf) * co + sigmoidf_(gi) * tanhf(gg);
                    cn_[k] = cn;
                    hv[cpp] = __float2half_rn(sigmoidf_(go) * tanhf(cn));
                }
                const int m = m0 + mloc;
                const int j = bn * 32 + wn * 8 + lc;
                const uint32_t ph = (uint32_t)__half_as_ushort(hv[0])
                                  | ((uint32_t)__half_as_ushort(hv[1]) << 16);
                *(uint32_t*)(hout + m * HD + j) = ph;
            }
            *(float4*)(cp_base + mi * 4) = make_float4(cn_[0], cn_[1], cn_[2], cn_[3]);
        }
    } else {
        // ======================= LOGITS PATH (for step t-1) =======================
        if (t == 0) return;
        const int m0 = (bx - 1024) * 32;
        const int tprev = t - 1;

        float acc[2][2][4];
        #pragma unroll
        for (int a = 0; a < 2; a++)
            #pragma unroll
            for (int b = 0; b < 2; b++)
                #pragma unroll
                for (int c = 0; c < 4; c++) acc[a][b][c] = 0.0f;

        auto issue_loads = [&](int kc, int stage) {
            const int k0 = kc * 64;
            const uint32_t s0 = sb + stage * LSTAGE_BYTES;
            {                                             // A: 32 rows x 8 chunks
                const int r = tid >> 3, ck = tid & 7;
                cp_async16(s0 + (uint32_t)(r * 144 + ck * 16),
                           hin + (m0 + r) * HD + k0 + ck * 8);
            }
            #pragma unroll
            for (int i = 0; i < 4; i++) {                 // B: 128 rows x 8 chunks
                const int e = tid + i * 256;
                const int r = e >> 3, ck = e & 7;
                cp_async16(s0 + LS_B + (uint32_t)(r * 144 + ck * 16),
                           Wo16 + r * HD + k0 + ck * 8);
            }
            CP_COMMIT();
        };

        issue_loads(0, 0);
        for (int kc = 0; kc < 8; kc++) {
            CP_WAIT0();
            __syncthreads();
            if (kc < 7) issue_loads(kc + 1, (kc + 1) & 1);
            const uint32_t s0 = sb + (kc & 1) * LSTAGE_BYTES;
            #pragma unroll
            for (int ks = 0; ks < 4; ks++) {
                uint32_t af[2][4], bf[2][2];
                #pragma unroll
                for (int mi = 0; mi < 2; mi++) {
                    const uint32_t ao = (uint32_t)((mi*16 + arow) * 144 + (ks*16 + acol) * 2);
                    ldmatrix_x4(af[mi][0], af[mi][1], af[mi][2], af[mi][3], s0 + ao);
                }
                {
                    const uint32_t bo_ = (uint32_t)((wid*16 + bx4row) * 144
                                                    + (ks*16 + bx4col) * 2);
                    ldmatrix_x4(bf[0][0], bf[0][1], bf[1][0], bf[1][1], s0 + LS_B + bo_);
                }
                #pragma unroll
                for (int mi = 0; mi < 2; mi++)
                    #pragma unroll
                    for (int f = 0; f < 2; f++) mma16816(acc[mi][f], af[mi], bf[f]);
            }
            __syncthreads();
        }

        const int lr = lane >> 2;
        const int lc = (lane & 3) * 2;
        #pragma unroll
        for (int mi = 0; mi < 2; mi++) {
            #pragma unroll
            for (int rh = 0; rh < 2; rh++) {
                const int m = m0 + mi*16 + lr + rh*8;
                float* orow = out + m * (CD * AD) + tprev * AD;
                #pragma unroll
                for (int f = 0; f < 2; f++) {
                    const int n = wid*16 + f*8 + lc;
                    const float2 b2 = *(const float2*)(bo + n);
                    float2 v;
                    v.x = acc[mi][f][rh*2 + 0] + b2.x;
                    v.y = acc[mi][f][rh*2 + 1] + b2.y;
                    *(float2*)(orow + n) = v;
                }
            }
        }
    }
}

// ============================================================================
// Standalone logits (final step).
// ============================================================================
__global__ __launch_bounds__(256, 3) void logits_kernel(
    const __half* __restrict__ h,
    const __half* __restrict__ Wo16,
    const float* __restrict__ bo,
    float* __restrict__ out, int t)
{
    extern __shared__ char smem[];
    const int tid = threadIdx.x;
    const int wid = tid >> 5, lane = tid & 31;
    const int m0 = blockIdx.x * 32;
    const uint32_t sb = smem_u32(smem);

    const int arow = (lane & 7) + ((lane >> 3) & 1) * 8;
    const int acol = (lane >> 4) * 8;
    const int bx4row = ((lane >> 4) << 3) + (lane & 7);
    const int bx4col = ((lane >> 3) & 1) * 8;

    float acc[2][2][4];
    #pragma unroll
    for (int a = 0; a < 2; a++)
        #pragma unroll
        for (int b = 0; b < 2; b++)
            #pragma unroll
            for (int c = 0; c < 4; c++) acc[a][b][c] = 0.0f;

    auto issue_loads = [&](int kc, int stage) {
        const int k0 = kc * 64;
        const uint32_t s0 = sb + stage * LSTAGE_BYTES;
        {
            const int r = tid >> 3, ck = tid & 7;
            cp_async16(s0 + (uint32_t)(r * 144 + ck * 16),
                       h + (m0 + r) * HD + k0 + ck * 8);
        }
        #pragma unroll
        for (int i = 0; i < 4; i++) {
            const int e = tid + i * 256;
            const int r = e >> 3, ck = e & 7;
            cp_async16(s0 + LS_B + (uint32_t)(r * 144 + ck * 16),
                       Wo16 + r * HD + k0 + ck * 8);
        }
        CP_COMMIT();
    };

    issue_loads(0, 0);
    for (int kc = 0; kc < 8; kc++) {
        CP_WAIT0();
        __syncthreads();
        if (kc < 7) issue_loads(kc + 1, (kc + 1) & 1);
        const uint32_t s0 = sb + (kc & 1) * LSTAGE_BYTES;
        #pragma unroll
        for (int ks = 0; ks < 4; ks++) {
            uint32_t af[2][4], bf[2][2];
            #pragma unroll
            for (int mi = 0; mi < 2; mi++) {
                const uint32_t ao = (uint32_t)((mi*16 + arow) * 144 + (ks*16 + acol) * 2);
                ldmatrix_x4(af[mi][0], af[mi][1], af[mi][2], af[mi][3], s0 + ao);
            }
            {
                const uint32_t bo_ = (uint32_t)((wid*16 + bx4row) * 144
                                                + (ks*16 + bx4col) * 2);
                ldmatrix_x4(bf[0][0], bf[0][1], bf[1][0], bf[1][1], s0 + LS_B + bo_);
            }
            #pragma unroll
            for (int mi = 0; mi < 2; mi++)
                #pragma unroll
                for (int f = 0; f < 2; f++) mma16816(acc[mi][f], af[mi], bf[f]);
        }
        __syncthreads();
    }

    const int lr = lane >> 2;
    const int lc = (lane & 3) * 2;
    #pragma unroll
    for (int mi = 0; mi < 2; mi++) {
        #pragma unroll
        for (int rh = 0; rh < 2; rh++) {
            const int m = m0 + mi*16 + lr + rh*8;
            float* orow = out + m * (CD * AD) + t * AD;
            #pragma unroll
            for (int f = 0; f < 2; f++) {
                const int n = wid*16 + f*8 + lc;
                const float2 b2 = *(const float2*)(bo + n);
                float2 v;
                v.x = acc[mi][f][rh*2 + 0] + b2.x;
                v.y = acc[mi][f][rh*2 + 1] + b2.y;
                *(float2*)(orow + n) = v;
            }
        }
    }
}

// ============================================================================
// kernel_launch
// ============================================================================
extern "C" void kernel_launch(void* const* d_in, const int* in_sizes, int n_in,
                              void* d_out, int out_size)
{
    const float* X    = (const float*)d_in[0];
    const int*   tc   = (const int*)  d_in[1];
    const float* Wp   = (const float*)d_in[2];
    const float* bp   = (const float*)d_in[3];
    const float* Wih  = (const float*)d_in[4];
    const float* Whh  = (const float*)d_in[5];
    const float* bih  = (const float*)d_in[6];
    const float* bhh  = (const float*)d_in[7];
    const float* Wo   = (const float*)d_in[8];
    const float* bo   = (const float*)d_in[9];
    float* out = (float*)d_out;

    __half *h0b, *h1b, *wp16, *wo16;
    float *cS, *xb;
    cudaGetSymbolAddress((void**)&h0b,  g_h0);
    cudaGetSymbolAddress((void**)&h1b,  g_h1);
    cudaGetSymbolAddress((void**)&cS,   g_c);
    cudaGetSymbolAddress((void**)&wp16, g_WP);
    cudaGetSymbolAddress((void**)&wo16, g_Wo16);
    cudaGetSymbolAddress((void**)&xb,   g_xbT);

    cudaFuncSetAttribute(step_kernel,   cudaFuncAttributeMaxDynamicSharedMemorySize, GEMM_SMEM);
    cudaFuncSetAttribute(logits_kernel, cudaFuncAttributeMaxDynamicSharedMemorySize, GEMM_SMEM);

    prep_whh <<<(G4H * HD) / 256, 256>>>(Whh, wp16);
    prep_comb<<<1280, 256>>>(Wih, bih, bhh, Wo, xb, wo16);
    h0_kernel<<<dim3(BWN / 64, HD / 64), 256>>>(X, Wp, bp, h0b);

    for (int t = 0; t < CD; t++) {
        const __half* hin  = (t & 1) ? h1b : h0b;
        __half*       hout = (t & 1) ? h0b : h1b;
        const int nblk = (t == 0) ? 1024 : 1152;   // gates + (t>0) logits(t-1)
        step_kernel<<<nblk, 256, GEMM_SMEM>>>(
            t, hin, hout, wp16, xb, tc, cS, wo16, bo, out);
    }
    // final logits for t = 15
    logits_kernel<<<BWN / 32, 256, GEMM_SMEM>>>(
        (CD & 1) ? h1b : h0b, wo16, bo, out, CD - 1);
}

// round 9
// speedup vs baseline: 8.9614x; 1.1805x over previous
#include <cuda_runtime.h>
#include <cuda_fp16.h>
#include <math.h>
#include <stdint.h>

// Problem dims (fixed)
#define BWN 4096   // B*W
#define HD  512    // hidden
#define QD  256    // quantized repr
#define AD  128    // alphabet
#define CD  16     // chars per word
#define G4H 2048   // 4*H

// ============================================================================
// PTX helpers (compute_103-safe: mma.sync / ldmatrix / cp.async only)
// ============================================================================
__device__ __forceinline__ uint32_t smem_u32(const void* p) {
    uint32_t a;
    asm("{ .reg .u64 t; cvta.to.shared.u64 t, %1; cvt.u32.u64 %0, t; }"
        : "=r"(a) : "l"(p));
    return a;
}
__device__ __forceinline__ void ldmatrix_x4(uint32_t& r0, uint32_t& r1,
                                            uint32_t& r2, uint32_t& r3,
                                            uint32_t addr) {
    asm volatile("ldmatrix.sync.aligned.m8n8.x4.shared.b16 {%0,%1,%2,%3}, [%4];"
                 : "=r"(r0), "=r"(r1), "=r"(r2), "=r"(r3) : "r"(addr));
}
__device__ __forceinline__ void mma16816(float (&d)[4], const uint32_t (&a)[4],
                                         const uint32_t (&b)[2]) {
    asm volatile("mma.sync.aligned.m16n8k16.row.col.f32.f16.f16.f32 "
                 "{%0,%1,%2,%3}, {%4,%5,%6,%7}, {%8,%9}, {%0,%1,%2,%3};"
                 : "+f"(d[0]), "+f"(d[1]), "+f"(d[2]), "+f"(d[3])
                 : "r"(a[0]), "r"(a[1]), "r"(a[2]), "r"(a[3]),
                   "r"(b[0]), "r"(b[1]));
}
__device__ __forceinline__ void cp_async16(uint32_t saddr, const void* g) {
    asm volatile("cp.async.cg.shared.global [%0], [%1], 16;"
                 :: "r"(saddr), "l"(g) : "memory");
}
#define CP_COMMIT() asm volatile("cp.async.commit_group;" ::: "memory")
#define CP_WAIT0()  asm volatile("cp.async.wait_group 0;" ::: "memory")

// ============================================================================
// Device state (no allocation allowed)
// ============================================================================
__device__ __half g_h0[BWN * HD];                    // hidden, fp16 (|h| <= 1)
__device__ __half g_h1[BWN * HD];
__device__ float  g_c[BWN * HD];                     // MMA-fragment layout
__device__ __half g_WB[G4H * HD];                    // W_hh in B-fragment order
__device__ __half g_Wo16[AD * HD];                   // Wo fp16
__device__ float  g_xbT[AD * G4H];                   // fragment-ordered xbias

__device__ __forceinline__ float sigmoidf_(float x) {
    return __fdividef(1.0f, 1.0f + __expf(-x));
}
__device__ __forceinline__ float tanhf_(float x) {
    return 1.0f - __fdividef(2.0f, __expf(2.0f * x) + 1.0f);
}

// ============================================================================
// prep_whh_frag: store W_hh so each warp's per-ks B fragments are two
// coalesced LDG.128s. Half index i:
//   block = i>>8; lane = (i>>3)&31; j = i&7
//   fpair = block&1; wn=(block>>1)&3; ks=(block>>3)&3; kc=(block>>5)&7; bn=block>>8
//   fsub = j>>2; reg = (j>>1)&1; h = j&1; f = fpair*2+fsub (= gate g)
//   n = f*512 + bn*32 + wn*8 + (lane>>2)
//   k = kc*64 + ks*16 + (lane&3)*2 + reg*8 + h
// ============================================================================
__global__ void prep_whh(const float* __restrict__ Whh, __half* __restrict__ WB) {
    int i = blockIdx.x * 256 + threadIdx.x;        // over 2048*512
    int lane = (i >> 3) & 31, j = i & 7;
    int block = i >> 8;
    int fpair = block & 1, wn = (block >> 1) & 3, ks = (block >> 3) & 3;
    int kc = (block >> 5) & 7, bn = block >> 8;
    int f = fpair * 2 + (j >> 2);
    int reg = (j >> 1) & 1, h = j & 1;
    int n = f * HD + bn * 32 + wn * 8 + (lane >> 2);
    int k = kc * 64 + ks * 16 + (lane & 3) * 2 + reg * 8 + h;
    WB[i] = __float2half_rn(Whh[n * HD + k]);
}
// Combined: blocks [0,1024) -> xbias (128*2048), blocks [1024,1280) -> Wo fp16 (128*512)
__global__ void prep_comb(const float* __restrict__ Wih,
                          const float* __restrict__ bih,
                          const float* __restrict__ bhh,
                          const float* __restrict__ Wo,
                          float* __restrict__ xb,
                          __half* __restrict__ Wo16) {
    if (blockIdx.x < 1024) {
        int q = blockIdx.x * 256 + threadIdx.x;    // xbT[q], q = ((a*16+bn)*4+wn)*32 + jl*4 + g
        int a = q >> 11, bn = (q >> 7) & 15, wn = (q >> 5) & 3, jl = (q >> 2) & 7, g = q & 3;
        int n = g * HD + bn * 32 + wn * 8 + jl;
        xb[q] = Wih[n * AD + a] + bih[n] + bhh[n];
    } else {
        int i = (blockIdx.x - 1024) * 256 + threadIdx.x;   // over 128*512
        Wo16[i] = __float2half_rn(Wo[i]);
    }
}

// ============================================================================
// h0 = X @ Wp^T + bp  (SIMT fp32, M=4096 N=512 K=256) -> fp16
// ============================================================================
__global__ __launch_bounds__(256) void h0_kernel(
    const float* __restrict__ X, const float* __restrict__ Wp,
    const float* __restrict__ bp, __half* __restrict__ hout)
{
    __shared__ float sA[64][17];
    __shared__ float sB[64][17];
    const int tx = threadIdx.x;
    const int cn = tx & 15, rm = tx >> 4;
    const int m0 = blockIdx.x * 64, n0 = blockIdx.y * 64;

    float acc[4][4];
    #pragma unroll
    for (int i = 0; i < 4; i++)
        #pragma unroll
        for (int j = 0; j < 4; j++) acc[i][j] = 0.0f;

    for (int k0 = 0; k0 < QD; k0 += 16) {
        const int r = tx >> 2, kq = (tx & 3) << 2;
        float4 va = *(const float4*)&X [(m0 + r) * QD + k0 + kq];
        sA[r][kq+0] = va.x; sA[r][kq+1] = va.y; sA[r][kq+2] = va.z; sA[r][kq+3] = va.w;
        float4 vb = *(const float4*)&Wp[(n0 + r) * QD + k0 + kq];
        sB[r][kq+0] = vb.x; sB[r][kq+1] = vb.y; sB[r][kq+2] = vb.z; sB[r][kq+3] = vb.w;
        __syncthreads();
        #pragma unroll
        for (int kk = 0; kk < 16; kk++) {
            float a[4], b[4];
            #pragma unroll
            for (int rr = 0; rr < 4; rr++) a[rr] = sA[rm + rr*16][kk];
            #pragma unroll
            for (int jj = 0; jj < 4; jj++) b[jj] = sB[cn + jj*16][kk];
            #pragma unroll
            for (int rr = 0; rr < 4; rr++)
                #pragma unroll
                for (int jj = 0; jj < 4; jj++) acc[rr][jj] += a[rr] * b[jj];
        }
        __syncthreads();
    }
    #pragma unroll
    for (int rr = 0; rr < 4; rr++) {
        const int m = m0 + rm + rr*16;
        #pragma unroll
        for (int jj = 0; jj < 4; jj++) {
            const int n = n0 + cn + jj*16;
            hout[m * HD + n] = __float2half_rn(acc[rr][jj] + bp[n]);
        }
    }
}

// ============================================================================
// Merged step kernel (3 CTAs/SM).
// Gates blocks [0,1024): tile 64m x 128p, 8 warps (2m x 4n), warp 32m x 32p.
//   A (h) staged in smem (KC=64, 2-stage cp.async, stride-144).
//   B (W_hh) read DIRECTLY from L2 as MMA fragments (2 x LDG.128 per ks) —
//   no B smem staging, no B LDSM: smem traffic cut ~55%.
// Logits blocks [1024,1152): m-tile 32, warp 32m x 16n (smem path for A+B).
// ============================================================================
#define TB144    18432          // 128 * 144
#define TA144    9216           // 64 * 144  (A stage, gates)
#define GSTAGE   TA144

#define LT_A     4608           // 32 * 144
#define LS_B     LT_A
#define LSTAGE_BYTES (LT_A + TB144)
#define STEP_SMEM (2 * LSTAGE_BYTES)   // 46080: covers both paths

__global__ __launch_bounds__(256, 3) void step_kernel(
    int t,
    const __half* __restrict__ hin,
    __half*       __restrict__ hout,
    const __half* __restrict__ WB,
    const float* __restrict__ xbT,
    const int* __restrict__ chars,
    float* __restrict__ cst,
    const __half* __restrict__ Wo16,
    const float* __restrict__ bo,
    float* __restrict__ out)
{
    extern __shared__ char smem[];
    __shared__ int sIdx[64];
    const int tid = threadIdx.x;
    const int wid = tid >> 5, lane = tid & 31;
    const uint32_t sb = smem_u32(smem);
    const int bx = blockIdx.x;

    // lane-invariant LDSM geometry
    const int arow = (lane & 7) + ((lane >> 3) & 1) * 8;
    const int acol = (lane >> 4) * 8;
    const int bx4row = ((lane >> 4) << 3) + (lane & 7);
    const int bx4col = ((lane >> 3) & 1) * 8;

    if (bx < 1024) {
        // ======================= GATES PATH =======================
        const int bm = bx & 63, bn = bx >> 6;       // 64 x 16
        const int m0 = bm * 64;
        const int wm = wid >> 2, wn = wid & 3;      // 2m x 4n warps

        if (tid < 64) {
            int idx = 0;
            if (t > 0) {
                int c = chars[(m0 + tid) * CD + (t - 1)];
                idx = (c >= 0 && c < AD) ? c : 0;
            }
            sIdx[tid] = idx;
        }

        // B fragment base for this warp: halves offset
        const __half* wbBase = WB + (bn * 256 + wn * 2) * 256 + lane * 8;

        float acc[2][4][4];
        #pragma unroll
        for (int a = 0; a < 2; a++)
            #pragma unroll
            for (int b = 0; b < 4; b++)
                #pragma unroll
                for (int c = 0; c < 4; c++) acc[a][b][c] = 0.0f;

        auto issue_loads = [&](int kc, int stage) {
            const int k0 = kc * 64;
            const uint32_t s0 = sb + stage * GSTAGE;
            #pragma unroll
            for (int i = 0; i < 2; i++) {                 // A: 64 rows x 8 chunks
                const int e = tid + i * 256;              // 0..511
                const int r = e >> 3, ck = e & 7;
                cp_async16(s0 + (uint32_t)(r * 144 + ck * 16),
                           hin + (m0 + r) * HD + k0 + ck * 8);
            }
            CP_COMMIT();
        };

        issue_loads(0, 0);
        for (int kc = 0; kc < 8; kc++) {
            CP_WAIT0();
            __syncthreads();
            if (kc < 7) issue_loads(kc + 1, (kc + 1) & 1);
            const uint32_t s0 = sb + (kc & 1) * GSTAGE;
            const __half* wbk = wbBase + kc * 8192;       // 32 blocks * 256 halves
            #pragma unroll
            for (int ks = 0; ks < 4; ks++) {
                // B fragments straight from gmem (coalesced 512B per warp)
                const uint4 bq0 = *(const uint4*)(wbk + ks * 2048);
                const uint4 bq1 = *(const uint4*)(wbk + ks * 2048 + 256);
                uint32_t af[2][4];
                #pragma unroll
                for (int mi = 0; mi < 2; mi++) {
                    const uint32_t ao = (uint32_t)((wm*32 + mi*16 + arow) * 144
                                                   + (ks*16 + acol) * 2);
                    ldmatrix_x4(af[mi][0], af[mi][1], af[mi][2], af[mi][3], s0 + ao);
                }
                uint32_t bf[4][2];
                bf[0][0] = bq0.x; bf[0][1] = bq0.y;
                bf[1][0] = bq0.z; bf[1][1] = bq0.w;
                bf[2][0] = bq1.x; bf[2][1] = bq1.y;
                bf[3][0] = bq1.z; bf[3][1] = bq1.w;
                #pragma unroll
                for (int mi = 0; mi < 2; mi++)
                    #pragma unroll
                    for (int f = 0; f < 4; f++) mma16816(acc[mi][f], af[mi], bf[f]);
            }
            __syncthreads();
        }

        // Epilogue: gates -> LSTM cell update. acc[mi][gate][k], k = rh*2 + cp.
        const int lr = lane >> 2;
        const int lc = (lane & 3) * 2;
        float* cp_base = cst + (((bm * 16 + bn) * 8 + wid) * 256 + lane * 8);

        #pragma unroll
        for (int mi = 0; mi < 2; mi++) {
            float4 cold = (t > 0) ? *(float4*)(cp_base + mi * 4)
                                  : make_float4(0.f, 0.f, 0.f, 0.f);
            float cn_[4];
            #pragma unroll
            for (int rh = 0; rh < 2; rh++) {
                const int mloc = wm*32 + mi*16 + lr + rh*8;
                const int idx = sIdx[mloc];
                const float* xb = xbT + ((idx * 16 + bn) * 4 + wn) * 32 + lc * 4;
                const float4 x0 = *(const float4*)xb;
                const float4 x1 = *(const float4*)(xb + 4);
                __half hv[2];
                #pragma unroll
                for (int cpp = 0; cpp < 2; cpp++) {
                    const float4 xv = cpp ? x1 : x0;
                    const int k = rh * 2 + cpp;
                    const float gi = acc[mi][0][k] + xv.x;
                    const float gf = acc[mi][1][k] + xv.y;
                    const float gg = acc[mi][2][k] + xv.z;
                    const float go = acc[mi][3][k] + xv.w;
                    const float co = (k == 0) ? cold.x : (k == 1) ? cold.y
                                   : (k == 2) ? cold.z : cold.w;
                    const float cn = sigmoidf_(gf) * co + sigmoidf_(gi) * tanhf_(gg);
                    cn_[k] = cn;
                    hv[cpp] = __float2half_rn(sigmoidf_(go) * tanhf_(cn));
                }
                const int m = m0 + mloc;
                const int j = bn * 32 + wn * 8 + lc;
                const uint32_t ph = (uint32_t)__half_as_ushort(hv[0])
                                  | ((uint32_t)__half_as_ushort(hv[1]) << 16);
                *(uint32_t*)(hout + m * HD + j) = ph;
            }
            *(float4*)(cp_base + mi * 4) = make_float4(cn_[0], cn_[1], cn_[2], cn_[3]);
        }
    } else {
        // ======================= LOGITS PATH (for step t-1) =======================
        if (t == 0) return;
        const int m0 = (bx - 1024) * 32;
        const int tprev = t - 1;

        float acc[2][2][4];
        #pragma unroll
        for (int a = 0; a < 2; a++)
            #pragma unroll
            for (int b = 0; b < 2; b++)
                #pragma unroll
                for (int c = 0; c < 4; c++) acc[a][b][c] = 0.0f;

        auto issue_loads = [&](int kc, int stage) {
            const int k0 = kc * 64;
            const uint32_t s0 = sb + stage * LSTAGE_BYTES;
            {                                             // A: 32 rows x 8 chunks
                const int r = tid >> 3, ck = tid & 7;
                cp_async16(s0 + (uint32_t)(r * 144 + ck * 16),
                           hin + (m0 + r) * HD + k0 + ck * 8);
            }
            #pragma unroll
            for (int i = 0; i < 4; i++) {                 // B: 128 rows x 8 chunks
                const int e = tid + i * 256;
                const int r = e >> 3, ck = e & 7;
                cp_async16(s0 + LS_B + (uint32_t)(r * 144 + ck * 16),
                           Wo16 + r * HD + k0 + ck * 8);
            }
            CP_COMMIT();
        };

        issue_loads(0, 0);
        for (int kc = 0; kc < 8; kc++) {
            CP_WAIT0();
            __syncthreads();
            if (kc < 7) issue_loads(kc + 1, (kc + 1) & 1);
            const uint32_t s0 = sb + (kc & 1) * LSTAGE_BYTES;
            #pragma unroll
            for (int ks = 0; ks < 4; ks++) {
                uint32_t af[2][4], bf[2][2];
                #pragma unroll
                for (int mi = 0; mi < 2; mi++) {
                    const uint32_t ao = (uint32_t)((mi*16 + arow) * 144 + (ks*16 + acol) * 2);
                    ldmatrix_x4(af[mi][0], af[mi][1], af[mi][2], af[mi][3], s0 + ao);
                }
                {
                    const uint32_t bo_ = (uint32_t)((wid*16 + bx4row) * 144
                                                    + (ks*16 + bx4col) * 2);
                    ldmatrix_x4(bf[0][0], bf[0][1], bf[1][0], bf[1][1], s0 + LS_B + bo_);
                }
                #pragma unroll
                for (int mi = 0; mi < 2; mi++)
                    #pragma unroll
                    for (int f = 0; f < 2; f++) mma16816(acc[mi][f], af[mi], bf[f]);
            }
            __syncthreads();
        }

        const int lr = lane >> 2;
        const int lc = (lane & 3) * 2;
        #pragma unroll
        for (int mi = 0; mi < 2; mi++) {
            #pragma unroll
            for (int rh = 0; rh < 2; rh++) {
                const int m = m0 + mi*16 + lr + rh*8;
                float* orow = out + m * (CD * AD) + tprev * AD;
                #pragma unroll
                for (int f = 0; f < 2; f++) {
                    const int n = wid*16 + f*8 + lc;
                    const float2 b2 = *(const float2*)(bo + n);
                    float2 v;
                    v.x = acc[mi][f][rh*2 + 0] + b2.x;
                    v.y = acc[mi][f][rh*2 + 1] + b2.y;
                    *(float2*)(orow + n) = v;
                }
            }
        }
    }
}

// ============================================================================
// Standalone logits (final step).
// ============================================================================
__global__ __launch_bounds__(256, 3) void logits_kernel(
    const __half* __restrict__ h,
    const __half* __restrict__ Wo16,
    const float* __restrict__ bo,
    float* __restrict__ out, int t)
{
    extern __shared__ char smem[];
    const int tid = threadIdx.x;
    const int wid = tid >> 5, lane = tid & 31;
    const int m0 = blockIdx.x * 32;
    const uint32_t sb = smem_u32(smem);

    const int arow = (lane & 7) + ((lane >> 3) & 1) * 8;
    const int acol = (lane >> 4) * 8;
    const int bx4row = ((lane >> 4) << 3) + (lane & 7);
    const int bx4col = ((lane >> 3) & 1) * 8;

    float acc[2][2][4];
    #pragma unroll
    for (int a = 0; a < 2; a++)
        #pragma unroll
        for (int b = 0; b < 2; b++)
            #pragma unroll
            for (int c = 0; c < 4; c++) acc[a][b][c] = 0.0f;

    auto issue_loads = [&](int kc, int stage) {
        const int k0 = kc * 64;
        const uint32_t s0 = sb + stage * LSTAGE_BYTES;
        {
            const int r = tid >> 3, ck = tid & 7;
            cp_async16(s0 + (uint32_t)(r * 144 + ck * 16),
                       h + (m0 + r) * HD + k0 + ck * 8);
        }
        #pragma unroll
        for (int i = 0; i < 4; i++) {
            const int e = tid + i * 256;
            const int r = e >> 3, ck = e & 7;
            cp_async16(s0 + LS_B + (uint32_t)(r * 144 + ck * 16),
                       Wo16 + r * HD + k0 + ck * 8);
        }
        CP_COMMIT();
    };

    issue_loads(0, 0);
    for (int kc = 0; kc < 8; kc++) {
        CP_WAIT0();
        __syncthreads();
        if (kc < 7) issue_loads(kc + 1, (kc + 1) & 1);
        const uint32_t s0 = sb + (kc & 1) * LSTAGE_BYTES;
        #pragma unroll
        for (int ks = 0; ks < 4; ks++) {
            uint32_t af[2][4], bf[2][2];
            #pragma unroll
            for (int mi = 0; mi < 2; mi++) {
                const uint32_t ao = (uint32_t)((mi*16 + arow) * 144 + (ks*16 + acol) * 2);
                ldmatrix_x4(af[mi][0], af[mi][1], af[mi][2], af[mi][3], s0 + ao);
            }
            {
                const uint32_t bo_ = (uint32_t)((wid*16 + bx4row) * 144
                                                + (ks*16 + bx4col) * 2);
                ldmatrix_x4(bf[0][0], bf[0][1], bf[1][0], bf[1][1], s0 + LS_B + bo_);
            }
            #pragma unroll
            for (int mi = 0; mi < 2; mi++)
                #pragma unroll
                for (int f = 0; f < 2; f++) mma16816(acc[mi][f], af[mi], bf[f]);
        }
        __syncthreads();
    }

    const int lr = lane >> 2;
    const int lc = (lane & 3) * 2;
    #pragma unroll
    for (int mi = 0; mi < 2; mi++) {
        #pragma unroll
        for (int rh = 0; rh < 2; rh++) {
            const int m = m0 + mi*16 + lr + rh*8;
            float* orow = out + m * (CD * AD) + t * AD;
            #pragma unroll
            for (int f = 0; f < 2; f++) {
                const int n = wid*16 + f*8 + lc;
                const float2 b2 = *(const float2*)(bo + n);
                float2 v;
                v.x = acc[mi][f][rh*2 + 0] + b2.x;
                v.y = acc[mi][f][rh*2 + 1] + b2.y;
                *(float2*)(orow + n) = v;
            }
        }
    }
}

// ============================================================================
// kernel_launch
// ============================================================================
extern "C" void kernel_launch(void* const* d_in, const int* in_sizes, int n_in,
                              void* d_out, int out_size)
{
    const float* X    = (const float*)d_in[0];
    const int*   tc   = (const int*)  d_in[1];
    const float* Wp   = (const float*)d_in[2];
    const float* bp   = (const float*)d_in[3];
    const float* Wih  = (const float*)d_in[4];
    const float* Whh  = (const float*)d_in[5];
    const float* bih  = (const float*)d_in[6];
    const float* bhh  = (const float*)d_in[7];
    const float* Wo   = (const float*)d_in[8];
    const float* bo   = (const float*)d_in[9];
    float* out = (float*)d_out;

    __half *h0b, *h1b, *wb, *wo16;
    float *cS, *xb;
    cudaGetSymbolAddress((void**)&h0b,  g_h0);
    cudaGetSymbolAddress((void**)&h1b,  g_h1);
    cudaGetSymbolAddress((void**)&cS,   g_c);
    cudaGetSymbolAddress((void**)&wb,   g_WB);
    cudaGetSymbolAddress((void**)&wo16, g_Wo16);
    cudaGetSymbolAddress((void**)&xb,   g_xbT);

    cudaFuncSetAttribute(step_kernel,   cudaFuncAttributeMaxDynamicSharedMemorySize, STEP_SMEM);
    cudaFuncSetAttribute(logits_kernel, cudaFuncAttributeMaxDynamicSharedMemorySize, STEP_SMEM);

    prep_whh <<<(G4H * HD) / 256, 256>>>(Whh, wb);
    prep_comb<<<1280, 256>>>(Wih, bih, bhh, Wo, xb, wo16);
    h0_kernel<<<dim3(BWN / 64, HD / 64), 256>>>(X, Wp, bp, h0b);

    for (int t = 0; t < CD; t++) {
        const __half* hin  = (t & 1) ? h1b : h0b;
        __half*       hout = (t & 1) ? h0b : h1b;
        const int nblk = (t == 0) ? 1024 : 1152;   // gates + (t>0) logits(t-1)
        step_kernel<<<nblk, 256, STEP_SMEM>>>(
            t, hin, hout, wb, xb, tc, cS, wo16, bo, out);
    }
    // final logits for t = 15
    logits_kernel<<<BWN / 32, 256, STEP_SMEM>>>(
        (CD & 1) ? h1b : h0b, wo16, bo, out, CD - 1);
}

// round 10
// speedup vs baseline: 10.5621x; 1.1786x over previous
#include <cuda_runtime.h>
#include <cuda_fp16.h>
#include <math.h>
#include <stdint.h>

// Problem dims (fixed)
#define BWN 4096   // B*W
#define HD  512    // hidden
#define QD  256    // quantized repr
#define AD  128    // alphabet
#define CD  16     // chars per word
#define G4H 2048   // 4*H

// ============================================================================
// PTX helpers
// ============================================================================
__device__ __forceinline__ void mma16816(float (&d)[4], const uint32_t (&a)[4],
                                         const uint32_t (&b)[2]) {
    asm volatile("mma.sync.aligned.m16n8k16.row.col.f32.f16.f16.f32 "
                 "{%0,%1,%2,%3}, {%4,%5,%6,%7}, {%8,%9}, {%0,%1,%2,%3};"
                 : "+f"(d[0]), "+f"(d[1]), "+f"(d[2]), "+f"(d[3])
                 : "r"(a[0]), "r"(a[1]), "r"(a[2]), "r"(a[3]),
                   "r"(b[0]), "r"(b[1]));
}

// ============================================================================
// Device state (no allocation allowed)
// h buffers hold A-FRAGMENT layout: tile (mt=m>>4, kt=k>>4);
//   halves index = ((mt*32 + kt)*32 + lane)*8 + reg*2 + half
//   reg = rowhalf + 2*colhalf; lane = (m&7)*4 + ((k&7)>>1); half = k&1
// ============================================================================
__device__ __half g_h0[BWN * HD];
__device__ __half g_h1[BWN * HD];
__device__ float  g_c[BWN * HD];                     // MMA-fragment layout
__device__ __half g_WB[G4H * HD];                    // W_hh in B-fragment order
__device__ __half g_WoB[AD * HD];                    // Wo in B-fragment order
__device__ float  g_xbT[AD * G4H];                   // fragment-ordered xbias

__device__ __forceinline__ float sigmoidf_(float x) {
    return __fdividef(1.0f, 1.0f + __expf(-x));
}
__device__ __forceinline__ float tanhf_(float x) {
    return 1.0f - __fdividef(2.0f, __expf(2.0f * x) + 1.0f);
}

// ============================================================================
// prep_whh: W_hh into warp-coalesced B fragments (same layout as R9 — passed).
//   halves i: j=i&7; lane=(i>>3)&31; block=i>>8;
//   fpair=block&1; wn=(block>>1)&3; ks=(block>>3)&3; kc=(block>>5)&7; bn=block>>8
//   f = fpair*2 + (j>>2); reg=(j>>1)&1; h=j&1
//   n = f*512 + bn*32 + wn*8 + (lane>>2); k = kc*64+ks*16+(lane&3)*2+reg*8+h
// ============================================================================
__global__ void prep_whh(const float* __restrict__ Whh, __half* __restrict__ WB) {
    int i = blockIdx.x * 256 + threadIdx.x;        // over 2048*512
    int lane = (i >> 3) & 31, j = i & 7;
    int block = i >> 8;
    int fpair = block & 1, wn = (block >> 1) & 3, ks = (block >> 3) & 3;
    int kc = (block >> 5) & 7, bn = block >> 8;
    int f = fpair * 2 + (j >> 2);
    int reg = (j >> 1) & 1, h = j & 1;
    int n = f * HD + bn * 32 + wn * 8 + (lane >> 2);
    int k = kc * 64 + ks * 16 + (lane & 3) * 2 + reg * 8 + h;
    WB[i] = __float2half_rn(Whh[n * HD + k]);
}
// Combined: blocks [0,1024) -> xbias; blocks [1024,1280) -> Wo B-fragments
//   WoB halves i: j=i&7; lane=(i>>3)&31; wid=(i>>8)&7; kt=i>>11
//   n = wid*16 + (j>>2)*8 + (lane>>2); k = kt*16 + (lane&3)*2 + ((j>>1)&1)*8 + (j&1)
__global__ void prep_comb(const float* __restrict__ Wih,
                          const float* __restrict__ bih,
                          const float* __restrict__ bhh,
                          const float* __restrict__ Wo,
                          float* __restrict__ xb,
                          __half* __restrict__ WoB) {
    if (blockIdx.x < 1024) {
        int q = blockIdx.x * 256 + threadIdx.x;    // xbT[q], q = ((a*16+bn)*4+wn)*32 + jl*4 + g
        int a = q >> 11, bn = (q >> 7) & 15, wn = (q >> 5) & 3, jl = (q >> 2) & 7, g = q & 3;
        int n = g * HD + bn * 32 + wn * 8 + jl;
        xb[q] = Wih[n * AD + a] + bih[n] + bhh[n];
    } else {
        int i = (blockIdx.x - 1024) * 256 + threadIdx.x;   // over 128*512
        int j = i & 7, lane = (i >> 3) & 31, wid = (i >> 8) & 7, kt = i >> 11;
        int n = wid * 16 + (j >> 2) * 8 + (lane >> 2);
        int k = kt * 16 + (lane & 3) * 2 + ((j >> 1) & 1) * 8 + (j & 1);
        WoB[i] = __float2half_rn(Wo[n * HD + k]);
    }
}

// ============================================================================
// h0 = X @ Wp^T + bp  (SIMT fp32) -> writes h in A-FRAGMENT layout
// ============================================================================
__global__ __launch_bounds__(256) void h0_kernel(
    const float* __restrict__ X, const float* __restrict__ Wp,
    const float* __restrict__ bp, __half* __restrict__ hout)
{
    __shared__ float sA[64][17];
    __shared__ float sB[64][17];
    const int tx = threadIdx.x;
    const int cn = tx & 15, rm = tx >> 4;
    const int m0 = blockIdx.x * 64, n0 = blockIdx.y * 64;

    float acc[4][4];
    #pragma unroll
    for (int i = 0; i < 4; i++)
        #pragma unroll
        for (int j = 0; j < 4; j++) acc[i][j] = 0.0f;

    for (int k0 = 0; k0 < QD; k0 += 16) {
        const int r = tx >> 2, kq = (tx & 3) << 2;
        float4 va = *(const float4*)&X [(m0 + r) * QD + k0 + kq];
        sA[r][kq+0] = va.x; sA[r][kq+1] = va.y; sA[r][kq+2] = va.z; sA[r][kq+3] = va.w;
        float4 vb = *(const float4*)&Wp[(n0 + r) * QD + k0 + kq];
        sB[r][kq+0] = vb.x; sB[r][kq+1] = vb.y; sB[r][kq+2] = vb.z; sB[r][kq+3] = vb.w;
        __syncthreads();
        #pragma unroll
        for (int kk = 0; kk < 16; kk++) {
            float a[4], b[4];
            #pragma unroll
            for (int rr = 0; rr < 4; rr++) a[rr] = sA[rm + rr*16][kk];
            #pragma unroll
            for (int jj = 0; jj < 4; jj++) b[jj] = sB[cn + jj*16][kk];
            #pragma unroll
            for (int rr = 0; rr < 4; rr++)
                #pragma unroll
                for (int jj = 0; jj < 4; jj++) acc[rr][jj] += a[rr] * b[jj];
        }
        __syncthreads();
    }
    #pragma unroll
    for (int rr = 0; rr < 4; rr++) {
        const int m = m0 + rm + rr*16;
        #pragma unroll
        for (int jj = 0; jj < 4; jj++) {
            const int n = n0 + cn + jj*16;
            const int mt = m >> 4, ktt = n >> 4;
            const int ln = ((m & 7) << 2) | ((n & 7) >> 1);
            const int rg = ((m >> 3) & 1) + (((n >> 3) & 1) << 1);
            hout[(mt*32 + ktt)*256 + ln*8 + rg*2 + (n & 1)]
                = __float2half_rn(acc[rr][jj] + bp[n]);
        }
    }
}

// ============================================================================
// Merged step kernel — NO smem, NO barriers, pure LDG + HMMA.
// Gates blocks [0,1024): CTA 64m x 128p, 8 warps (2m x 4n), warp 32m x 32p.
//   A: one LDG.128 per (mi, kt) from h fragment layout (L1-dedup across wn).
//   B: two LDG.128 per kt from WB fragment layout (L1-dedup across wm).
// Logits blocks [1024,1152): m-tile 32, warp 32m x 16n, A/B fragment LDG.
// ============================================================================
__global__ __launch_bounds__(256, 3) void step_kernel(
    int t,
    const __half* __restrict__ hin,
    __half*       __restrict__ hout,
    const __half* __restrict__ WB,
    const float* __restrict__ xbT,
    const int* __restrict__ chars,
    float* __restrict__ cst,
    const __half* __restrict__ WoB,
    const float* __restrict__ bo,
    float* __restrict__ out)
{
    const int tid = threadIdx.x;
    const int wid = tid >> 5, lane = tid & 31;
    const int bx = blockIdx.x;

    if (bx < 1024) {
        // ======================= GATES PATH =======================
        const int bm = bx & 63, bn = bx >> 6;       // 64 x 16
        const int m0 = bm * 64;
        const int wm = wid >> 2, wn = wid & 3;      // 2m x 4n warps

        // A fragment base (mi stride = 8192 halves, kt stride = 256)
        const __half* aP = hin + ((bm*4 + wm*2) * 32) * 256 + lane * 8;
        // B fragment base (kt stride = 2048, fpair +256)
        const __half* bP = WB + (bn * 256 + wn * 2) * 256 + lane * 8;

        float acc[2][4][4];
        #pragma unroll
        for (int a = 0; a < 2; a++)
            #pragma unroll
            for (int b = 0; b < 4; b++)
                #pragma unroll
                for (int c = 0; c < 4; c++) acc[a][b][c] = 0.0f;

        #pragma unroll
        for (int kt = 0; kt < 32; kt++) {
            const uint4 aq0 = *(const uint4*)(aP + kt * 256);
            const uint4 aq1 = *(const uint4*)(aP + 8192 + kt * 256);
            const uint4 bq0 = *(const uint4*)(bP + kt * 2048);
            const uint4 bq1 = *(const uint4*)(bP + kt * 2048 + 256);
            uint32_t af0[4] = {aq0.x, aq0.y, aq0.z, aq0.w};
            uint32_t af1[4] = {aq1.x, aq1.y, aq1.z, aq1.w};
            uint32_t bf[4][2];
            bf[0][0] = bq0.x; bf[0][1] = bq0.y;
            bf[1][0] = bq0.z; bf[1][1] = bq0.w;
            bf[2][0] = bq1.x; bf[2][1] = bq1.y;
            bf[3][0] = bq1.z; bf[3][1] = bq1.w;
            #pragma unroll
            for (int f = 0; f < 4; f++) {
                mma16816(acc[0][f], af0, bf[f]);
                mma16816(acc[1][f], af1, bf[f]);
            }
        }

        // Epilogue: gates -> LSTM cell update. acc[mi][gate][k], k = rh*2 + cp.
        const int lr = lane >> 2;
        const int lc = (lane & 3) * 2;
        float* cp_base = cst + (((bm * 16 + bn) * 8 + wid) * 256 + lane * 8);

        #pragma unroll
        for (int mi = 0; mi < 2; mi++) {
            float4 cold = (t > 0) ? *(float4*)(cp_base + mi * 4)
                                  : make_float4(0.f, 0.f, 0.f, 0.f);
            float cn_[4];
            uint32_t ph[2];
            #pragma unroll
            for (int rh = 0; rh < 2; rh++) {
                const int m = m0 + wm*32 + mi*16 + lr + rh*8;
                int idx = 0;
                if (t > 0) {
                    int cc = chars[m * CD + (t - 1)];
                    idx = (cc >= 0 && cc < AD) ? cc : 0;
                }
                const float* xb = xbT + ((idx * 16 + bn) * 4 + wn) * 32 + lc * 4;
                const float4 x0 = *(const float4*)xb;
                const float4 x1 = *(const float4*)(xb + 4);
                __half hv[2];
                #pragma unroll
                for (int cpp = 0; cpp < 2; cpp++) {
                    const float4 xv = cpp ? x1 : x0;
                    const int k = rh * 2 + cpp;
                    const float gi = acc[mi][0][k] + xv.x;
                    const float gf = acc[mi][1][k] + xv.y;
                    const float gg = acc[mi][2][k] + xv.z;
                    const float go = acc[mi][3][k] + xv.w;
                    const float co = (k == 0) ? cold.x : (k == 1) ? cold.y
                                   : (k == 2) ? cold.z : cold.w;
                    const float cn = sigmoidf_(gf) * co + sigmoidf_(gi) * tanhf_(gg);
                    cn_[k] = cn;
                    hv[cpp] = __float2half_rn(sigmoidf_(go) * tanhf_(cn));
                }
                ph[rh] = (uint32_t)__half_as_ushort(hv[0])
                       | ((uint32_t)__half_as_ushort(hv[1]) << 16);
            }
            // write h_t in A-fragment layout: one 8B store
            const int mt = bm*4 + wm*2 + mi;
            const int ktj = bn*2 + (wn >> 1);
            uint2 w; w.x = ph[0]; w.y = ph[1];
            *(uint2*)(hout + (mt*32 + ktj)*256 + lane*8 + (wn & 1)*4) = w;
            *(float4*)(cp_base + mi * 4) = make_float4(cn_[0], cn_[1], cn_[2], cn_[3]);
        }
    } else {
        // ======================= LOGITS PATH (for step t-1) =======================
        if (t == 0) return;
        const int m0 = (bx - 1024) * 32;
        const int tprev = t - 1;

        const __half* aP = hin + ((m0 >> 4) * 32) * 256 + lane * 8;
        const __half* bP = WoB + (wid * 32 + lane) * 8;   // kt stride = 2048 halves

        float acc[2][2][4];
        #pragma unroll
        for (int a = 0; a < 2; a++)
            #pragma unroll
            for (int b = 0; b < 2; b++)
                #pragma unroll
                for (int c = 0; c < 4; c++) acc[a][b][c] = 0.0f;

        #pragma unroll
        for (int kt = 0; kt < 32; kt++) {
            const uint4 aq0 = *(const uint4*)(aP + kt * 256);
            const uint4 aq1 = *(const uint4*)(aP + 8192 + kt * 256);
            const uint4 bq  = *(const uint4*)(bP + kt * 2048);
            uint32_t af0[4] = {aq0.x, aq0.y, aq0.z, aq0.w};
            uint32_t af1[4] = {aq1.x, aq1.y, aq1.z, aq1.w};
            uint32_t bf[2][2];
            bf[0][0] = bq.x; bf[0][1] = bq.y;
            bf[1][0] = bq.z; bf[1][1] = bq.w;
            mma16816(acc[0][0], af0, bf[0]);
            mma16816(acc[0][1], af0, bf[1]);
            mma16816(acc[1][0], af1, bf[0]);
            mma16816(acc[1][1], af1, bf[1]);
        }

        const int lr = lane >> 2;
        const int lc = (lane & 3) * 2;
        #pragma unroll
        for (int mi = 0; mi < 2; mi++) {
            #pragma unroll
            for (int rh = 0; rh < 2; rh++) {
                const int m = m0 + mi*16 + lr + rh*8;
                float* orow = out + m * (CD * AD) + tprev * AD;
                #pragma unroll
                for (int f = 0; f < 2; f++) {
                    const int n = wid*16 + f*8 + lc;
                    const float2 b2 = *(const float2*)(bo + n);
                    float2 v;
                    v.x = acc[mi][f][rh*2 + 0] + b2.x;
                    v.y = acc[mi][f][rh*2 + 1] + b2.y;
                    *(float2*)(orow + n) = v;
                }
            }
        }
    }
}

// ============================================================================
// Standalone logits (final step) — same fragment-LDG structure.
// ============================================================================
__global__ __launch_bounds__(256, 3) void logits_kernel(
    const __half* __restrict__ h,
    const __half* __restrict__ WoB,
    const float* __restrict__ bo,
    float* __restrict__ out, int t)
{
    const int tid = threadIdx.x;
    const int wid = tid >> 5, lane = tid & 31;
    const int m0 = blockIdx.x * 32;

    const __half* aP = h + ((m0 >> 4) * 32) * 256 + lane * 8;
    const __half* bP = WoB + (wid * 32 + lane) * 8;

    float acc[2][2][4];
    #pragma unroll
    for (int a = 0; a < 2; a++)
        #pragma unroll
        for (int b = 0; b < 2; b++)
            #pragma unroll
            for (int c = 0; c < 4; c++) acc[a][b][c] = 0.0f;

    #pragma unroll
    for (int kt = 0; kt < 32; kt++) {
        const uint4 aq0 = *(const uint4*)(aP + kt * 256);
        const uint4 aq1 = *(const uint4*)(aP + 8192 + kt * 256);
        const uint4 bq  = *(const uint4*)(bP + kt * 2048);
        uint32_t af0[4] = {aq0.x, aq0.y, aq0.z, aq0.w};
        uint32_t af1[4] = {aq1.x, aq1.y, aq1.z, aq1.w};
        uint32_t bf[2][2];
        bf[0][0] = bq.x; bf[0][1] = bq.y;
        bf[1][0] = bq.z; bf[1][1] = bq.w;
        mma16816(acc[0][0], af0, bf[0]);
        mma16816(acc[0][1], af0, bf[1]);
        mma16816(acc[1][0], af1, bf[0]);
        mma16816(acc[1][1], af1, bf[1]);
    }

    const int lr = lane >> 2;
    const int lc = (lane & 3) * 2;
    #pragma unroll
    for (int mi = 0; mi < 2; mi++) {
        #pragma unroll
        for (int rh = 0; rh < 2; rh++) {
            const int m = m0 + mi*16 + lr + rh*8;
            float* orow = out + m * (CD * AD) + t * AD;
            #pragma unroll
            for (int f = 0; f < 2; f++) {
                const int n = wid*16 + f*8 + lc;
                const float2 b2 = *(const float2*)(bo + n);
                float2 v;
                v.x = acc[mi][f][rh*2 + 0] + b2.x;
                v.y = acc[mi][f][rh*2 + 1] + b2.y;
                *(float2*)(orow + n) = v;
            }
        }
    }
}

// ============================================================================
// kernel_launch
// ============================================================================
extern "C" void kernel_launch(void* const* d_in, const int* in_sizes, int n_in,
                              void* d_out, int out_size)
{
    const float* X    = (const float*)d_in[0];
    const int*   tc   = (const int*)  d_in[1];
    const float* Wp   = (const float*)d_in[2];
    const float* bp   = (const float*)d_in[3];
    const float* Wih  = (const float*)d_in[4];
    const float* Whh  = (const float*)d_in[5];
    const float* bih  = (const float*)d_in[6];
    const float* bhh  = (const float*)d_in[7];
    const float* Wo   = (const float*)d_in[8];
    const float* bo   = (const float*)d_in[9];
    float* out = (float*)d_out;

    __half *h0b, *h1b, *wb, *wob;
    float *cS, *xb;
    cudaGetSymbolAddress((void**)&h0b, g_h0);
    cudaGetSymbolAddress((void**)&h1b, g_h1);
    cudaGetSymbolAddress((void**)&cS,  g_c);
    cudaGetSymbolAddress((void**)&wb,  g_WB);
    cudaGetSymbolAddress((void**)&wob, g_WoB);
    cudaGetSymbolAddress((void**)&xb,  g_xbT);

    prep_whh <<<(G4H * HD) / 256, 256>>>(Whh, wb);
    prep_comb<<<1280, 256>>>(Wih, bih, bhh, Wo, xb, wob);
    h0_kernel<<<dim3(BWN / 64, HD / 64), 256>>>(X, Wp, bp, h0b);

    for (int t = 0; t < CD; t++) {
        const __half* hin  = (t & 1) ? h1b : h0b;
        __half*       hout = (t & 1) ? h0b : h1b;
        const int nblk = (t == 0) ? 1024 : 1152;   // gates + (t>0) logits(t-1)
        step_kernel<<<nblk, 256>>>(
            t, hin, hout, wb, xb, tc, cS, wob, bo, out);
    }
    // final logits for t = 15
    logits_kernel<<<BWN / 32, 256>>>(
        (CD & 1) ? h1b : h0b, wob, bo, out, CD - 1);
}

// round 11
// speedup vs baseline: 10.9675x; 1.0384x over previous
#include <cuda_runtime.h>
#include <cuda_fp16.h>
#include <math.h>
#include <stdint.h>

// Problem dims (fixed)
#define BWN 4096   // B*W
#define HD  512    // hidden
#define QD  256    // quantized repr
#define AD  128    // alphabet
#define CD  16     // chars per word
#define G4H 2048   // 4*H

// ============================================================================
// PTX helpers
// ============================================================================
__device__ __forceinline__ void mma16816(float (&d)[4], const uint32_t (&a)[4],
                                         const uint32_t (&b)[2]) {
    asm volatile("mma.sync.aligned.m16n8k16.row.col.f32.f16.f16.f32 "
                 "{%0,%1,%2,%3}, {%4,%5,%6,%7}, {%8,%9}, {%0,%1,%2,%3};"
                 : "+f"(d[0]), "+f"(d[1]), "+f"(d[2]), "+f"(d[3])
                 : "r"(a[0]), "r"(a[1]), "r"(a[2]), "r"(a[3]),
                   "r"(b[0]), "r"(b[1]));
}

// ============================================================================
// Device state (no allocation allowed)
// h buffers hold A-FRAGMENT layout: tile (mt=m>>4, kt=k>>4);
//   halves index = ((mt*32 + kt)*32 + lane)*8 + reg*2 + half
// ============================================================================
__device__ __half g_h0[BWN * HD];
__device__ __half g_h1[BWN * HD];
__device__ float  g_c[BWN * HD];                     // MMA-fragment layout
__device__ __half g_WB[G4H * HD];                    // W_hh in B-fragment order
__device__ __half g_WoB[AD * HD];                    // Wo in B-fragment order
__device__ float  g_xbT[AD * G4H];                   // fragment-ordered xbias

__device__ __forceinline__ float sigmoidf_(float x) {
    return __fdividef(1.0f, 1.0f + __expf(-x));
}
__device__ __forceinline__ float tanhf_(float x) {
    return 1.0f - __fdividef(2.0f, __expf(2.0f * x) + 1.0f);
}

// ============================================================================
// prep_whh: W_hh into warp-coalesced B fragments (layout validated R9/R10).
// ============================================================================
__global__ void prep_whh(const float* __restrict__ Whh, __half* __restrict__ WB) {
    int i = blockIdx.x * 256 + threadIdx.x;        // over 2048*512
    int lane = (i >> 3) & 31, j = i & 7;
    int block = i >> 8;
    int fpair = block & 1, wn = (block >> 1) & 3, ks = (block >> 3) & 3;
    int kc = (block >> 5) & 7, bn = block >> 8;
    int f = fpair * 2 + (j >> 2);
    int reg = (j >> 1) & 1, h = j & 1;
    int n = f * HD + bn * 32 + wn * 8 + (lane >> 2);
    int k = kc * 64 + ks * 16 + (lane & 3) * 2 + reg * 8 + h;
    WB[i] = __float2half_rn(Whh[n * HD + k]);
}
// Combined: blocks [0,1024) -> xbias; blocks [1024,1280) -> Wo B-fragments
__global__ void prep_comb(const float* __restrict__ Wih,
                          const float* __restrict__ bih,
                          const float* __restrict__ bhh,
                          const float* __restrict__ Wo,
                          float* __restrict__ xb,
                          __half* __restrict__ WoB) {
    if (blockIdx.x < 1024) {
        int q = blockIdx.x * 256 + threadIdx.x;    // xbT[q], q = ((a*16+bn)*4+wn)*32 + jl*4 + g
        int a = q >> 11, bn = (q >> 7) & 15, wn = (q >> 5) & 3, jl = (q >> 2) & 7, g = q & 3;
        int n = g * HD + bn * 32 + wn * 8 + jl;
        xb[q] = Wih[n * AD + a] + bih[n] + bhh[n];
    } else {
        int i = (blockIdx.x - 1024) * 256 + threadIdx.x;   // over 128*512
        int j = i & 7, lane = (i >> 3) & 31, wid = (i >> 8) & 7, kt = i >> 11;
        int n = wid * 16 + (j >> 2) * 8 + (lane >> 2);
        int k = kt * 16 + (lane & 3) * 2 + ((j >> 1) & 1) * 8 + (j & 1);
        WoB[i] = __float2half_rn(Wo[n * HD + k]);
    }
}

// ============================================================================
// h0 = X @ Wp^T + bp  (SIMT fp32) -> writes h in A-FRAGMENT layout
// ============================================================================
__global__ __launch_bounds__(256) void h0_kernel(
    const float* __restrict__ X, const float* __restrict__ Wp,
    const float* __restrict__ bp, __half* __restrict__ hout)
{
    __shared__ float sA[64][17];
    __shared__ float sB[64][17];
    const int tx = threadIdx.x;
    const int cn = tx & 15, rm = tx >> 4;
    const int m0 = blockIdx.x * 64, n0 = blockIdx.y * 64;

    float acc[4][4];
    #pragma unroll
    for (int i = 0; i < 4; i++)
        #pragma unroll
        for (int j = 0; j < 4; j++) acc[i][j] = 0.0f;

    for (int k0 = 0; k0 < QD; k0 += 16) {
        const int r = tx >> 2, kq = (tx & 3) << 2;
        float4 va = *(const float4*)&X [(m0 + r) * QD + k0 + kq];
        sA[r][kq+0] = va.x; sA[r][kq+1] = va.y; sA[r][kq+2] = va.z; sA[r][kq+3] = va.w;
        float4 vb = *(const float4*)&Wp[(n0 + r) * QD + k0 + kq];
        sB[r][kq+0] = vb.x; sB[r][kq+1] = vb.y; sB[r][kq+2] = vb.z; sB[r][kq+3] = vb.w;
        __syncthreads();
        #pragma unroll
        for (int kk = 0; kk < 16; kk++) {
            float a[4], b[4];
            #pragma unroll
            for (int rr = 0; rr < 4; rr++) a[rr] = sA[rm + rr*16][kk];
            #pragma unroll
            for (int jj = 0; jj < 4; jj++) b[jj] = sB[cn + jj*16][kk];
            #pragma unroll
            for (int rr = 0; rr < 4; rr++)
                #pragma unroll
                for (int jj = 0; jj < 4; jj++) acc[rr][jj] += a[rr] * b[jj];
        }
        __syncthreads();
    }
    #pragma unroll
    for (int rr = 0; rr < 4; rr++) {
        const int m = m0 + rm + rr*16;
        #pragma unroll
        for (int jj = 0; jj < 4; jj++) {
            const int n = n0 + cn + jj*16;
            const int mt = m >> 4, ktt = n >> 4;
            const int ln = ((m & 7) << 2) | ((n & 7) >> 1);
            const int rg = ((m >> 3) & 1) + (((n >> 3) & 1) << 1);
            hout[(mt*32 + ktt)*256 + ln*8 + rg*2 + (n & 1)]
                = __float2half_rn(acc[rr][jj] + bp[n]);
        }
    }
}

// ============================================================================
// Merged step kernel — no smem, no barriers; 2 CTAs/SM, 128-reg budget.
// Gates blocks [0,512): CTA 64m x 256p, 8 warps (2m x 4n), warp 32m x 64p
//   (= two independent 128p bn-blocks). Per kt: 6 LDG.128, 16 HMMA.
//   Explicit 1-iteration ping-pong prefetch (load->use ~1 kt-round > L2 hit).
// Logits blocks [512,640): m-tile 32, warp 32m x 16n, fragment LDG.
// ============================================================================
__global__ __launch_bounds__(256, 2) void step_kernel(
    int t,
    const __half* __restrict__ hin,
    __half*       __restrict__ hout,
    const __half* __restrict__ WB,
    const float* __restrict__ xbT,
    const int* __restrict__ chars,
    float* __restrict__ cst,
    const __half* __restrict__ WoB,
    const float* __restrict__ bo,
    float* __restrict__ out)
{
    const int tid = threadIdx.x;
    const int wid = tid >> 5, lane = tid & 31;
    const int bx = blockIdx.x;

    if (bx < 512) {
        // ======================= GATES PATH =======================
        const int bm = bx & 63, bnp = bx >> 6;      // 64 x 8
        const int m0 = bm * 64;
        const int bn0 = bnp * 2, bn1 = bn0 + 1;
        const int wm = wid >> 2, wn = wid & 3;      // 2m x 4n warps

        // A fragment base (mi stride 8192, kt stride 256)
        const __half* aP = hin + ((bm*4 + wm*2) * 32) * 256 + lane * 8;
        // B fragment bases for the two bn blocks (kt stride 2048)
        const __half* bP0 = WB + (bn0 * 256 + wn * 2) * 256 + lane * 8;
        const __half* bP1 = WB + (bn1 * 256 + wn * 2) * 256 + lane * 8;

        float acc[2][2][4][4];   // [mi][blk][f][k]
        #pragma unroll
        for (int a = 0; a < 2; a++)
            #pragma unroll
            for (int b = 0; b < 2; b++)
                #pragma unroll
                for (int c = 0; c < 4; c++)
                    #pragma unroll
                    for (int d = 0; d < 4; d++) acc[a][b][c][d] = 0.0f;

        // ping-pong operand buffers
        uint4 A0[2], A1[2], Ba[2][2], Bb[2][2];

        A0[0]    = *(const uint4*)(aP);
        A1[0]    = *(const uint4*)(aP + 8192);
        Ba[0][0] = *(const uint4*)(bP0);
        Ba[1][0] = *(const uint4*)(bP0 + 256);
        Bb[0][0] = *(const uint4*)(bP1);
        Bb[1][0] = *(const uint4*)(bP1 + 256);

        #pragma unroll
        for (int kt = 0; kt < 32; kt++) {
            const int cur = kt & 1, nxt = cur ^ 1;
            if (kt < 31) {
                const int ko = (kt + 1) * 256;
                const int kb = (kt + 1) * 2048;
                A0[nxt]    = *(const uint4*)(aP + ko);
                A1[nxt]    = *(const uint4*)(aP + 8192 + ko);
                Ba[0][nxt] = *(const uint4*)(bP0 + kb);
                Ba[1][nxt] = *(const uint4*)(bP0 + kb + 256);
                Bb[0][nxt] = *(const uint4*)(bP1 + kb);
                Bb[1][nxt] = *(const uint4*)(bP1 + kb + 256);
            }
            uint32_t af0[4] = {A0[cur].x, A0[cur].y, A0[cur].z, A0[cur].w};
            uint32_t af1[4] = {A1[cur].x, A1[cur].y, A1[cur].z, A1[cur].w};
            uint32_t bf0[4][2], bf1[4][2];
            bf0[0][0] = Ba[0][cur].x; bf0[0][1] = Ba[0][cur].y;
            bf0[1][0] = Ba[0][cur].z; bf0[1][1] = Ba[0][cur].w;
            bf0[2][0] = Ba[1][cur].x; bf0[2][1] = Ba[1][cur].y;
            bf0[3][0] = Ba[1][cur].z; bf0[3][1] = Ba[1][cur].w;
            bf1[0][0] = Bb[0][cur].x; bf1[0][1] = Bb[0][cur].y;
            bf1[1][0] = Bb[0][cur].z; bf1[1][1] = Bb[0][cur].w;
            bf1[2][0] = Bb[1][cur].x; bf1[2][1] = Bb[1][cur].y;
            bf1[3][0] = Bb[1][cur].z; bf1[3][1] = Bb[1][cur].w;
            #pragma unroll
            for (int f = 0; f < 4; f++) {
                mma16816(acc[0][0][f], af0, bf0[f]);
                mma16816(acc[1][0][f], af1, bf0[f]);
                mma16816(acc[0][1][f], af0, bf1[f]);
                mma16816(acc[1][1][f], af1, bf1[f]);
            }
        }

        // Epilogue: per bn block, gates -> LSTM cell update.
        const int lr = lane >> 2;
        const int lc = (lane & 3) * 2;
        int cidx[2][2];   // [mi][rh] char idx
        #pragma unroll
        for (int mi = 0; mi < 2; mi++)
            #pragma unroll
            for (int rh = 0; rh < 2; rh++) {
                const int m = m0 + wm*32 + mi*16 + lr + rh*8;
                int idx = 0;
                if (t > 0) {
                    int cc = chars[m * CD + (t - 1)];
                    idx = (cc >= 0 && cc < AD) ? cc : 0;
                }
                cidx[mi][rh] = idx;
            }

        #pragma unroll
        for (int blk = 0; blk < 2; blk++) {
            const int bn = bn0 + blk;
            float* cp_base = cst + (((bm * 16 + bn) * 8 + wid) * 256 + lane * 8);
            #pragma unroll
            for (int mi = 0; mi < 2; mi++) {
                float4 cold = (t > 0) ? *(float4*)(cp_base + mi * 4)
                                      : make_float4(0.f, 0.f, 0.f, 0.f);
                float cn_[4];
                uint32_t ph[2];
                #pragma unroll
                for (int rh = 0; rh < 2; rh++) {
                    const float* xb = xbT + ((cidx[mi][rh] * 16 + bn) * 4 + wn) * 32 + lc * 4;
                    const float4 x0 = *(const float4*)xb;
                    const float4 x1 = *(const float4*)(xb + 4);
                    __half hv[2];
                    #pragma unroll
                    for (int cpp = 0; cpp < 2; cpp++) {
                        const float4 xv = cpp ? x1 : x0;
                        const int k = rh * 2 + cpp;
                        const float gi = acc[mi][blk][0][k] + xv.x;
                        const float gf = acc[mi][blk][1][k] + xv.y;
                        const float gg = acc[mi][blk][2][k] + xv.z;
                        const float go = acc[mi][blk][3][k] + xv.w;
                        const float co = (k == 0) ? cold.x : (k == 1) ? cold.y
                                       : (k == 2) ? cold.z : cold.w;
                        const float cn = sigmoidf_(gf) * co + sigmoidf_(gi) * tanhf_(gg);
                        cn_[k] = cn;
                        hv[cpp] = __float2half_rn(sigmoidf_(go) * tanhf_(cn));
                    }
                    ph[rh] = (uint32_t)__half_as_ushort(hv[0])
                           | ((uint32_t)__half_as_ushort(hv[1]) << 16);
                }
                const int mt = bm*4 + wm*2 + mi;
                const int ktj = bn*2 + (wn >> 1);
                uint2 w; w.x = ph[0]; w.y = ph[1];
                *(uint2*)(hout + (mt*32 + ktj)*256 + lane*8 + (wn & 1)*4) = w;
                *(float4*)(cp_base + mi * 4) = make_float4(cn_[0], cn_[1], cn_[2], cn_[3]);
            }
        }
    } else {
        // ======================= LOGITS PATH (for step t-1) =======================
        if (t == 0) return;
        const int m0 = (bx - 512) * 32;
        const int tprev = t - 1;

        const __half* aP = hin + ((m0 >> 4) * 32) * 256 + lane * 8;
        const __half* bP = WoB + (wid * 32 + lane) * 8;

        float acc[2][2][4];
        #pragma unroll
        for (int a = 0; a < 2; a++)
            #pragma unroll
            for (int b = 0; b < 2; b++)
                #pragma unroll
                for (int c = 0; c < 4; c++) acc[a][b][c] = 0.0f;

        #pragma unroll
        for (int kt = 0; kt < 32; kt++) {
            const uint4 aq0 = *(const uint4*)(aP + kt * 256);
            const uint4 aq1 = *(const uint4*)(aP + 8192 + kt * 256);
            const uint4 bq  = *(const uint4*)(bP + kt * 2048);
            uint32_t af0[4] = {aq0.x, aq0.y, aq0.z, aq0.w};
            uint32_t af1[4] = {aq1.x, aq1.y, aq1.z, aq1.w};
            uint32_t bf[2][2];
            bf[0][0] = bq.x; bf[0][1] = bq.y;
            bf[1][0] = bq.z; bf[1][1] = bq.w;
            mma16816(acc[0][0], af0, bf[0]);
            mma16816(acc[0][1], af0, bf[1]);
            mma16816(acc[1][0], af1, bf[0]);
            mma16816(acc[1][1], af1, bf[1]);
        }

        const int lr = lane >> 2;
        const int lc = (lane & 3) * 2;
        #pragma unroll
        for (int mi = 0; mi < 2; mi++) {
            #pragma unroll
            for (int rh = 0; rh < 2; rh++) {
                const int m = m0 + mi*16 + lr + rh*8;
                float* orow = out + m * (CD * AD) + tprev * AD;
                #pragma unroll
                for (int f = 0; f < 2; f++) {
                    const int n = wid*16 + f*8 + lc;
                    const float2 b2 = *(const float2*)(bo + n);
                    float2 v;
                    v.x = acc[mi][f][rh*2 + 0] + b2.x;
                    v.y = acc[mi][f][rh*2 + 1] + b2.y;
                    *(float2*)(orow + n) = v;
                }
            }
        }
    }
}

// ============================================================================
// Standalone logits (final step).
// ============================================================================
__global__ __launch_bounds__(256, 2) void logits_kernel(
    const __half* __restrict__ h,
    const __half* __restrict__ WoB,
    const float* __restrict__ bo,
    float* __restrict__ out, int t)
{
    const int tid = threadIdx.x;
    const int wid = tid >> 5, lane = tid & 31;
    const int m0 = blockIdx.x * 32;

    const __half* aP = h + ((m0 >> 4) * 32) * 256 + lane * 8;
    const __half* bP = WoB + (wid * 32 + lane) * 8;

    float acc[2][2][4];
    #pragma unroll
    for (int a = 0; a < 2; a++)
        #pragma unroll
        for (int b = 0; b < 2; b++)
            #pragma unroll
            for (int c = 0; c < 4; c++) acc[a][b][c] = 0.0f;

    #pragma unroll
    for (int kt = 0; kt < 32; kt++) {
        const uint4 aq0 = *(const uint4*)(aP + kt * 256);
        const uint4 aq1 = *(const uint4*)(aP + 8192 + kt * 256);
        const uint4 bq  = *(const uint4*)(bP + kt * 2048);
        uint32_t af0[4] = {aq0.x, aq0.y, aq0.z, aq0.w};
        uint32_t af1[4] = {aq1.x, aq1.y, aq1.z, aq1.w};
        uint32_t bf[2][2];
        bf[0][0] = bq.x; bf[0][1] = bq.y;
        bf[1][0] = bq.z; bf[1][1] = bq.w;
        mma16816(acc[0][0], af0, bf[0]);
        mma16816(acc[0][1], af0, bf[1]);
        mma16816(acc[1][0], af1, bf[0]);
        mma16816(acc[1][1], af1, bf[1]);
    }

    const int lr = lane >> 2;
    const int lc = (lane & 3) * 2;
    #pragma unroll
    for (int mi = 0; mi < 2; mi++) {
        #pragma unroll
        for (int rh = 0; rh < 2; rh++) {
            const int m = m0 + mi*16 + lr + rh*8;
            float* orow = out + m * (CD * AD) + t * AD;
            #pragma unroll
            for (int f = 0; f < 2; f++) {
                const int n = wid*16 + f*8 + lc;
                const float2 b2 = *(const float2*)(bo + n);
                float2 v;
                v.x = acc[mi][f][rh*2 + 0] + b2.x;
                v.y = acc[mi][f][rh*2 + 1] + b2.y;
                *(float2*)(orow + n) = v;
            }
        }
    }
}

// ============================================================================
// kernel_launch
// ============================================================================
extern "C" void kernel_launch(void* const* d_in, const int* in_sizes, int n_in,
                              void* d_out, int out_size)
{
    const float* X    = (const float*)d_in[0];
    const int*   tc   = (const int*)  d_in[1];
    const float* Wp   = (const float*)d_in[2];
    const float* bp   = (const float*)d_in[3];
    const float* Wih  = (const float*)d_in[4];
    const float* Whh  = (const float*)d_in[5];
    const float* bih  = (const float*)d_in[6];
    const float* bhh  = (const float*)d_in[7];
    const float* Wo   = (const float*)d_in[8];
    const float* bo   = (const float*)d_in[9];
    float* out = (float*)d_out;

    __half *h0b, *h1b, *wb, *wob;
    float *cS, *xb;
    cudaGetSymbolAddress((void**)&h0b, g_h0);
    cudaGetSymbolAddress((void**)&h1b, g_h1);
    cudaGetSymbolAddress((void**)&cS,  g_c);
    cudaGetSymbolAddress((void**)&wb,  g_WB);
    cudaGetSymbolAddress((void**)&wob, g_WoB);
    cudaGetSymbolAddress((void**)&xb,  g_xbT);

    prep_whh <<<(G4H * HD) / 256, 256>>>(Whh, wb);
    prep_comb<<<1280, 256>>>(Wih, bih, bhh, Wo, xb, wob);
    h0_kernel<<<dim3(BWN / 64, HD / 64), 256>>>(X, Wp, bp, h0b);

    for (int t = 0; t < CD; t++) {
        const __half* hin  = (t & 1) ? h1b : h0b;
        __half*       hout = (t & 1) ? h0b : h1b;
        const int nblk = (t == 0) ? 512 : 640;     // gates + (t>0) logits(t-1)
        step_kernel<<<nblk, 256>>>(
            t, hin, hout, wb, xb, tc, cS, wob, bo, out);
    }
    // final logits for t = 15
    logits_kernel<<<BWN / 32, 256>>>(
        (CD & 1) ? h1b : h0b, wob, bo, out, CD - 1);
}

// round 12
// speedup vs baseline: 11.1640x; 1.0179x over previous
#include <cuda_runtime.h>
#include <cuda_fp16.h>
#include <math.h>
#include <stdint.h>

// Problem dims (fixed)
#define BWN 4096   // B*W
#define HD  512    // hidden
#define QD  256    // quantized repr
#define AD  128    // alphabet
#define CD  16     // chars per word
#define G4H 2048   // 4*H

// ============================================================================
// PTX helpers
// ============================================================================
__device__ __forceinline__ uint32_t smem_u32(const void* p) {
    uint32_t a;
    asm("{ .reg .u64 t; cvta.to.shared.u64 t, %1; cvt.u32.u64 %0, t; }"
        : "=r"(a) : "l"(p));
    return a;
}
__device__ __forceinline__ void mma16816(float (&d)[4], const uint32_t (&a)[4],
                                         const uint32_t (&b)[2]) {
    asm volatile("mma.sync.aligned.m16n8k16.row.col.f32.f16.f16.f32 "
                 "{%0,%1,%2,%3}, {%4,%5,%6,%7}, {%8,%9}, {%0,%1,%2,%3};"
                 : "+f"(d[0]), "+f"(d[1]), "+f"(d[2]), "+f"(d[3])
                 : "r"(a[0]), "r"(a[1]), "r"(a[2]), "r"(a[3]),
                   "r"(b[0]), "r"(b[1]));
}
__device__ __forceinline__ void cp_async16(uint32_t saddr, const void* g) {
    asm volatile("cp.async.cg.shared.global [%0], [%1], 16;"
                 :: "r"(saddr), "l"(g) : "memory");
}
#define CP_COMMIT() asm volatile("cp.async.commit_group;" ::: "memory")
#define CP_WAIT0()  asm volatile("cp.async.wait_group 0;" ::: "memory")

// ============================================================================
// Device state (no allocation allowed)
// h buffers hold A-FRAGMENT layout: tile (mt=m>>4, kt=k>>4);
//   halves index = ((mt*32 + kt)*32 + lane)*8 + reg*2 + half
// ============================================================================
__device__ __half g_h0[BWN * HD];
__device__ __half g_h1[BWN * HD];
__device__ float  g_c[BWN * HD];                     // MMA-fragment layout
__device__ __half g_WB[G4H * HD];                    // W_hh in B-fragment order
__device__ __half g_WoB[AD * HD];                    // Wo in B-fragment order
__device__ float  g_xbT[AD * G4H];                   // fragment-ordered xbias

__device__ __forceinline__ float sigmoidf_(float x) {
    return __fdividef(1.0f, 1.0f + __expf(-x));
}
__device__ __forceinline__ float tanhf_(float x) {
    return 1.0f - __fdividef(2.0f, __expf(2.0f * x) + 1.0f);
}

// ============================================================================
// prep_whh: W_hh into warp-coalesced B fragments (layout validated R9-R11).
// ============================================================================
__global__ void prep_whh(const float* __restrict__ Whh, __half* __restrict__ WB) {
    int i = blockIdx.x * 256 + threadIdx.x;        // over 2048*512
    int lane = (i >> 3) & 31, j = i & 7;
    int block = i >> 8;
    int fpair = block & 1, wn = (block >> 1) & 3, ks = (block >> 3) & 3;
    int kc = (block >> 5) & 7, bn = block >> 8;
    int f = fpair * 2 + (j >> 2);
    int reg = (j >> 1) & 1, h = j & 1;
    int n = f * HD + bn * 32 + wn * 8 + (lane >> 2);
    int k = kc * 64 + ks * 16 + (lane & 3) * 2 + reg * 8 + h;
    WB[i] = __float2half_rn(Whh[n * HD + k]);
}
// Combined: blocks [0,1024) -> xbias; blocks [1024,1280) -> Wo B-fragments
__global__ void prep_comb(const float* __restrict__ Wih,
                          const float* __restrict__ bih,
                          const float* __restrict__ bhh,
                          const float* __restrict__ Wo,
                          float* __restrict__ xb,
                          __half* __restrict__ WoB) {
    if (blockIdx.x < 1024) {
        int q = blockIdx.x * 256 + threadIdx.x;    // xbT[q], q = ((a*16+bn)*4+wn)*32 + jl*4 + g
        int a = q >> 11, bn = (q >> 7) & 15, wn = (q >> 5) & 3, jl = (q >> 2) & 7, g = q & 3;
        int n = g * HD + bn * 32 + wn * 8 + jl;
        xb[q] = Wih[n * AD + a] + bih[n] + bhh[n];
    } else {
        int i = (blockIdx.x - 1024) * 256 + threadIdx.x;   // over 128*512
        int j = i & 7, lane = (i >> 3) & 31, wid = (i >> 8) & 7, kt = i >> 11;
        int n = wid * 16 + (j >> 2) * 8 + (lane >> 2);
        int k = kt * 16 + (lane & 3) * 2 + ((j >> 1) & 1) * 8 + (j & 1);
        WoB[i] = __float2half_rn(Wo[n * HD + k]);
    }
}

// ============================================================================
// h0 = X @ Wp^T + bp  (SIMT fp32) -> writes h in A-FRAGMENT layout
// ============================================================================
__global__ __launch_bounds__(256) void h0_kernel(
    const float* __restrict__ X, const float* __restrict__ Wp,
    const float* __restrict__ bp, __half* __restrict__ hout)
{
    __shared__ float sA[64][17];
    __shared__ float sB[64][17];
    const int tx = threadIdx.x;
    const int cn = tx & 15, rm = tx >> 4;
    const int m0 = blockIdx.x * 64, n0 = blockIdx.y * 64;

    float acc[4][4];
    #pragma unroll
    for (int i = 0; i < 4; i++)
        #pragma unroll
        for (int j = 0; j < 4; j++) acc[i][j] = 0.0f;

    for (int k0 = 0; k0 < QD; k0 += 16) {
        const int r = tx >> 2, kq = (tx & 3) << 2;
        float4 va = *(const float4*)&X [(m0 + r) * QD + k0 + kq];
        sA[r][kq+0] = va.x; sA[r][kq+1] = va.y; sA[r][kq+2] = va.z; sA[r][kq+3] = va.w;
        float4 vb = *(const float4*)&Wp[(n0 + r) * QD + k0 + kq];
        sB[r][kq+0] = vb.x; sB[r][kq+1] = vb.y; sB[r][kq+2] = vb.z; sB[r][kq+3] = vb.w;
        __syncthreads();
        #pragma unroll
        for (int kk = 0; kk < 16; kk++) {
            float a[4], b[4];
            #pragma unroll
            for (int rr = 0; rr < 4; rr++) a[rr] = sA[rm + rr*16][kk];
            #pragma unroll
            for (int jj = 0; jj < 4; jj++) b[jj] = sB[cn + jj*16][kk];
            #pragma unroll
            for (int rr = 0; rr < 4; rr++)
                #pragma unroll
                for (int jj = 0; jj < 4; jj++) acc[rr][jj] += a[rr] * b[jj];
        }
        __syncthreads();
    }
    #pragma unroll
    for (int rr = 0; rr < 4; rr++) {
        const int m = m0 + rm + rr*16;
        #pragma unroll
        for (int jj = 0; jj < 4; jj++) {
            const int n = n0 + cn + jj*16;
            const int mt = m >> 4, ktt = n >> 4;
            const int ln = ((m & 7) << 2) | ((n & 7) >> 1);
            const int rg = ((m >> 3) & 1) + (((n >> 3) & 1) << 1);
            hout[(mt*32 + ktt)*256 + ln*8 + rg*2 + (n & 1)]
                = __float2half_rn(acc[rr][jj] + bp[n]);
        }
    }
}

// ============================================================================
// Merged step kernel — 2 CTAs/SM.
// Gates blocks [0,512): CTA 64m x 256p, 8 warps (2m x 4n), warp 32m x 64p.
//   A (h_{t-1}, fresh each step -> L2 misses) is staged ONCE per CTA into
//   64KB smem via cp.async burst (one barrier), then read per kt via
//   conflict-free LDS.128 (29-cyc deterministic, covered by 16 MMAs).
//   B (weights, L1/L2-warm) stays direct-LDG with 1-iter ping-pong prefetch.
//   Per kt: 2 LDS.128 + 4 LDG.128 + 16 HMMA.
// Logits blocks [512,640): m-tile 32, warp 32m x 16n, fragment LDG (no smem).
// ============================================================================
#define A_SMEM_BYTES 65536      // 64 rows x 512 k x 2B, fragment layout

__global__ __launch_bounds__(256, 2) void step_kernel(
    int t,
    const __half* __restrict__ hin,
    __half*       __restrict__ hout,
    const __half* __restrict__ WB,
    const float* __restrict__ xbT,
    const int* __restrict__ chars,
    float* __restrict__ cst,
    const __half* __restrict__ WoB,
    const float* __restrict__ bo,
    float* __restrict__ out)
{
    extern __shared__ __half sA[];
    const int tid = threadIdx.x;
    const int wid = tid >> 5, lane = tid & 31;
    const int bx = blockIdx.x;

    if (bx < 512) {
        // ======================= GATES PATH =======================
        const int bm = bx & 63, bnp = bx >> 6;      // 64 x 8
        const int m0 = bm * 64;
        const int bn0 = bnp * 2, bn1 = bn0 + 1;
        const int wm = wid >> 2, wn = wid & 3;      // 2m x 4n warps

        // Stage full A tile (4 mt x 32 kt x 256 halves = 32768 halves) to smem.
        // Gmem fragment layout is contiguous over exactly this range.
        {
            const uint32_t sbase = smem_u32(sA);
            const __half* aG = hin + (bm * 4 * 32) * 256;
            #pragma unroll
            for (int i = 0; i < 16; i++) {
                const int ch = tid + i * 256;          // 0..4095 16B-chunks
                cp_async16(sbase + ch * 16, aG + ch * 8);
            }
            CP_COMMIT();
        }

        // B fragment bases for the two bn blocks (kt stride 2048)
        const __half* bP0 = WB + (bn0 * 256 + wn * 2) * 256 + lane * 8;
        const __half* bP1 = WB + (bn1 * 256 + wn * 2) * 256 + lane * 8;

        // Prefetch B stage 0 while A streams in
        uint4 Ba[2][2], Bb[2][2];
        Ba[0][0] = *(const uint4*)(bP0);
        Ba[1][0] = *(const uint4*)(bP0 + 256);
        Bb[0][0] = *(const uint4*)(bP1);
        Bb[1][0] = *(const uint4*)(bP1 + 256);

        float acc[2][2][4][4];   // [mi][blk][f][k]
        #pragma unroll
        for (int a = 0; a < 2; a++)
            #pragma unroll
            for (int b = 0; b < 2; b++)
                #pragma unroll
                for (int c = 0; c < 4; c++)
                    #pragma unroll
                    for (int d = 0; d < 4; d++) acc[a][b][c][d] = 0.0f;

        CP_WAIT0();
        __syncthreads();

        const __half* aS0 = sA + (wm * 2) * 8192 + lane * 8;       // mi=0
        const __half* aS1 = aS0 + 8192;                            // mi=1

        #pragma unroll
        for (int kt = 0; kt < 32; kt++) {
            const int cur = kt & 1, nxt = cur ^ 1;
            if (kt < 31) {
                const int kb = (kt + 1) * 2048;
                Ba[0][nxt] = *(const uint4*)(bP0 + kb);
                Ba[1][nxt] = *(const uint4*)(bP0 + kb + 256);
                Bb[0][nxt] = *(const uint4*)(bP1 + kb);
                Bb[1][nxt] = *(const uint4*)(bP1 + kb + 256);
            }
            const uint4 aq0 = *(const uint4*)(aS0 + kt * 256);     // LDS.128
            const uint4 aq1 = *(const uint4*)(aS1 + kt * 256);
            uint32_t af0[4] = {aq0.x, aq0.y, aq0.z, aq0.w};
            uint32_t af1[4] = {aq1.x, aq1.y, aq1.z, aq1.w};
            uint32_t bf0[4][2], bf1[4][2];
            bf0[0][0] = Ba[0][cur].x; bf0[0][1] = Ba[0][cur].y;
            bf0[1][0] = Ba[0][cur].z; bf0[1][1] = Ba[0][cur].w;
            bf0[2][0] = Ba[1][cur].x; bf0[2][1] = Ba[1][cur].y;
            bf0[3][0] = Ba[1][cur].z; bf0[3][1] = Ba[1][cur].w;
            bf1[0][0] = Bb[0][cur].x; bf1[0][1] = Bb[0][cur].y;
            bf1[1][0] = Bb[0][cur].z; bf1[1][1] = Bb[0][cur].w;
            bf1[2][0] = Bb[1][cur].x; bf1[2][1] = Bb[1][cur].y;
            bf1[3][0] = Bb[1][cur].z; bf1[3][1] = Bb[1][cur].w;
            #pragma unroll
            for (int f = 0; f < 4; f++) {
                mma16816(acc[0][0][f], af0, bf0[f]);
                mma16816(acc[1][0][f], af1, bf0[f]);
                mma16816(acc[0][1][f], af0, bf1[f]);
                mma16816(acc[1][1][f], af1, bf1[f]);
            }
        }

        // Epilogue: per bn block, gates -> LSTM cell update.
        const int lr = lane >> 2;
        const int lc = (lane & 3) * 2;
        int cidx[2][2];   // [mi][rh] char idx
        #pragma unroll
        for (int mi = 0; mi < 2; mi++)
            #pragma unroll
            for (int rh = 0; rh < 2; rh++) {
                const int m = m0 + wm*32 + mi*16 + lr + rh*8;
                int idx = 0;
                if (t > 0) {
                    int cc = chars[m * CD + (t - 1)];
                    idx = (cc >= 0 && cc < AD) ? cc : 0;
                }
                cidx[mi][rh] = idx;
            }

        #pragma unroll
        for (int blk = 0; blk < 2; blk++) {
            const int bn = bn0 + blk;
            float* cp_base = cst + (((bm * 16 + bn) * 8 + wid) * 256 + lane * 8);
            #pragma unroll
            for (int mi = 0; mi < 2; mi++) {
                float4 cold = (t > 0) ? *(float4*)(cp_base + mi * 4)
                                      : make_float4(0.f, 0.f, 0.f, 0.f);
                float cn_[4];
                uint32_t ph[2];
                #pragma unroll
                for (int rh = 0; rh < 2; rh++) {
                    const float* xb = xbT + ((cidx[mi][rh] * 16 + bn) * 4 + wn) * 32 + lc * 4;
                    const float4 x0 = *(const float4*)xb;
                    const float4 x1 = *(const float4*)(xb + 4);
                    __half hv[2];
                    #pragma unroll
                    for (int cpp = 0; cpp < 2; cpp++) {
                        const float4 xv = cpp ? x1 : x0;
                        const int k = rh * 2 + cpp;
                        const float gi = acc[mi][blk][0][k] + xv.x;
                        const float gf = acc[mi][blk][1][k] + xv.y;
                        const float gg = acc[mi][blk][2][k] + xv.z;
                        const float go = acc[mi][blk][3][k] + xv.w;
                        const float co = (k == 0) ? cold.x : (k == 1) ? cold.y
                                       : (k == 2) ? cold.z : cold.w;
                        const float cn = sigmoidf_(gf) * co + sigmoidf_(gi) * tanhf_(gg);
                        cn_[k] = cn;
                        hv[cpp] = __float2half_rn(sigmoidf_(go) * tanhf_(cn));
                    }
                    ph[rh] = (uint32_t)__half_as_ushort(hv[0])
                           | ((uint32_t)__half_as_ushort(hv[1]) << 16);
                }
                const int mt = bm*4 + wm*2 + mi;
                const int ktj = bn*2 + (wn >> 1);
                uint2 w; w.x = ph[0]; w.y = ph[1];
                *(uint2*)(hout + (mt*32 + ktj)*256 + lane*8 + (wn & 1)*4) = w;
                *(float4*)(cp_base + mi * 4) = make_float4(cn_[0], cn_[1], cn_[2], cn_[3]);
            }
        }
    } else {
        // ======================= LOGITS PATH (for step t-1) =======================
        if (t == 0) return;
        const int m0 = (bx - 512) * 32;
        const int tprev = t - 1;

        const __half* aP = hin + ((m0 >> 4) * 32) * 256 + lane * 8;
        const __half* bP = WoB + (wid * 32 + lane) * 8;

        float acc[2][2][4];
        #pragma unroll
        for (int a = 0; a < 2; a++)
            #pragma unroll
            for (int b = 0; b < 2; b++)
                #pragma unroll
                for (int c = 0; c < 4; c++) acc[a][b][c] = 0.0f;

        #pragma unroll
        for (int kt = 0; kt < 32; kt++) {
            const uint4 aq0 = *(const uint4*)(aP + kt * 256);
            const uint4 aq1 = *(const uint4*)(aP + 8192 + kt * 256);
            const uint4 bq  = *(const uint4*)(bP + kt * 2048);
            uint32_t af0[4] = {aq0.x, aq0.y, aq0.z, aq0.w};
            uint32_t af1[4] = {aq1.x, aq1.y, aq1.z, aq1.w};
            uint32_t bf[2][2];
            bf[0][0] = bq.x; bf[0][1] = bq.y;
            bf[1][0] = bq.z; bf[1][1] = bq.w;
            mma16816(acc[0][0], af0, bf[0]);
            mma16816(acc[0][1], af0, bf[1]);
            mma16816(acc[1][0], af1, bf[0]);
            mma16816(acc[1][1], af1, bf[1]);
        }

        const int lr = lane >> 2;
        const int lc = (lane & 3) * 2;
        #pragma unroll
        for (int mi = 0; mi < 2; mi++) {
            #pragma unroll
            for (int rh = 0; rh < 2; rh++) {
                const int m = m0 + mi*16 + lr + rh*8;
                float* orow = out + m * (CD * AD) + tprev * AD;
                #pragma unroll
                for (int f = 0; f < 2; f++) {
                    const int n = wid*16 + f*8 + lc;
                    const float2 b2 = *(const float2*)(bo + n);
                    float2 v;
                    v.x = acc[mi][f][rh*2 + 0] + b2.x;
                    v.y = acc[mi][f][rh*2 + 1] + b2.y;
                    *(float2*)(orow + n) = v;
                }
            }
        }
    }
}

// ============================================================================
// Standalone logits (final step).
// ============================================================================
__global__ __launch_bounds__(256, 2) void logits_kernel(
    const __half* __restrict__ h,
    const __half* __restrict__ WoB,
    const float* __restrict__ bo,
    float* __restrict__ out, int t)
{
    const int tid = threadIdx.x;
    const int wid = tid >> 5, lane = tid & 31;
    const int m0 = blockIdx.x * 32;

    const __half* aP = h + ((m0 >> 4) * 32) * 256 + lane * 8;
    const __half* bP = WoB + (wid * 32 + lane) * 8;

    float acc[2][2][4];
    #pragma unroll
    for (int a = 0; a < 2; a++)
        #pragma unroll
        for (int b = 0; b < 2; b++)
            #pragma unroll
            for (int c = 0; c < 4; c++) acc[a][b][c] = 0.0f;

    #pragma unroll
    for (int kt = 0; kt < 32; kt++) {
        const uint4 aq0 = *(const uint4*)(aP + kt * 256);
        const uint4 aq1 = *(const uint4*)(aP + 8192 + kt * 256);
        const uint4 bq  = *(const uint4*)(bP + kt * 2048);
        uint32_t af0[4] = {aq0.x, aq0.y, aq0.z, aq0.w};
        uint32_t af1[4] = {aq1.x, aq1.y, aq1.z, aq1.w};
        uint32_t bf[2][2];
        bf[0][0] = bq.x; bf[0][1] = bq.y;
        bf[1][0] = bq.z; bf[1][1] = bq.w;
        mma16816(acc[0][0], af0, bf[0]);
        mma16816(acc[0][1], af0, bf[1]);
        mma16816(acc[1][0], af1, bf[0]);
        mma16816(acc[1][1], af1, bf[1]);
    }

    const int lr = lane >> 2;
    const int lc = (lane & 3) * 2;
    #pragma unroll
    for (int mi = 0; mi < 2; mi++) {
        #pragma unroll
        for (int rh = 0; rh < 2; rh++) {
            const int m = m0 + mi*16 + lr + rh*8;
            float* orow = out + m * (CD * AD) + t * AD;
            #pragma unroll
            for (int f = 0; f < 2; f++) {
                const int n = wid*16 + f*8 + lc;
                const float2 b2 = *(const float2*)(bo + n);
                float2 v;
                v.x = acc[mi][f][rh*2 + 0] + b2.x;
                v.y = acc[mi][f][rh*2 + 1] + b2.y;
                *(float2*)(orow + n) = v;
            }
        }
    }
}

// ============================================================================
// kernel_launch
// ============================================================================
extern "C" void kernel_launch(void* const* d_in, const int* in_sizes, int n_in,
                              void* d_out, int out_size)
{
    const float* X    = (const float*)d_in[0];
    const int*   tc   = (const int*)  d_in[1];
    const float* Wp   = (const float*)d_in[2];
    const float* bp   = (const float*)d_in[3];
    const float* Wih  = (const float*)d_in[4];
    const float* Whh  = (const float*)d_in[5];
    const float* bih  = (const float*)d_in[6];
    const float* bhh  = (const float*)d_in[7];
    const float* Wo   = (const float*)d_in[8];
    const float* bo   = (const float*)d_in[9];
    float* out = (float*)d_out;

    __half *h0b, *h1b, *wb, *wob;
    float *cS, *xb;
    cudaGetSymbolAddress((void**)&h0b, g_h0);
    cudaGetSymbolAddress((void**)&h1b, g_h1);
    cudaGetSymbolAddress((void**)&cS,  g_c);
    cudaGetSymbolAddress((void**)&wb,  g_WB);
    cudaGetSymbolAddress((void**)&wob, g_WoB);
    cudaGetSymbolAddress((void**)&xb,  g_xbT);

    cudaFuncSetAttribute(step_kernel, cudaFuncAttributeMaxDynamicSharedMemorySize,
                         A_SMEM_BYTES);

    prep_whh <<<(G4H * HD) / 256, 256>>>(Whh, wb);
    prep_comb<<<1280, 256>>>(Wih, bih, bhh, Wo, xb, wob);
    h0_kernel<<<dim3(BWN / 64, HD / 64), 256>>>(X, Wp, bp, h0b);

    for (int t = 0; t < CD; t++) {
        const __half* hin  = (t & 1) ? h1b : h0b;
        __half*       hout = (t & 1) ? h0b : h1b;
        const int nblk = (t == 0) ? 512 : 640;     // gates + (t>0) logits(t-1)
        step_kernel<<<nblk, 256, A_SMEM_BYTES>>>(
            t, hin, hout, wb, xb, tc, cS, wob, bo, out);
    }
    // final logits for t = 15
    logits_kernel<<<BWN / 32, 256>>>(
        (CD & 1) ? h1b : h0b, wob, bo, out, CD - 1);
}